// round 8
// baseline (speedup 1.0000x reference)
#include <cuda_runtime.h>
#include <cuda_fp16.h>
#include <cstdint>

#define BATCH 2
#define SEQ_N 4096
#define SEQ_M 4096
#define DIM_C 512
#define HEADS 8
#define HDIM  64

// ---------------------------------------------------------------------------
// Scratch
// ---------------------------------------------------------------------------
__device__ float g_Q[BATCH * SEQ_N * DIM_C];
__device__ float g_K[BATCH * SEQ_M * DIM_C];
__device__ float g_V[BATCH * SEQ_M * DIM_C];
__device__ __half g_Qh[BATCH * HEADS * SEQ_N * HDIM];
__device__ __half g_Kh[BATCH * HEADS * SEQ_M * HDIM];
__device__ __half g_Vt[BATCH * HEADS * HDIM * SEQ_M];
__device__ uint32_t g_Mbits[BATCH * 128 * SEQ_N];
__device__ int g_maskBool;
__device__ __half g_Xh[BATCH * SEQ_N * DIM_C];
__device__ __half g_Xl[BATCH * SEQ_N * DIM_C];
__device__ __half g_Ch[BATCH * SEQ_M * DIM_C];
__device__ __half g_Cl[BATCH * SEQ_M * DIM_C];
__device__ __half g_Wth[4 * DIM_C * DIM_C];   // transposed [n][k]
__device__ __half g_Wtl[4 * DIM_C * DIM_C];

// ---------------------------------------------------------------------------
// helpers
// ---------------------------------------------------------------------------
__device__ __forceinline__ float ex2f(float x) {
    float y; asm("ex2.approx.ftz.f32 %0, %1;" : "=f"(y) : "f"(x)); return y;
}
__device__ __forceinline__ uint32_t pack_h2(float lo, float hi) {
    uint32_t r; asm("cvt.rn.f16x2.f32 %0, %1, %2;" : "=r"(r) : "f"(hi), "f"(lo)); return r;
}
__device__ __forceinline__ void mma_f16(float c[4], const uint32_t a[4],
                                        uint32_t b0, uint32_t b1) {
    asm volatile(
        "mma.sync.aligned.m16n8k16.row.col.f32.f16.f16.f32 "
        "{%0,%1,%2,%3}, {%4,%5,%6,%7}, {%8,%9}, {%0,%1,%2,%3};"
        : "+f"(c[0]), "+f"(c[1]), "+f"(c[2]), "+f"(c[3])
        : "r"(a[0]), "r"(a[1]), "r"(a[2]), "r"(a[3]), "r"(b0), "r"(b1));
}
__device__ __forceinline__ void ldsm_x4(uint32_t r[4], uint32_t addr) {
    asm volatile("ldmatrix.sync.aligned.m8n8.x4.shared.b16 {%0,%1,%2,%3}, [%4];"
                 : "=r"(r[0]), "=r"(r[1]), "=r"(r[2]), "=r"(r[3]) : "r"(addr));
}
__device__ __forceinline__ uint32_t smem_u32(const void* p) {
    return (uint32_t)__cvta_generic_to_shared(p);
}
__device__ __forceinline__ void cp16(uint32_t smem_dst, const void* gsrc) {
    asm volatile("cp.async.cg.shared.global [%0], [%1], 16;" ::
                 "r"(smem_dst), "l"(gsrc));
}
__device__ __forceinline__ void cp_commit() {
    asm volatile("cp.async.commit_group;");
}
__device__ __forceinline__ void cp_wait1() {
    asm volatile("cp.async.wait_group 1;");
}
__device__ __forceinline__ void cp_wait0() {
    asm volatile("cp.async.wait_group 0;");
}

// ---------------------------------------------------------------------------
// Mask dtype detection + packing (verified)
// ---------------------------------------------------------------------------
__global__ void detect_mask_kernel(const uint32_t* __restrict__ m)
{
    __shared__ int found;
    if (threadIdx.x == 0) found = 0;
    __syncthreads();
    uint32_t v = m[threadIdx.x] | m[threadIdx.x + 256] |
                 m[threadIdx.x + 512] | m[threadIdx.x + 768];
    if (v > 1u) atomicOr(&found, 1);
    __syncthreads();
    if (threadIdx.x == 0) g_maskBool = found;
}

__global__ __launch_bounds__(128) void pack_mask_kernel(
    const unsigned char* __restrict__ mraw, uint32_t* __restrict__ out)
{
    const int bn = blockIdx.x;
    const int w  = threadIdx.x;
    const int b  = bn >> 12;
    const int n  = bn & 4095;
    uint32_t bits = 0;
    if (g_maskBool) {
        const uint32_t* p = (const uint32_t*)(mraw + (size_t)bn * 4096) + w * 8;
#pragma unroll
        for (int i = 0; i < 8; ++i) {
            uint32_t v = p[i];
#pragma unroll
            for (int j = 0; j < 4; ++j)
                if ((v >> (j * 8)) & 0xFFu) bits |= 1u << (i * 4 + j);
        }
    } else {
        const int* p = (const int*)mraw + (size_t)bn * 4096 + w * 32;
#pragma unroll
        for (int i = 0; i < 32; ++i)
            if (p[i] != 0) bits |= 1u << i;
    }
    out[((size_t)(b * 128 + w)) * 4096 + n] = bits;
}

// ---------------------------------------------------------------------------
// All 4 weights: transpose + fp16 split in one launch (grid z = weight id)
// ---------------------------------------------------------------------------
__global__ __launch_bounds__(256) void wsplit4_kernel(
    const float* __restrict__ W0, const float* __restrict__ W1,
    const float* __restrict__ W2, const float* __restrict__ W3,
    uint32_t* __restrict__ Wth, uint32_t* __restrict__ Wtl)
{
    const int z = blockIdx.z;
    const float* W = (z == 0) ? W0 : (z == 1) ? W1 : (z == 2) ? W2 : W3;
    uint32_t* oh = Wth + (size_t)z * (DIM_C * DIM_C / 2);
    uint32_t* ol = Wtl + (size_t)z * (DIM_C * DIM_C / 2);

    const int n0 = blockIdx.x * 64;
    const int k0 = blockIdx.y * 64;
    const int t  = threadIdx.x;
    __shared__ float S[64][65];
#pragma unroll
    for (int i = 0; i < 16; ++i) {
        int e = i * 256 + t;
        int r = e >> 6, c = e & 63;
        S[r][c] = W[(size_t)(k0 + r) * 512 + n0 + c];
    }
    __syncthreads();
#pragma unroll
    for (int i = 0; i < 8; ++i) {
        int e = i * 256 + t;
        int n = e >> 5, kw = e & 31;
        float v0 = S[2 * kw][n], v1 = S[2 * kw + 1][n];
        __half h0 = __float2half(v0), h1 = __float2half(v1);
        float r0 = v0 - __half2float(h0), r1 = v1 - __half2float(h1);
        size_t dst = (size_t)(n0 + n) * 256 + (k0 >> 1) + kw;
        oh[dst] = ((uint32_t)__half_as_ushort(h1) << 16) | __half_as_ushort(h0);
        ol[dst] = pack_h2(r0, r1);
    }
}

// ---------------------------------------------------------------------------
// x and context fp16 splits in one launch (grid y = which input)
// ---------------------------------------------------------------------------
__global__ void split2_kernel(const float4* __restrict__ x, const float4* __restrict__ ctx,
                              uint2* __restrict__ xh, uint2* __restrict__ xl,
                              uint2* __restrict__ ch, uint2* __restrict__ cl, int n4)
{
    int i = blockIdx.x * blockDim.x + threadIdx.x;
    if (i >= n4) return;
    const float4* s = blockIdx.y ? ctx : x;
    uint2* oh = blockIdx.y ? ch : xh;
    uint2* ol = blockIdx.y ? cl : xl;
    float4 v = s[i];
    __half hx = __float2half(v.x), hy = __float2half(v.y);
    __half hz = __float2half(v.z), hw = __float2half(v.w);
    uint2 h, l;
    h.x = ((uint32_t)__half_as_ushort(hy) << 16) | __half_as_ushort(hx);
    h.y = ((uint32_t)__half_as_ushort(hw) << 16) | __half_as_ushort(hz);
    l.x = pack_h2(v.x - __half2float(hx), v.y - __half2float(hy));
    l.y = pack_h2(v.z - __half2float(hz), v.w - __half2float(hw));
    oh[i] = h;
    ol[i] = l;
}

// ---------------------------------------------------------------------------
// Tensor-core GEMM (unchanged from round 7)
// ---------------------------------------------------------------------------
#define GSTAGE_WORDS (4 * 128 * 20)
__global__ __launch_bounds__(256) void gemm_mma_kernel(
    const uint32_t* __restrict__ Ah, const uint32_t* __restrict__ Al,
    const uint32_t* __restrict__ Wth, const uint32_t* __restrict__ Wtl,
    const float* __restrict__ bias, float* __restrict__ Y)
{
    extern __shared__ uint32_t sm[];
    const int row0 = blockIdx.y * 128;
    const int col0 = blockIdx.x * 128;
    const int t = threadIdx.x, w = t >> 5, lane = t & 31;
    const int wm = w & 3, wn = w >> 2;
    const int qr = lane >> 2, qc = lane & 3;

    const uint32_t smb = smem_u32(sm);

    float acc[2][8][4];
#pragma unroll
    for (int mt = 0; mt < 2; ++mt)
#pragma unroll
        for (int n = 0; n < 8; ++n)
#pragma unroll
            for (int k = 0; k < 4; ++k) acc[mt][n][k] = 0.f;

    const int a_row = wm * 32 + (lane & 7) + ((lane >> 3) & 1) * 8;
    const int a_wrd = (lane >> 4) * 4;
    const uint32_t ah_o = (0 * 2560 + a_row * 20 + a_wrd) * 4;
    const uint32_t al_o = (1 * 2560 + a_row * 20 + a_wrd) * 4;
    const int b_row = wn * 64 + (lane & 7);
    const int b_wrd = (lane >> 3) * 4;
    const uint32_t wh_o = (2 * 2560 + b_row * 20 + b_wrd) * 4;
    const uint32_t wl_o = (3 * 2560 + b_row * 20 + b_wrd) * 4;

    const int ld_seg = (t & 3) * 4;

    auto issue = [&](int ch, int st) {
        const int kw = ch * 16;
        const uint32_t sb = smb + st * GSTAGE_WORDS * 4;
#pragma unroll
        for (int i = 0; i < 2; ++i) {
            int row = i * 64 + (t >> 2);
            size_t ga = (size_t)(row0 + row) * 256 + kw + ld_seg;
            size_t gw = (size_t)(col0 + row) * 256 + kw + ld_seg;
            uint32_t so = (row * 20 + ld_seg) * 4;
            cp16(sb + 0 * 2560 * 4 + so, &Ah[ga]);
            cp16(sb + 1 * 2560 * 4 + so, &Al[ga]);
            cp16(sb + 2 * 2560 * 4 + so, &Wth[gw]);
            cp16(sb + 3 * 2560 * 4 + so, &Wtl[gw]);
        }
        cp_commit();
    };

    issue(0, 0);
    issue(1, 1);

    for (int ch = 0; ch < 16; ++ch) {
        if (ch < 15) cp_wait1(); else cp_wait0();
        __syncthreads();

        const uint32_t sb = smb + (ch & 1) * GSTAGE_WORDS * 4;
        uint32_t ahi[2][2][4], alo[2][2][4];
#pragma unroll
        for (int mt = 0; mt < 2; ++mt)
#pragma unroll
            for (int kc = 0; kc < 2; ++kc) {
                ldsm_x4(ahi[mt][kc], sb + ah_o + (mt * 16 * 20 + kc * 8) * 4);
                ldsm_x4(alo[mt][kc], sb + al_o + (mt * 16 * 20 + kc * 8) * 4);
            }
#pragma unroll
        for (int np = 0; np < 4; ++np) {
            const int n0 = 2 * np, n1 = 2 * np + 1;
            uint32_t bh0[4], bh1[4], bl0[4], bl1[4];
            ldsm_x4(bh0, sb + wh_o + n0 * 8 * 20 * 4);
            ldsm_x4(bh1, sb + wh_o + n1 * 8 * 20 * 4);
            ldsm_x4(bl0, sb + wl_o + n0 * 8 * 20 * 4);
            ldsm_x4(bl1, sb + wl_o + n1 * 8 * 20 * 4);
            mma_f16(acc[0][n0], ahi[0][0], bh0[0], bh0[1]);
            mma_f16(acc[1][n0], ahi[1][0], bh0[0], bh0[1]);
            mma_f16(acc[0][n1], ahi[0][0], bh1[0], bh1[1]);
            mma_f16(acc[1][n1], ahi[1][0], bh1[0], bh1[1]);
            mma_f16(acc[0][n0], ahi[0][1], bh0[2], bh0[3]);
            mma_f16(acc[1][n0], ahi[1][1], bh0[2], bh0[3]);
            mma_f16(acc[0][n1], ahi[0][1], bh1[2], bh1[3]);
            mma_f16(acc[1][n1], ahi[1][1], bh1[2], bh1[3]);
            mma_f16(acc[0][n0], alo[0][0], bh0[0], bh0[1]);
            mma_f16(acc[1][n0], alo[1][0], bh0[0], bh0[1]);
            mma_f16(acc[0][n1], alo[0][0], bh1[0], bh1[1]);
            mma_f16(acc[1][n1], alo[1][0], bh1[0], bh1[1]);
            mma_f16(acc[0][n0], alo[0][1], bh0[2], bh0[3]);
            mma_f16(acc[1][n0], alo[1][1], bh0[2], bh0[3]);
            mma_f16(acc[0][n1], alo[0][1], bh1[2], bh1[3]);
            mma_f16(acc[1][n1], alo[1][1], bh1[2], bh1[3]);
            mma_f16(acc[0][n0], ahi[0][0], bl0[0], bl0[1]);
            mma_f16(acc[1][n0], ahi[1][0], bl0[0], bl0[1]);
            mma_f16(acc[0][n1], ahi[0][0], bl1[0], bl1[1]);
            mma_f16(acc[1][n1], ahi[1][0], bl1[0], bl1[1]);
            mma_f16(acc[0][n0], ahi[0][1], bl0[2], bl0[3]);
            mma_f16(acc[1][n0], ahi[1][1], bl0[2], bl0[3]);
            mma_f16(acc[0][n1], ahi[0][1], bl1[2], bl1[3]);
            mma_f16(acc[1][n1], ahi[1][1], bl1[2], bl1[3]);
        }
        __syncthreads();
        if (ch + 2 < 16) issue(ch + 2, ch & 1);
    }

#pragma unroll
    for (int mt = 0; mt < 2; ++mt)
#pragma unroll
        for (int n = 0; n < 8; ++n) {
            int row = row0 + wm * 32 + mt * 16 + qr;
            int col = col0 + wn * 64 + n * 8 + qc * 2;
            float2 bi = *(const float2*)&bias[col];
            float2 v0 = make_float2(acc[mt][n][0] + bi.x, acc[mt][n][1] + bi.y);
            float2 v1 = make_float2(acc[mt][n][2] + bi.x, acc[mt][n][3] + bi.y);
            *(float2*)&Y[(size_t)row * 512 + col] = v0;
            *(float2*)&Y[(size_t)(row + 8) * 512 + col] = v1;
        }
}

// ---------------------------------------------------------------------------
// RoPE 2D: fp32 [b,n,h,64] -> fp16 [b,h,n,64], scale folded in.
// ---------------------------------------------------------------------------
__global__ void rope2d_h_kernel(const float* __restrict__ src, __half* __restrict__ dst,
                                const int* __restrict__ pos, float qscale, int total)
{
    int idx = blockIdx.x * blockDim.x + threadIdx.x;
    if (idx >= total) return;
    int pair = idx & 31;
    int h    = (idx >> 5) & 7;
    int n    = (idx >> 8) & 4095;
    int b    = idx >> 20;
    int blk  = pair >> 4;
    int ii   = pair & 15;

    float invf = exp2f(-(float)ii * 0.41524101186092864f);
    int p = pos[((size_t)(b * 4096 + n)) * 2 + blk];
    float ang = (float)p * invf;
    float sn, cs;
    sincosf(ang, &sn, &cs);

    size_t sbase = ((size_t)(b * 4096 + n) * 8 + h) * 64 + blk * 32 + ii;
    float v1 = src[sbase];
    float v2 = src[sbase + 16];
    size_t dbase = ((size_t)((b * 8 + h) * 4096 + n)) * 64 + blk * 32 + ii;
    dst[dbase]      = __float2half((v1 * cs - v2 * sn) * qscale);
    dst[dbase + 16] = __float2half((v2 * cs + v1 * sn) * qscale);
}

// ---------------------------------------------------------------------------
// V: fp32 [b,m,(h,d)] -> fp16 transposed [b,h,d,m]
// ---------------------------------------------------------------------------
__global__ __launch_bounds__(256) void vtrans_kernel(
    const float* __restrict__ V, uint32_t* __restrict__ Vt)
{
    const int m0 = blockIdx.x * 64;
    const int h  = blockIdx.y;
    const int b  = blockIdx.z;
    const int t  = threadIdx.x;
    __shared__ float S[64][65];
#pragma unroll
    for (int i = 0; i < 16; ++i) {
        int e = i * 256 + t;
        int m = e >> 6, d = e & 63;
        S[m][d] = V[((size_t)(b * 4096 + m0 + m)) * 512 + h * 64 + d];
    }
    __syncthreads();
#pragma unroll
    for (int i = 0; i < 8; ++i) {
        int e = i * 256 + t;
        int d = e >> 5, mm = e & 31;
        uint32_t v = pack_h2(S[2 * mm][d], S[2 * mm + 1][d]);
        Vt[((size_t)((b * 8 + h) * 64 + d)) * 2048 + (m0 >> 1) + mm] = v;
    }
}

// ---------------------------------------------------------------------------
// Flash attention, static-max softmax (no online rescale), deferred-PV
// pipeline: per tile, one dense tensor burst [PV(t-1) + S(t)] then softmax(t).
// 3-stage cp.async K/V ring in dynamic smem.
// ---------------------------------------------------------------------------
#define AKOFF(s) ((s) * 9216)              // K stage byte offset (2304 words)
#define AVOFF(s) (27648 + (s) * 9216)      // V stage byte offset
#define ATT_SMEM 55296

__global__ __launch_bounds__(256) void attn_mma_kernel(
    const uint32_t* __restrict__ Qh, const uint32_t* __restrict__ Kh,
    const uint32_t* __restrict__ Vt, const uint32_t* __restrict__ Mb,
    uint32_t* __restrict__ Oh, uint32_t* __restrict__ Ol)
{
    extern __shared__ uint32_t smn[];
    const int b = blockIdx.z, h = blockIdx.y;
    const int q0 = blockIdx.x * 128;
    const int t = threadIdx.x, w = t >> 5, lane = t & 31;
    const int qr = lane >> 2, qc = lane & 3;

    const uint32_t smb = smem_u32(smn);
    const size_t bh = (size_t)(b * 8 + h);
    const int n0 = q0 + w * 16 + qr;
    const int n1 = n0 + 8;

    const uint32_t lm_off = ((lane & 7) * 36 + (lane >> 3) * 4) * 4;

    const uint32_t* Kg = Kh + bh * SEQ_M * 32;
    const uint32_t* Vg = Vt + bh * HDIM * 2048;
    const uint32_t* Mrow = Mb + (size_t)b * 128 * 4096;

    auto issue = [&](int mt, int st) {
        const int mk = mt * 64;
        const int seg = (t & 7) * 4;
#pragma unroll
        for (int i = 0; i < 2; ++i) {
            int row = i * 32 + (t >> 3);
            cp16(smb + AKOFF(st) + (row * 36 + seg) * 4,
                 &Kg[(size_t)(mk + row) * 32 + seg]);
            cp16(smb + AVOFF(st) + (row * 36 + seg) * 4,
                 &Vg[(size_t)row * 2048 + (mk >> 1) + seg]);
        }
        cp_commit();
    };

    issue(0, 0);
    issue(1, 1);

    uint32_t qa[4][4];
    {
        const uint32_t* Qb = Qh + (bh * 4096 + q0 + (size_t)w * 16) * 32;
#pragma unroll
        for (int kc = 0; kc < 4; ++kc) {
            qa[kc][0] = Qb[qr * 32 + kc * 8 + qc];
            qa[kc][1] = Qb[(qr + 8) * 32 + kc * 8 + qc];
            qa[kc][2] = Qb[qr * 32 + kc * 8 + qc + 4];
            qa[kc][3] = Qb[(qr + 8) * 32 + kc * 8 + qc + 4];
        }
    }

    float o[8][4];
#pragma unroll
    for (int j = 0; j < 8; ++j)
#pragma unroll
        for (int k = 0; k < 4; ++k) o[j][k] = 0.f;
    float l0 = 0.f, l1 = 0.f;
    uint32_t pa[4][4];

    // ---- softmax+pack macro body (static max; masked -> exactly 0) ----
    auto softmax_pack = [&](float c[8][4], uint32_t ma0, uint32_t ma1,
                            uint32_t mb0_, uint32_t mb1_) {
#pragma unroll
        for (int j = 0; j < 8; ++j) {
            int bi = j * 8 + qc * 2;
            uint32_t w0 = (bi < 32) ? ma0 : ma1;
            uint32_t w1 = (bi < 32) ? mb0_ : mb1_;
            int sh = bi & 31;
            float p0 = ((w0 >> sh) & 1u)       ? 0.f : ex2f(c[j][0]);
            float p1 = ((w0 >> (sh + 1)) & 1u) ? 0.f : ex2f(c[j][1]);
            float p2 = ((w1 >> sh) & 1u)       ? 0.f : ex2f(c[j][2]);
            float p3 = ((w1 >> (sh + 1)) & 1u) ? 0.f : ex2f(c[j][3]);
            l0 += p0 + p1;
            l1 += p2 + p3;
            c[j][0] = p0; c[j][1] = p1; c[j][2] = p2; c[j][3] = p3;
        }
#pragma unroll
        for (int kc = 0; kc < 4; ++kc) {
            pa[kc][0] = pack_h2(c[2 * kc][0], c[2 * kc][1]);
            pa[kc][1] = pack_h2(c[2 * kc][2], c[2 * kc][3]);
            pa[kc][2] = pack_h2(c[2 * kc + 1][0], c[2 * kc + 1][1]);
            pa[kc][3] = pack_h2(c[2 * kc + 1][2], c[2 * kc + 1][3]);
        }
    };

    // ---- prologue: tile 0 (S only) ----
    {
        uint32_t ma0 = Mrow[(size_t)0 * 4096 + n0];
        uint32_t ma1 = Mrow[(size_t)1 * 4096 + n0];
        uint32_t mb0_ = Mrow[(size_t)0 * 4096 + n1];
        uint32_t mb1_ = Mrow[(size_t)1 * 4096 + n1];
        cp_wait1();
        __syncthreads();
        issue(2, 2);      // stage 2 is fresh: no WAR hazard
        const uint32_t kcur = smb + AKOFF(0) + lm_off;
        float c[8][4];
#pragma unroll
        for (int g = 0; g < 8; ++g) {
            uint32_t kA[4], kB[4];
            ldsm_x4(kA, kcur + g * 1152);
            ldsm_x4(kB, kcur + g * 1152 + 64);
            c[g][0] = c[g][1] = c[g][2] = c[g][3] = 0.f;
            mma_f16(c[g], qa[0], kA[0], kA[1]);
            mma_f16(c[g], qa[1], kA[2], kA[3]);
            mma_f16(c[g], qa[2], kB[0], kB[1]);
            mma_f16(c[g], qa[3], kB[2], kB[3]);
        }
        softmax_pack(c, ma0, ma1, mb0_, mb1_);
    }

    // ---- main loop: tiles 1..63 ----
    for (int tt = 1; tt < 64; ++tt) {
        const int wz = (tt * 64) >> 5;
        uint32_t ma0 = Mrow[(size_t)wz * 4096 + n0];
        uint32_t ma1 = Mrow[(size_t)(wz + 1) * 4096 + n0];
        uint32_t mb0_ = Mrow[(size_t)wz * 4096 + n1];
        uint32_t mb1_ = Mrow[(size_t)(wz + 1) * 4096 + n1];

        if (tt < 63) cp_wait1(); else cp_wait0();
        __syncthreads();

        const uint32_t kcur  = smb + AKOFF(tt % 3) + lm_off;
        const uint32_t vprev = smb + AVOFF((tt + 2) % 3) + lm_off;   // V_{tt-1}

        // dense tensor burst: PV(t-1) + S(t), 16 independent chains
        float c[8][4];
#pragma unroll
        for (int g = 0; g < 8; ++g) {
            uint32_t vA[4], vB[4], kA[4], kB[4];
            ldsm_x4(vA, vprev + g * 1152);
            ldsm_x4(vB, vprev + g * 1152 + 64);
            ldsm_x4(kA, kcur + g * 1152);
            ldsm_x4(kB, kcur + g * 1152 + 64);
            c[g][0] = c[g][1] = c[g][2] = c[g][3] = 0.f;
            mma_f16(o[g], pa[0], vA[0], vA[1]);
            mma_f16(c[g], qa[0], kA[0], kA[1]);
            mma_f16(o[g], pa[1], vA[2], vA[3]);
            mma_f16(c[g], qa[1], kA[2], kA[3]);
            mma_f16(o[g], pa[2], vB[0], vB[1]);
            mma_f16(c[g], qa[2], kB[0], kB[1]);
            mma_f16(o[g], pa[3], vB[2], vB[3]);
            mma_f16(c[g], qa[3], kB[2], kB[3]);
        }

        softmax_pack(c, ma0, ma1, mb0_, mb1_);

        __syncthreads();   // WAR guard before overwriting stage (tt+2)%3
        if (tt + 2 < 64) issue(tt + 2, (tt + 2) % 3);
    }

    // ---- final PV for tile 63 (V stage 63%3 == 0) ----
    {
        const uint32_t vprev = smb + AVOFF(0) + lm_off;
#pragma unroll
        for (int g = 0; g < 8; ++g) {
            uint32_t vA[4], vB[4];
            ldsm_x4(vA, vprev + g * 1152);
            ldsm_x4(vB, vprev + g * 1152 + 64);
            mma_f16(o[g], pa[0], vA[0], vA[1]);
            mma_f16(o[g], pa[1], vA[2], vA[3]);
            mma_f16(o[g], pa[2], vB[0], vB[1]);
            mma_f16(o[g], pa[3], vB[2], vB[3]);
        }
    }

    l0 += __shfl_xor_sync(0xffffffffu, l0, 1);
    l0 += __shfl_xor_sync(0xffffffffu, l0, 2);
    l1 += __shfl_xor_sync(0xffffffffu, l1, 1);
    l1 += __shfl_xor_sync(0xffffffffu, l1, 2);
    float i0 = 1.f / fmaxf(l0, 1e-30f);
    float i1 = 1.f / fmaxf(l1, 1e-30f);
#pragma unroll
    for (int j = 0; j < 8; ++j) {
        int colw = h * 32 + j * 4 + qc;
        float v0 = o[j][0] * i0, v1 = o[j][1] * i0;
        float v2 = o[j][2] * i1, v3 = o[j][3] * i1;
        __half h0 = __float2half(v0), h1 = __float2half(v1);
        __half h2 = __float2half(v2), h3 = __float2half(v3);
        Oh[(size_t)n0 * 256 + (size_t)b * 4096 * 256 + colw] =
            ((uint32_t)__half_as_ushort(h1) << 16) | __half_as_ushort(h0);
        Ol[(size_t)n0 * 256 + (size_t)b * 4096 * 256 + colw] =
            pack_h2(v0 - __half2float(h0), v1 - __half2float(h1));
        Oh[(size_t)n1 * 256 + (size_t)b * 4096 * 256 + colw] =
            ((uint32_t)__half_as_ushort(h3) << 16) | __half_as_ushort(h2);
        Ol[(size_t)n1 * 256 + (size_t)b * 4096 * 256 + colw] =
            pack_h2(v2 - __half2float(h2), v3 - __half2float(h3));
    }
}

// ---------------------------------------------------------------------------
// Launch
// ---------------------------------------------------------------------------
extern "C" void kernel_launch(void* const* d_in, const int* in_sizes, int n_in,
                              void* d_out, int out_size)
{
    const float* x       = (const float*)d_in[0];
    const float* context = (const float*)d_in[1];
    const int*   pos_x   = (const int*)d_in[2];
    const int*   pos_ctx = (const int*)d_in[3];
    const unsigned char* mask = (const unsigned char*)d_in[4];
    const float* Wq = (const float*)d_in[5];
    const float* bq = (const float*)d_in[6];
    const float* Wk = (const float*)d_in[7];
    const float* bk = (const float*)d_in[8];
    const float* Wv = (const float*)d_in[9];
    const float* bv = (const float*)d_in[10];
    const float* Wo = (const float*)d_in[11];
    const float* bo = (const float*)d_in[12];
    float* out = (float*)d_out;

    float *qp, *kp, *vp;
    __half *qh, *kh;
    uint32_t *vt, *mb;
    __half *xh, *xl, *chh, *cl, *wth, *wtl;
    cudaGetSymbolAddress((void**)&qp, g_Q);
    cudaGetSymbolAddress((void**)&kp, g_K);
    cudaGetSymbolAddress((void**)&vp, g_V);
    cudaGetSymbolAddress((void**)&qh, g_Qh);
    cudaGetSymbolAddress((void**)&kh, g_Kh);
    cudaGetSymbolAddress((void**)&vt, g_Vt);
    cudaGetSymbolAddress((void**)&mb, g_Mbits);
    cudaGetSymbolAddress((void**)&xh, g_Xh);
    cudaGetSymbolAddress((void**)&xl, g_Xl);
    cudaGetSymbolAddress((void**)&chh, g_Ch);
    cudaGetSymbolAddress((void**)&cl, g_Cl);
    cudaGetSymbolAddress((void**)&wth, g_Wth);
    cudaGetSymbolAddress((void**)&wtl, g_Wtl);

    const int WSZ2 = DIM_C * DIM_C / 2;
    const int GEMM_SMEM = 2 * GSTAGE_WORDS * 4;   // 80 KB
    cudaFuncSetAttribute(gemm_mma_kernel,
                         cudaFuncAttributeMaxDynamicSharedMemorySize, GEMM_SMEM);
    cudaFuncSetAttribute(attn_mma_kernel,
                         cudaFuncAttributeMaxDynamicSharedMemorySize, ATT_SMEM);

    dim3 wgrid(8, 8, 4);
    wsplit4_kernel<<<wgrid, 256>>>(Wq, Wk, Wv, Wo, (uint32_t*)wth, (uint32_t*)wtl);

    const int n4 = BATCH * SEQ_N * DIM_C / 4;
    dim3 sgrid(n4 / 256, 2);
    split2_kernel<<<sgrid, 256>>>((const float4*)x, (const float4*)context,
                                  (uint2*)xh, (uint2*)xl, (uint2*)chh, (uint2*)cl, n4);

    detect_mask_kernel<<<1, 256>>>((const uint32_t*)mask);

    dim3 ggrid(DIM_C / 128, (BATCH * SEQ_N) / 128);   // (4, 64)
    gemm_mma_kernel<<<ggrid, 256, GEMM_SMEM>>>(
        (const uint32_t*)xh, (const uint32_t*)xl,
        (const uint32_t*)wth + 0 * WSZ2, (const uint32_t*)wtl + 0 * WSZ2, bq, qp);

    pack_mask_kernel<<<BATCH * SEQ_N, 128>>>(mask, mb);

    gemm_mma_kernel<<<ggrid, 256, GEMM_SMEM>>>(
        (const uint32_t*)chh, (const uint32_t*)cl,
        (const uint32_t*)wth + 1 * WSZ2, (const uint32_t*)wtl + 1 * WSZ2, bk, kp);
    gemm_mma_kernel<<<ggrid, 256, GEMM_SMEM>>>(
        (const uint32_t*)chh, (const uint32_t*)cl,
        (const uint32_t*)wth + 2 * WSZ2, (const uint32_t*)wtl + 2 * WSZ2, bv, vp);

    const int rope_total = BATCH * SEQ_N * HEADS * 32;
    const float qscale = 0.125f * 1.4426950408889634f;
    rope2d_h_kernel<<<(rope_total + 255) / 256, 256>>>(qp, qh, pos_x, qscale, rope_total);
    rope2d_h_kernel<<<(rope_total + 255) / 256, 256>>>(kp, kh, pos_ctx, 1.0f, rope_total);

    dim3 vgrid(SEQ_M / 64, HEADS, BATCH);
    vtrans_kernel<<<vgrid, 256>>>(vp, vt);

    dim3 agrid(SEQ_N / 128, HEADS, BATCH);
    attn_mma_kernel<<<agrid, 256, ATT_SMEM>>>(
        (const uint32_t*)qh, (const uint32_t*)kh, vt, mb,
        (uint32_t*)xh, (uint32_t*)xl);

    gemm_mma_kernel<<<ggrid, 256, GEMM_SMEM>>>(
        (const uint32_t*)xh, (const uint32_t*)xl,
        (const uint32_t*)wth + 3 * WSZ2, (const uint32_t*)wtl + 3 * WSZ2, bo, out);
}

// round 9
// speedup vs baseline: 1.0312x; 1.0312x over previous
#include <cuda_runtime.h>
#include <cuda_fp16.h>
#include <cstdint>

#define BATCH 2
#define SEQ_N 4096
#define SEQ_M 4096
#define DIM_C 512
#define HEADS 8
#define HDIM  64

// ---------------------------------------------------------------------------
// Scratch
// ---------------------------------------------------------------------------
__device__ float g_Q[BATCH * SEQ_N * DIM_C];
__device__ float g_K[BATCH * SEQ_M * DIM_C];
__device__ float g_V[BATCH * SEQ_M * DIM_C];
__device__ __half g_Qh[BATCH * HEADS * SEQ_N * HDIM];
__device__ __half g_Kh[BATCH * HEADS * SEQ_M * HDIM];
__device__ __half g_Vt[BATCH * HEADS * HDIM * SEQ_M];
__device__ uint32_t g_Mbits[BATCH * 128 * SEQ_N];
__device__ int g_maskBool;
__device__ __half g_Xh[BATCH * SEQ_N * DIM_C];
__device__ __half g_Xl[BATCH * SEQ_N * DIM_C];
__device__ __half g_Ch[BATCH * SEQ_M * DIM_C];
__device__ __half g_Cl[BATCH * SEQ_M * DIM_C];
__device__ __half g_Wth[4 * DIM_C * DIM_C];   // transposed [n][k]
__device__ __half g_Wtl[4 * DIM_C * DIM_C];

// ---------------------------------------------------------------------------
// helpers
// ---------------------------------------------------------------------------
__device__ __forceinline__ uint32_t pack_h2(float lo, float hi) {
    uint32_t r; asm("cvt.rn.f16x2.f32 %0, %1, %2;" : "=r"(r) : "f"(hi), "f"(lo)); return r;
}
__device__ __forceinline__ uint32_t ex2h2(uint32_t x) {
    uint32_t y; asm("ex2.approx.f16x2 %0, %1;" : "=r"(y) : "r"(x)); return y;
}
__device__ __forceinline__ void mma_f16(float c[4], const uint32_t a[4],
                                        uint32_t b0, uint32_t b1) {
    asm volatile(
        "mma.sync.aligned.m16n8k16.row.col.f32.f16.f16.f32 "
        "{%0,%1,%2,%3}, {%4,%5,%6,%7}, {%8,%9}, {%0,%1,%2,%3};"
        : "+f"(c[0]), "+f"(c[1]), "+f"(c[2]), "+f"(c[3])
        : "r"(a[0]), "r"(a[1]), "r"(a[2]), "r"(a[3]), "r"(b0), "r"(b1));
}
__device__ __forceinline__ void ldsm_x4(uint32_t r[4], uint32_t addr) {
    asm volatile("ldmatrix.sync.aligned.m8n8.x4.shared.b16 {%0,%1,%2,%3}, [%4];"
                 : "=r"(r[0]), "=r"(r[1]), "=r"(r[2]), "=r"(r[3]) : "r"(addr));
}
__device__ __forceinline__ uint32_t smem_u32(const void* p) {
    return (uint32_t)__cvta_generic_to_shared(p);
}
__device__ __forceinline__ void cp16(uint32_t smem_dst, const void* gsrc) {
    asm volatile("cp.async.cg.shared.global [%0], [%1], 16;" ::
                 "r"(smem_dst), "l"(gsrc));
}
__device__ __forceinline__ void cp_commit() {
    asm volatile("cp.async.commit_group;");
}
__device__ __forceinline__ void cp_wait1() {
    asm volatile("cp.async.wait_group 1;");
}
__device__ __forceinline__ void cp_wait0() {
    asm volatile("cp.async.wait_group 0;");
}

// ---------------------------------------------------------------------------
// Mask dtype detection + packing (verified)
// ---------------------------------------------------------------------------
__global__ void detect_mask_kernel(const uint32_t* __restrict__ m)
{
    __shared__ int found;
    if (threadIdx.x == 0) found = 0;
    __syncthreads();
    uint32_t v = m[threadIdx.x] | m[threadIdx.x + 256] |
                 m[threadIdx.x + 512] | m[threadIdx.x + 768];
    if (v > 1u) atomicOr(&found, 1);
    __syncthreads();
    if (threadIdx.x == 0) g_maskBool = found;
}

__global__ __launch_bounds__(128) void pack_mask_kernel(
    const unsigned char* __restrict__ mraw, uint32_t* __restrict__ out)
{
    const int bn = blockIdx.x;
    const int w  = threadIdx.x;
    const int b  = bn >> 12;
    const int n  = bn & 4095;
    uint32_t bits = 0;
    if (g_maskBool) {
        const uint32_t* p = (const uint32_t*)(mraw + (size_t)bn * 4096) + w * 8;
#pragma unroll
        for (int i = 0; i < 8; ++i) {
            uint32_t v = p[i];
#pragma unroll
            for (int j = 0; j < 4; ++j)
                if ((v >> (j * 8)) & 0xFFu) bits |= 1u << (i * 4 + j);
        }
    } else {
        const int* p = (const int*)mraw + (size_t)bn * 4096 + w * 32;
#pragma unroll
        for (int i = 0; i < 32; ++i)
            if (p[i] != 0) bits |= 1u << i;
    }
    out[((size_t)(b * 128 + w)) * 4096 + n] = bits;
}

// ---------------------------------------------------------------------------
// All 4 weights: transpose + fp16 split in one launch (grid z = weight id)
// ---------------------------------------------------------------------------
__global__ __launch_bounds__(256) void wsplit4_kernel(
    const float* __restrict__ W0, const float* __restrict__ W1,
    const float* __restrict__ W2, const float* __restrict__ W3,
    uint32_t* __restrict__ Wth, uint32_t* __restrict__ Wtl)
{
    const int z = blockIdx.z;
    const float* W = (z == 0) ? W0 : (z == 1) ? W1 : (z == 2) ? W2 : W3;
    uint32_t* oh = Wth + (size_t)z * (DIM_C * DIM_C / 2);
    uint32_t* ol = Wtl + (size_t)z * (DIM_C * DIM_C / 2);

    const int n0 = blockIdx.x * 64;
    const int k0 = blockIdx.y * 64;
    const int t  = threadIdx.x;
    __shared__ float S[64][65];
#pragma unroll
    for (int i = 0; i < 16; ++i) {
        int e = i * 256 + t;
        int r = e >> 6, c = e & 63;
        S[r][c] = W[(size_t)(k0 + r) * 512 + n0 + c];
    }
    __syncthreads();
#pragma unroll
    for (int i = 0; i < 8; ++i) {
        int e = i * 256 + t;
        int n = e >> 5, kw = e & 31;
        float v0 = S[2 * kw][n], v1 = S[2 * kw + 1][n];
        __half h0 = __float2half(v0), h1 = __float2half(v1);
        float r0 = v0 - __half2float(h0), r1 = v1 - __half2float(h1);
        size_t dst = (size_t)(n0 + n) * 256 + (k0 >> 1) + kw;
        oh[dst] = ((uint32_t)__half_as_ushort(h1) << 16) | __half_as_ushort(h0);
        ol[dst] = pack_h2(r0, r1);
    }
}

// ---------------------------------------------------------------------------
// x and context fp16 splits in one launch (grid y = which input)
// ---------------------------------------------------------------------------
__global__ void split2_kernel(const float4* __restrict__ x, const float4* __restrict__ ctx,
                              uint2* __restrict__ xh, uint2* __restrict__ xl,
                              uint2* __restrict__ ch, uint2* __restrict__ cl, int n4)
{
    int i = blockIdx.x * blockDim.x + threadIdx.x;
    if (i >= n4) return;
    const float4* s = blockIdx.y ? ctx : x;
    uint2* oh = blockIdx.y ? ch : xh;
    uint2* ol = blockIdx.y ? cl : xl;
    float4 v = s[i];
    __half hx = __float2half(v.x), hy = __float2half(v.y);
    __half hz = __float2half(v.z), hw = __float2half(v.w);
    uint2 h, l;
    h.x = ((uint32_t)__half_as_ushort(hy) << 16) | __half_as_ushort(hx);
    h.y = ((uint32_t)__half_as_ushort(hw) << 16) | __half_as_ushort(hz);
    l.x = pack_h2(v.x - __half2float(hx), v.y - __half2float(hy));
    l.y = pack_h2(v.z - __half2float(hz), v.w - __half2float(hw));
    oh[i] = h;
    ol[i] = l;
}

// ---------------------------------------------------------------------------
// Tensor-core GEMM, fp16 split, 512 threads (16 warps, warp tile 32x32),
// 2-stage cp.async pipeline. 4 warps/SMSP covers HMMA latency.
// ---------------------------------------------------------------------------
#define GSTAGE_WORDS (4 * 128 * 20)
__global__ __launch_bounds__(512) void gemm_mma_kernel(
    const uint32_t* __restrict__ Ah, const uint32_t* __restrict__ Al,
    const uint32_t* __restrict__ Wth, const uint32_t* __restrict__ Wtl,
    const float* __restrict__ bias, float* __restrict__ Y)
{
    extern __shared__ uint32_t sm[];
    const int row0 = blockIdx.y * 128;
    const int col0 = blockIdx.x * 128;
    const int t = threadIdx.x, w = t >> 5, lane = t & 31;
    const int wm = w & 3, wn = w >> 2;          // wm 0..3 rows, wn 0..3 cols
    const int qr = lane >> 2, qc = lane & 3;

    const uint32_t smb = smem_u32(sm);

    float acc[2][4][4];
#pragma unroll
    for (int mt = 0; mt < 2; ++mt)
#pragma unroll
        for (int n = 0; n < 4; ++n)
#pragma unroll
            for (int k = 0; k < 4; ++k) acc[mt][n][k] = 0.f;

    const int a_row = wm * 32 + (lane & 7) + ((lane >> 3) & 1) * 8;
    const int a_wrd = (lane >> 4) * 4;
    const uint32_t ah_o = (0 * 2560 + a_row * 20 + a_wrd) * 4;
    const uint32_t al_o = (1 * 2560 + a_row * 20 + a_wrd) * 4;
    const int b_row = wn * 32 + (lane & 7);
    const int b_wrd = (lane >> 3) * 4;
    const uint32_t wh_o = (2 * 2560 + b_row * 20 + b_wrd) * 4;
    const uint32_t wl_o = (3 * 2560 + b_row * 20 + b_wrd) * 4;

    // cp.async: 512 threads -> 1 x 16B per buffer per chunk
    const int ldr = t >> 2;            // 0..127
    const int lds = (t & 3) * 4;

    auto issue = [&](int ch, int st) {
        const int kw = ch * 16;
        const uint32_t sb = smb + st * GSTAGE_WORDS * 4;
        size_t ga = (size_t)(row0 + ldr) * 256 + kw + lds;
        size_t gw = (size_t)(col0 + ldr) * 256 + kw + lds;
        uint32_t so = (ldr * 20 + lds) * 4;
        cp16(sb + 0 * 2560 * 4 + so, &Ah[ga]);
        cp16(sb + 1 * 2560 * 4 + so, &Al[ga]);
        cp16(sb + 2 * 2560 * 4 + so, &Wth[gw]);
        cp16(sb + 3 * 2560 * 4 + so, &Wtl[gw]);
        cp_commit();
    };

    issue(0, 0);
    issue(1, 1);

    for (int ch = 0; ch < 16; ++ch) {
        if (ch < 15) cp_wait1(); else cp_wait0();
        __syncthreads();

        const uint32_t sb = smb + (ch & 1) * GSTAGE_WORDS * 4;
        uint32_t ahi[2][2][4], alo[2][2][4];
#pragma unroll
        for (int mt = 0; mt < 2; ++mt)
#pragma unroll
            for (int kc = 0; kc < 2; ++kc) {
                ldsm_x4(ahi[mt][kc], sb + ah_o + (mt * 16 * 20 + kc * 8) * 4);
                ldsm_x4(alo[mt][kc], sb + al_o + (mt * 16 * 20 + kc * 8) * 4);
            }
#pragma unroll
        for (int np = 0; np < 2; ++np) {
            const int n0 = 2 * np, n1 = 2 * np + 1;
            uint32_t bh0[4], bh1[4], bl0[4], bl1[4];
            ldsm_x4(bh0, sb + wh_o + n0 * 8 * 20 * 4);
            ldsm_x4(bh1, sb + wh_o + n1 * 8 * 20 * 4);
            ldsm_x4(bl0, sb + wl_o + n0 * 8 * 20 * 4);
            ldsm_x4(bl1, sb + wl_o + n1 * 8 * 20 * 4);
            mma_f16(acc[0][n0], ahi[0][0], bh0[0], bh0[1]);
            mma_f16(acc[1][n0], ahi[1][0], bh0[0], bh0[1]);
            mma_f16(acc[0][n1], ahi[0][0], bh1[0], bh1[1]);
            mma_f16(acc[1][n1], ahi[1][0], bh1[0], bh1[1]);
            mma_f16(acc[0][n0], ahi[0][1], bh0[2], bh0[3]);
            mma_f16(acc[1][n0], ahi[1][1], bh0[2], bh0[3]);
            mma_f16(acc[0][n1], ahi[0][1], bh1[2], bh1[3]);
            mma_f16(acc[1][n1], ahi[1][1], bh1[2], bh1[3]);
            mma_f16(acc[0][n0], alo[0][0], bh0[0], bh0[1]);
            mma_f16(acc[1][n0], alo[1][0], bh0[0], bh0[1]);
            mma_f16(acc[0][n1], alo[0][0], bh1[0], bh1[1]);
            mma_f16(acc[1][n1], alo[1][0], bh1[0], bh1[1]);
            mma_f16(acc[0][n0], alo[0][1], bh0[2], bh0[3]);
            mma_f16(acc[1][n0], alo[1][1], bh0[2], bh0[3]);
            mma_f16(acc[0][n1], alo[0][1], bh1[2], bh1[3]);
            mma_f16(acc[1][n1], alo[1][1], bh1[2], bh1[3]);
            mma_f16(acc[0][n0], ahi[0][0], bl0[0], bl0[1]);
            mma_f16(acc[1][n0], ahi[1][0], bl0[0], bl0[1]);
            mma_f16(acc[0][n1], ahi[0][0], bl1[0], bl1[1]);
            mma_f16(acc[1][n1], ahi[1][0], bl1[0], bl1[1]);
            mma_f16(acc[0][n0], ahi[0][1], bl0[2], bl0[3]);
            mma_f16(acc[1][n0], ahi[1][1], bl0[2], bl0[3]);
            mma_f16(acc[0][n1], ahi[0][1], bl1[2], bl1[3]);
            mma_f16(acc[1][n1], ahi[1][1], bl1[2], bl1[3]);
        }
        __syncthreads();
        if (ch + 2 < 16) issue(ch + 2, ch & 1);
    }

#pragma unroll
    for (int mt = 0; mt < 2; ++mt)
#pragma unroll
        for (int n = 0; n < 4; ++n) {
            int row = row0 + wm * 32 + mt * 16 + qr;
            int col = col0 + wn * 32 + n * 8 + qc * 2;
            float2 bi = *(const float2*)&bias[col];
            float2 v0 = make_float2(acc[mt][n][0] + bi.x, acc[mt][n][1] + bi.y);
            float2 v1 = make_float2(acc[mt][n][2] + bi.x, acc[mt][n][3] + bi.y);
            *(float2*)&Y[(size_t)row * 512 + col] = v0;
            *(float2*)&Y[(size_t)(row + 8) * 512 + col] = v1;
        }
}

// ---------------------------------------------------------------------------
// RoPE 2D: fp32 [b,n,h,64] -> fp16 [b,h,n,64], scale folded in.
// ---------------------------------------------------------------------------
__global__ void rope2d_h_kernel(const float* __restrict__ src, __half* __restrict__ dst,
                                const int* __restrict__ pos, float qscale, int total)
{
    int idx = blockIdx.x * blockDim.x + threadIdx.x;
    if (idx >= total) return;
    int pair = idx & 31;
    int h    = (idx >> 5) & 7;
    int n    = (idx >> 8) & 4095;
    int b    = idx >> 20;
    int blk  = pair >> 4;
    int ii   = pair & 15;

    float invf = exp2f(-(float)ii * 0.41524101186092864f);
    int p = pos[((size_t)(b * 4096 + n)) * 2 + blk];
    float ang = (float)p * invf;
    float sn, cs;
    sincosf(ang, &sn, &cs);

    size_t sbase = ((size_t)(b * 4096 + n) * 8 + h) * 64 + blk * 32 + ii;
    float v1 = src[sbase];
    float v2 = src[sbase + 16];
    size_t dbase = ((size_t)((b * 8 + h) * 4096 + n)) * 64 + blk * 32 + ii;
    dst[dbase]      = __float2half((v1 * cs - v2 * sn) * qscale);
    dst[dbase + 16] = __float2half((v2 * cs + v1 * sn) * qscale);
}

// ---------------------------------------------------------------------------
// V: fp32 [b,m,(h,d)] -> fp16 transposed [b,h,d,m]
// ---------------------------------------------------------------------------
__global__ __launch_bounds__(256) void vtrans_kernel(
    const float* __restrict__ V, uint32_t* __restrict__ Vt)
{
    const int m0 = blockIdx.x * 64;
    const int h  = blockIdx.y;
    const int b  = blockIdx.z;
    const int t  = threadIdx.x;
    __shared__ float S[64][65];
#pragma unroll
    for (int i = 0; i < 16; ++i) {
        int e = i * 256 + t;
        int m = e >> 6, d = e & 63;
        S[m][d] = V[((size_t)(b * 4096 + m0 + m)) * 512 + h * 64 + d];
    }
    __syncthreads();
#pragma unroll
    for (int i = 0; i < 8; ++i) {
        int e = i * 256 + t;
        int d = e >> 5, mm = e & 31;
        uint32_t v = pack_h2(S[2 * mm][d], S[2 * mm + 1][d]);
        Vt[((size_t)((b * 8 + h) * 64 + d)) * 2048 + (m0 >> 1) + mm] = v;
    }
}

// ---------------------------------------------------------------------------
// Flash attention, 512 threads: 16 warps = 8 q-row groups x 2 key-halves.
// Static-max softmax via ex2.f16x2. Deferred-PV tensor burst.
// 3-stage cp.async K/V ring; per-half O merged via smem at the epilogue.
// ---------------------------------------------------------------------------
#define AKOFF(s) ((s) * 9216)              // K stage byte offset (2304 words)
#define AVOFF(s) (27648 + (s) * 9216)      // V stage byte offset
#define ATT_SMEM 55296

__global__ __launch_bounds__(512) void attn_mma_kernel(
    const uint32_t* __restrict__ Qh, const uint32_t* __restrict__ Kh,
    const uint32_t* __restrict__ Vt, const uint32_t* __restrict__ Mb,
    uint32_t* __restrict__ Oh, uint32_t* __restrict__ Ol)
{
    extern __shared__ uint32_t smn[];
    const int b = blockIdx.z, h = blockIdx.y;
    const int q0 = blockIdx.x * 128;
    const int t = threadIdx.x, w = t >> 5, lane = t & 31;
    const int qr = lane >> 2, qc = lane & 3;
    const int wq = w & 7;          // q-row group: rows q0 + wq*16 ..
    const int g  = w >> 3;         // key half: keys [g*32, g*32+32) of each tile

    const uint32_t smb = smem_u32(smn);
    const size_t bh = (size_t)(b * 8 + h);
    const int n0 = q0 + wq * 16 + qr;
    const int n1 = n0 + 8;

    // ldmatrix lane offsets
    const uint32_t lmk = ((g * 32 + (lane & 7)) * 36 + (lane >> 3) * 4) * 4;   // K tile
    const uint32_t lmv = (((lane & 7)) * 36 + g * 16 + (lane >> 3) * 4) * 4;   // V tile

    const uint32_t* Kg = Kh + bh * SEQ_M * 32;
    const uint32_t* Vg = Vt + bh * HDIM * 2048;
    const uint32_t* Mrow = Mb + (size_t)b * 128 * 4096;

    auto issue = [&](int mt, int st) {
        const int mk = mt * 64;
        const int seg = (t & 7) * 4;
        const int row = t >> 3;          // 0..63, exactly once per row
        cp16(smb + AKOFF(st) + (row * 36 + seg) * 4,
             &Kg[(size_t)(mk + row) * 32 + seg]);
        cp16(smb + AVOFF(st) + (row * 36 + seg) * 4,
             &Vg[(size_t)row * 2048 + (mk >> 1) + seg]);
        cp_commit();
    };

    issue(0, 0);
    issue(1, 1);

    uint32_t qa[4][4];
    {
        const uint32_t* Qb = Qh + (bh * 4096 + q0 + (size_t)wq * 16) * 32;
#pragma unroll
        for (int kc = 0; kc < 4; ++kc) {
            qa[kc][0] = Qb[qr * 32 + kc * 8 + qc];
            qa[kc][1] = Qb[(qr + 8) * 32 + kc * 8 + qc];
            qa[kc][2] = Qb[qr * 32 + kc * 8 + qc + 4];
            qa[kc][3] = Qb[(qr + 8) * 32 + kc * 8 + qc + 4];
        }
    }

    float o[8][4];
#pragma unroll
    for (int j = 0; j < 8; ++j)
#pragma unroll
        for (int k = 0; k < 4; ++k) o[j][k] = 0.f;
    float l0 = 0.f, l1 = 0.f;
    uint32_t pa[2][4];

    // mask -> pack f16x2 -> ex2.f16x2 -> pa; l accumulated in f32
    auto softmax_pack = [&](float c[4][4], uint32_t mw0, uint32_t mw1) {
#pragma unroll
        for (int j = 0; j < 4; ++j) {
            int sh = j * 8 + qc * 2;
            if ((mw0 >> sh) & 1u)       c[j][0] = -1e30f;
            if ((mw0 >> (sh + 1)) & 1u) c[j][1] = -1e30f;
            if ((mw1 >> sh) & 1u)       c[j][2] = -1e30f;
            if ((mw1 >> (sh + 1)) & 1u) c[j][3] = -1e30f;
        }
#pragma unroll
        for (int kc = 0; kc < 2; ++kc) {
            pa[kc][0] = ex2h2(pack_h2(c[2 * kc][0], c[2 * kc][1]));
            pa[kc][1] = ex2h2(pack_h2(c[2 * kc][2], c[2 * kc][3]));
            pa[kc][2] = ex2h2(pack_h2(c[2 * kc + 1][0], c[2 * kc + 1][1]));
            pa[kc][3] = ex2h2(pack_h2(c[2 * kc + 1][2], c[2 * kc + 1][3]));
        }
#pragma unroll
        for (int kc = 0; kc < 2; ++kc) {
            float2 f0 = __half22float2(*(__half2*)&pa[kc][0]);
            float2 f1 = __half22float2(*(__half2*)&pa[kc][1]);
            float2 f2 = __half22float2(*(__half2*)&pa[kc][2]);
            float2 f3 = __half22float2(*(__half2*)&pa[kc][3]);
            l0 += f0.x + f0.y + f2.x + f2.y;
            l1 += f1.x + f1.y + f3.x + f3.y;
        }
    };

    // ---- prologue: tile 0, S only ----
    {
        uint32_t mw0 = Mrow[(size_t)g * 4096 + n0];
        uint32_t mw1 = Mrow[(size_t)g * 4096 + n1];
        cp_wait1();
        __syncthreads();
        issue(2, 2);
        const uint32_t ksb = smb + AKOFF(0) + lmk;
        float c[4][4];
#pragma unroll
        for (int u = 0; u < 4; ++u) {
            uint32_t kf[4], kf2[4];
            ldsm_x4(kf,  ksb + u * 1152);
            ldsm_x4(kf2, ksb + u * 1152 + 64);
            c[u][0] = c[u][1] = c[u][2] = c[u][3] = 0.f;
            mma_f16(c[u], qa[0], kf[0], kf[1]);
            mma_f16(c[u], qa[1], kf[2], kf[3]);
            mma_f16(c[u], qa[2], kf2[0], kf2[1]);
            mma_f16(c[u], qa[3], kf2[2], kf2[3]);
        }
        softmax_pack(c, mw0, mw1);
    }

    // ---- main loop: tiles 1..63 ----
    for (int tt = 1; tt < 64; ++tt) {
        const int wz = tt * 2 + g;
        uint32_t mw0 = Mrow[(size_t)wz * 4096 + n0];
        uint32_t mw1 = Mrow[(size_t)wz * 4096 + n1];

        if (tt < 63) cp_wait1(); else cp_wait0();
        __syncthreads();

        const uint32_t ksb = smb + AKOFF(tt % 3) + lmk;
        const uint32_t vsb = smb + AVOFF((tt + 2) % 3) + lmv;   // V_{tt-1}

        float c[4][4];
#pragma unroll
        for (int u = 0; u < 4; ++u) {
            uint32_t kf[4], kf2[4], vf0[4], vf1[4];
            ldsm_x4(kf,  ksb + u * 1152);
            ldsm_x4(kf2, ksb + u * 1152 + 64);
            ldsm_x4(vf0, vsb + (2 * u) * 1152);
            ldsm_x4(vf1, vsb + (2 * u + 1) * 1152);
            c[u][0] = c[u][1] = c[u][2] = c[u][3] = 0.f;
            mma_f16(o[2 * u],     pa[0], vf0[0], vf0[1]);
            mma_f16(c[u],         qa[0], kf[0], kf[1]);
            mma_f16(o[2 * u + 1], pa[0], vf1[0], vf1[1]);
            mma_f16(c[u],         qa[1], kf[2], kf[3]);
            mma_f16(o[2 * u],     pa[1], vf0[2], vf0[3]);
            mma_f16(c[u],         qa[2], kf2[0], kf2[1]);
            mma_f16(o[2 * u + 1], pa[1], vf1[2], vf1[3]);
            mma_f16(c[u],         qa[3], kf2[2], kf2[3]);
        }

        softmax_pack(c, mw0, mw1);

        __syncthreads();   // WAR guard before overwriting stage (tt+2)%3
        if (tt + 2 < 64) issue(tt + 2, (tt + 2) % 3);
    }

    // ---- final PV for tile 63 (V stage 0) ----
    {
        const uint32_t vsb = smb + AVOFF(0) + lmv;
#pragma unroll
        for (int u = 0; u < 4; ++u) {
            uint32_t vf0[4], vf1[4];
            ldsm_x4(vf0, vsb + (2 * u) * 1152);
            ldsm_x4(vf1, vsb + (2 * u + 1) * 1152);
            mma_f16(o[2 * u],     pa[0], vf0[0], vf0[1]);
            mma_f16(o[2 * u + 1], pa[0], vf1[0], vf1[1]);
            mma_f16(o[2 * u],     pa[1], vf0[2], vf0[3]);
            mma_f16(o[2 * u + 1], pa[1], vf1[2], vf1[3]);
        }
    }

    // per-row half-sums of l (all lanes in quad hold the value afterwards)
    l0 += __shfl_xor_sync(0xffffffffu, l0, 1);
    l0 += __shfl_xor_sync(0xffffffffu, l0, 2);
    l1 += __shfl_xor_sync(0xffffffffu, l1, 1);
    l1 += __shfl_xor_sync(0xffffffffu, l1, 2);

    // ---- merge the two key-halves via smem (K/V stages are dead now) ----
    float* sf = reinterpret_cast<float*>(smn);
    const int ro0 = wq * 16 + qr, ro1 = ro0 + 8;
    const int LOFF = 128 * 66;
    __syncthreads();
    if (g == 0) {
#pragma unroll
        for (int j = 0; j < 8; ++j) {
            int col = j * 8 + qc * 2;
            sf[ro0 * 66 + col]     = o[j][0];
            sf[ro0 * 66 + col + 1] = o[j][1];
            sf[ro1 * 66 + col]     = o[j][2];
            sf[ro1 * 66 + col + 1] = o[j][3];
        }
        if (qc == 0) { sf[LOFF + ro0] = l0; sf[LOFF + ro1] = l1; }
    }
    __syncthreads();
    if (g == 1) {
        float i0 = 1.f / fmaxf(l0 + sf[LOFF + ro0], 1e-30f);
        float i1 = 1.f / fmaxf(l1 + sf[LOFF + ro1], 1e-30f);
#pragma unroll
        for (int j = 0; j < 8; ++j) {
            int col = j * 8 + qc * 2;
            float v0 = (o[j][0] + sf[ro0 * 66 + col])     * i0;
            float v1 = (o[j][1] + sf[ro0 * 66 + col + 1]) * i0;
            float v2 = (o[j][2] + sf[ro1 * 66 + col])     * i1;
            float v3 = (o[j][3] + sf[ro1 * 66 + col + 1]) * i1;
            int colw = h * 32 + j * 4 + qc;
            __half h0 = __float2half(v0), h1 = __float2half(v1);
            __half h2 = __float2half(v2), h3 = __float2half(v3);
            Oh[(size_t)n0 * 256 + (size_t)b * 4096 * 256 + colw] =
                ((uint32_t)__half_as_ushort(h1) << 16) | __half_as_ushort(h0);
            Ol[(size_t)n0 * 256 + (size_t)b * 4096 * 256 + colw] =
                pack_h2(v0 - __half2float(h0), v1 - __half2float(h1));
            Oh[(size_t)n1 * 256 + (size_t)b * 4096 * 256 + colw] =
                ((uint32_t)__half_as_ushort(h3) << 16) | __half_as_ushort(h2);
            Ol[(size_t)n1 * 256 + (size_t)b * 4096 * 256 + colw] =
                pack_h2(v2 - __half2float(h2), v3 - __half2float(h3));
        }
    }
}

// ---------------------------------------------------------------------------
// Launch
// ---------------------------------------------------------------------------
extern "C" void kernel_launch(void* const* d_in, const int* in_sizes, int n_in,
                              void* d_out, int out_size)
{
    const float* x       = (const float*)d_in[0];
    const float* context = (const float*)d_in[1];
    const int*   pos_x   = (const int*)d_in[2];
    const int*   pos_ctx = (const int*)d_in[3];
    const unsigned char* mask = (const unsigned char*)d_in[4];
    const float* Wq = (const float*)d_in[5];
    const float* bq = (const float*)d_in[6];
    const float* Wk = (const float*)d_in[7];
    const float* bk = (const float*)d_in[8];
    const float* Wv = (const float*)d_in[9];
    const float* bv = (const float*)d_in[10];
    const float* Wo = (const float*)d_in[11];
    const float* bo = (const float*)d_in[12];
    float* out = (float*)d_out;

    float *qp, *kp, *vp;
    __half *qh, *kh;
    uint32_t *vt, *mb;
    __half *xh, *xl, *chh, *cl, *wth, *wtl;
    cudaGetSymbolAddress((void**)&qp, g_Q);
    cudaGetSymbolAddress((void**)&kp, g_K);
    cudaGetSymbolAddress((void**)&vp, g_V);
    cudaGetSymbolAddress((void**)&qh, g_Qh);
    cudaGetSymbolAddress((void**)&kh, g_Kh);
    cudaGetSymbolAddress((void**)&vt, g_Vt);
    cudaGetSymbolAddress((void**)&mb, g_Mbits);
    cudaGetSymbolAddress((void**)&xh, g_Xh);
    cudaGetSymbolAddress((void**)&xl, g_Xl);
    cudaGetSymbolAddress((void**)&chh, g_Ch);
    cudaGetSymbolAddress((void**)&cl, g_Cl);
    cudaGetSymbolAddress((void**)&wth, g_Wth);
    cudaGetSymbolAddress((void**)&wtl, g_Wtl);

    const int WSZ2 = DIM_C * DIM_C / 2;
    const int GEMM_SMEM = 2 * GSTAGE_WORDS * 4;   // 80 KB
    cudaFuncSetAttribute(gemm_mma_kernel,
                         cudaFuncAttributeMaxDynamicSharedMemorySize, GEMM_SMEM);
    cudaFuncSetAttribute(attn_mma_kernel,
                         cudaFuncAttributeMaxDynamicSharedMemorySize, ATT_SMEM);

    dim3 wgrid(8, 8, 4);
    wsplit4_kernel<<<wgrid, 256>>>(Wq, Wk, Wv, Wo, (uint32_t*)wth, (uint32_t*)wtl);

    const int n4 = BATCH * SEQ_N * DIM_C / 4;
    dim3 sgrid(n4 / 256, 2);
    split2_kernel<<<sgrid, 256>>>((const float4*)x, (const float4*)context,
                                  (uint2*)xh, (uint2*)xl, (uint2*)chh, (uint2*)cl, n4);

    detect_mask_kernel<<<1, 256>>>((const uint32_t*)mask);

    dim3 ggrid(DIM_C / 128, (BATCH * SEQ_N) / 128);   // (4, 64)
    gemm_mma_kernel<<<ggrid, 512, GEMM_SMEM>>>(
        (const uint32_t*)xh, (const uint32_t*)xl,
        (const uint32_t*)wth + 0 * WSZ2, (const uint32_t*)wtl + 0 * WSZ2, bq, qp);

    pack_mask_kernel<<<BATCH * SEQ_N, 128>>>(mask, mb);

    gemm_mma_kernel<<<ggrid, 512, GEMM_SMEM>>>(
        (const uint32_t*)chh, (const uint32_t*)cl,
        (const uint32_t*)wth + 1 * WSZ2, (const uint32_t*)wtl + 1 * WSZ2, bk, kp);
    gemm_mma_kernel<<<ggrid, 512, GEMM_SMEM>>>(
        (const uint32_t*)chh, (const uint32_t*)cl,
        (const uint32_t*)wth + 2 * WSZ2, (const uint32_t*)wtl + 2 * WSZ2, bv, vp);

    const int rope_total = BATCH * SEQ_N * HEADS * 32;
    const float qscale = 0.125f * 1.4426950408889634f;
    rope2d_h_kernel<<<(rope_total + 255) / 256, 256>>>(qp, qh, pos_x, qscale, rope_total);
    rope2d_h_kernel<<<(rope_total + 255) / 256, 256>>>(kp, kh, pos_ctx, 1.0f, rope_total);

    dim3 vgrid(SEQ_M / 64, HEADS, BATCH);
    vtrans_kernel<<<vgrid, 256>>>(vp, vt);

    dim3 agrid(SEQ_N / 128, HEADS, BATCH);
    attn_mma_kernel<<<agrid, 512, ATT_SMEM>>>(
        (const uint32_t*)qh, (const uint32_t*)kh, vt, mb,
        (uint32_t*)xh, (uint32_t*)xl);

    gemm_mma_kernel<<<ggrid, 512, GEMM_SMEM>>>(
        (const uint32_t*)xh, (const uint32_t*)xl,
        (const uint32_t*)wth + 3 * WSZ2, (const uint32_t*)wtl + 3 * WSZ2, bo, out);
}

// round 11
// speedup vs baseline: 1.1228x; 1.0888x over previous
#include <cuda_runtime.h>
#include <cuda_fp16.h>
#include <cstdint>

#define BATCH 2
#define SEQ_N 4096
#define SEQ_M 4096
#define DIM_C 512
#define HEADS 8
#define HDIM  64

// ---------------------------------------------------------------------------
// Scratch
// ---------------------------------------------------------------------------
__device__ float g_Q[BATCH * SEQ_N * DIM_C];
__device__ float g_K[BATCH * SEQ_M * DIM_C];
__device__ float g_V[BATCH * SEQ_M * DIM_C];
__device__ __half g_Qh[BATCH * HEADS * SEQ_N * HDIM];
__device__ __half g_Kh[BATCH * HEADS * SEQ_M * HDIM];
__device__ __half g_Vt[BATCH * HEADS * HDIM * SEQ_M];
__device__ uint32_t g_Mbits[BATCH * 128 * SEQ_N];
__device__ int g_maskBool;
__device__ __half g_Xh[BATCH * SEQ_N * DIM_C];
__device__ __half g_Xl[BATCH * SEQ_N * DIM_C];
__device__ __half g_Ch[BATCH * SEQ_M * DIM_C];
__device__ __half g_Cl[BATCH * SEQ_M * DIM_C];
__device__ __half g_Wth[4 * DIM_C * DIM_C];   // transposed [n][k]
__device__ __half g_Wtl[4 * DIM_C * DIM_C];

// ---------------------------------------------------------------------------
// helpers
// ---------------------------------------------------------------------------
__device__ __forceinline__ uint32_t pack_h2(float lo, float hi) {
    uint32_t r; asm("cvt.rn.f16x2.f32 %0, %1, %2;" : "=r"(r) : "f"(hi), "f"(lo)); return r;
}
__device__ __forceinline__ uint32_t ex2h2(uint32_t x) {
    uint32_t y; asm("ex2.approx.f16x2 %0, %1;" : "=r"(y) : "r"(x)); return y;
}
__device__ __forceinline__ void mma_f16(float c[4], const uint32_t a[4],
                                        uint32_t b0, uint32_t b1) {
    asm volatile(
        "mma.sync.aligned.m16n8k16.row.col.f32.f16.f16.f32 "
        "{%0,%1,%2,%3}, {%4,%5,%6,%7}, {%8,%9}, {%0,%1,%2,%3};"
        : "+f"(c[0]), "+f"(c[1]), "+f"(c[2]), "+f"(c[3])
        : "r"(a[0]), "r"(a[1]), "r"(a[2]), "r"(a[3]), "r"(b0), "r"(b1));
}
__device__ __forceinline__ void ldsm_x4(uint32_t r[4], uint32_t addr) {
    asm volatile("ldmatrix.sync.aligned.m8n8.x4.shared.b16 {%0,%1,%2,%3}, [%4];"
                 : "=r"(r[0]), "=r"(r[1]), "=r"(r[2]), "=r"(r[3]) : "r"(addr));
}
__device__ __forceinline__ uint32_t smem_u32(const void* p) {
    return (uint32_t)__cvta_generic_to_shared(p);
}
__device__ __forceinline__ void cp16(uint32_t smem_dst, const void* gsrc) {
    asm volatile("cp.async.cg.shared.global [%0], [%1], 16;" ::
                 "r"(smem_dst), "l"(gsrc));
}
__device__ __forceinline__ void cp_commit() {
    asm volatile("cp.async.commit_group;");
}
__device__ __forceinline__ void cp_wait1() {
    asm volatile("cp.async.wait_group 1;");
}
__device__ __forceinline__ void cp_wait0() {
    asm volatile("cp.async.wait_group 0;");
}

// ---------------------------------------------------------------------------
// Mask dtype detection + packing (verified)
// ---------------------------------------------------------------------------
__global__ void detect_mask_kernel(const uint32_t* __restrict__ m)
{
    __shared__ int found;
    if (threadIdx.x == 0) found = 0;
    __syncthreads();
    uint32_t v = m[threadIdx.x] | m[threadIdx.x + 256] |
                 m[threadIdx.x + 512] | m[threadIdx.x + 768];
    if (v > 1u) atomicOr(&found, 1);
    __syncthreads();
    if (threadIdx.x == 0) g_maskBool = found;
}

__global__ __launch_bounds__(128) void pack_mask_kernel(
    const unsigned char* __restrict__ mraw, uint32_t* __restrict__ out)
{
    const int bn = blockIdx.x;
    const int w  = threadIdx.x;
    const int b  = bn >> 12;
    const int n  = bn & 4095;
    uint32_t bits = 0;
    if (g_maskBool) {
        const uint32_t* p = (const uint32_t*)(mraw + (size_t)bn * 4096) + w * 8;
#pragma unroll
        for (int i = 0; i < 8; ++i) {
            uint32_t v = p[i];
#pragma unroll
            for (int j = 0; j < 4; ++j)
                if ((v >> (j * 8)) & 0xFFu) bits |= 1u << (i * 4 + j);
        }
    } else {
        const int* p = (const int*)mraw + (size_t)bn * 4096 + w * 32;
#pragma unroll
        for (int i = 0; i < 32; ++i)
            if (p[i] != 0) bits |= 1u << i;
    }
    out[((size_t)(b * 128 + w)) * 4096 + n] = bits;
}

// ---------------------------------------------------------------------------
// All 4 weights: transpose + fp16 split in one launch (grid z = weight id)
// ---------------------------------------------------------------------------
__global__ __launch_bounds__(256) void wsplit4_kernel(
    const float* __restrict__ W0, const float* __restrict__ W1,
    const float* __restrict__ W2, const float* __restrict__ W3,
    uint32_t* __restrict__ Wth, uint32_t* __restrict__ Wtl)
{
    const int z = blockIdx.z;
    const float* W = (z == 0) ? W0 : (z == 1) ? W1 : (z == 2) ? W2 : W3;
    uint32_t* oh = Wth + (size_t)z * (DIM_C * DIM_C / 2);
    uint32_t* ol = Wtl + (size_t)z * (DIM_C * DIM_C / 2);

    const int n0 = blockIdx.x * 64;
    const int k0 = blockIdx.y * 64;
    const int t  = threadIdx.x;
    __shared__ float S[64][65];
#pragma unroll
    for (int i = 0; i < 16; ++i) {
        int e = i * 256 + t;
        int r = e >> 6, c = e & 63;
        S[r][c] = W[(size_t)(k0 + r) * 512 + n0 + c];
    }
    __syncthreads();
#pragma unroll
    for (int i = 0; i < 8; ++i) {
        int e = i * 256 + t;
        int n = e >> 5, kw = e & 31;
        float v0 = S[2 * kw][n], v1 = S[2 * kw + 1][n];
        __half h0 = __float2half(v0), h1 = __float2half(v1);
        float r0 = v0 - __half2float(h0), r1 = v1 - __half2float(h1);
        size_t dst = (size_t)(n0 + n) * 256 + (k0 >> 1) + kw;
        oh[dst] = ((uint32_t)__half_as_ushort(h1) << 16) | __half_as_ushort(h0);
        ol[dst] = pack_h2(r0, r1);
    }
}

// ---------------------------------------------------------------------------
// x and context fp16 hi-conversion in one launch (lo halves not needed:
// Q/K/V GEMMs are single-product; O-proj lo comes fused from attention)
// ---------------------------------------------------------------------------
__global__ void split2_kernel(const float4* __restrict__ x, const float4* __restrict__ ctx,
                              uint2* __restrict__ xh, uint2* __restrict__ ch, int n4)
{
    int i = blockIdx.x * blockDim.x + threadIdx.x;
    if (i >= n4) return;
    const float4* s = blockIdx.y ? ctx : x;
    uint2* oh = blockIdx.y ? ch : xh;
    float4 v = s[i];
    __half hx = __float2half(v.x), hy = __float2half(v.y);
    __half hz = __float2half(v.z), hw = __float2half(v.w);
    uint2 h;
    h.x = ((uint32_t)__half_as_ushort(hy) << 16) | __half_as_ushort(hx);
    h.y = ((uint32_t)__half_as_ushort(hw) << 16) | __half_as_ushort(hz);
    oh[i] = h;
}

// ---------------------------------------------------------------------------
// Tensor-core GEMM, 512 threads (16 warps, warp tile 32x32), 2-stage cp.async
// pipeline. nprod = 1: Y = Ah*Wh (single product). nprod = 3: fp16-split
// 3-product (Ah*Wh + Al*Wh + Ah*Wl) for near-fp32 accuracy.
// ---------------------------------------------------------------------------
#define GSTAGE_WORDS (4 * 128 * 20)
__global__ __launch_bounds__(512) void gemm_mma_kernel(
    const uint32_t* __restrict__ Ah, const uint32_t* __restrict__ Al,
    const uint32_t* __restrict__ Wth, const uint32_t* __restrict__ Wtl,
    const float* __restrict__ bias, float* __restrict__ Y, int nprod)
{
    extern __shared__ uint32_t sm[];
    const int row0 = blockIdx.y * 128;
    const int col0 = blockIdx.x * 128;
    const int t = threadIdx.x, w = t >> 5, lane = t & 31;
    const int wm = w & 3, wn = w >> 2;
    const int qr = lane >> 2, qc = lane & 3;

    const uint32_t smb = smem_u32(sm);

    float acc[2][4][4];
#pragma unroll
    for (int mt = 0; mt < 2; ++mt)
#pragma unroll
        for (int n = 0; n < 4; ++n)
#pragma unroll
            for (int k = 0; k < 4; ++k) acc[mt][n][k] = 0.f;

    const int a_row = wm * 32 + (lane & 7) + ((lane >> 3) & 1) * 8;
    const int a_wrd = (lane >> 4) * 4;
    const uint32_t ah_o = (0 * 2560 + a_row * 20 + a_wrd) * 4;
    const uint32_t al_o = (1 * 2560 + a_row * 20 + a_wrd) * 4;
    const int b_row = wn * 32 + (lane & 7);
    const int b_wrd = (lane >> 3) * 4;
    const uint32_t wh_o = (2 * 2560 + b_row * 20 + b_wrd) * 4;
    const uint32_t wl_o = (3 * 2560 + b_row * 20 + b_wrd) * 4;

    const int ldr = t >> 2;            // 0..127
    const int lds = (t & 3) * 4;

    auto issue = [&](int ch, int st) {
        const int kw = ch * 16;
        const uint32_t sb = smb + st * GSTAGE_WORDS * 4;
        size_t ga = (size_t)(row0 + ldr) * 256 + kw + lds;
        size_t gw = (size_t)(col0 + ldr) * 256 + kw + lds;
        uint32_t so = (ldr * 20 + lds) * 4;
        cp16(sb + 0 * 2560 * 4 + so, &Ah[ga]);
        cp16(sb + 2 * 2560 * 4 + so, &Wth[gw]);
        if (nprod == 3) {
            cp16(sb + 1 * 2560 * 4 + so, &Al[ga]);
            cp16(sb + 3 * 2560 * 4 + so, &Wtl[gw]);
        }
        cp_commit();
    };

    issue(0, 0);
    issue(1, 1);

    for (int ch = 0; ch < 16; ++ch) {
        if (ch < 15) cp_wait1(); else cp_wait0();
        __syncthreads();

        const uint32_t sb = smb + (ch & 1) * GSTAGE_WORDS * 4;
        uint32_t ahi[2][2][4], alo[2][2][4];
#pragma unroll
        for (int mt = 0; mt < 2; ++mt)
#pragma unroll
            for (int kc = 0; kc < 2; ++kc) {
                ldsm_x4(ahi[mt][kc], sb + ah_o + (mt * 16 * 20 + kc * 8) * 4);
                if (nprod == 3)
                    ldsm_x4(alo[mt][kc], sb + al_o + (mt * 16 * 20 + kc * 8) * 4);
            }
#pragma unroll
        for (int np = 0; np < 2; ++np) {
            const int n0 = 2 * np, n1 = 2 * np + 1;
            uint32_t bh0[4], bh1[4];
            ldsm_x4(bh0, sb + wh_o + n0 * 8 * 20 * 4);
            ldsm_x4(bh1, sb + wh_o + n1 * 8 * 20 * 4);
            mma_f16(acc[0][n0], ahi[0][0], bh0[0], bh0[1]);
            mma_f16(acc[1][n0], ahi[1][0], bh0[0], bh0[1]);
            mma_f16(acc[0][n1], ahi[0][0], bh1[0], bh1[1]);
            mma_f16(acc[1][n1], ahi[1][0], bh1[0], bh1[1]);
            mma_f16(acc[0][n0], ahi[0][1], bh0[2], bh0[3]);
            mma_f16(acc[1][n0], ahi[1][1], bh0[2], bh0[3]);
            mma_f16(acc[0][n1], ahi[0][1], bh1[2], bh1[3]);
            mma_f16(acc[1][n1], ahi[1][1], bh1[2], bh1[3]);
            if (nprod == 3) {
                uint32_t bl0[4], bl1[4];
                ldsm_x4(bl0, sb + wl_o + n0 * 8 * 20 * 4);
                ldsm_x4(bl1, sb + wl_o + n1 * 8 * 20 * 4);
                mma_f16(acc[0][n0], alo[0][0], bh0[0], bh0[1]);
                mma_f16(acc[1][n0], alo[1][0], bh0[0], bh0[1]);
                mma_f16(acc[0][n1], alo[0][0], bh1[0], bh1[1]);
                mma_f16(acc[1][n1], alo[1][0], bh1[0], bh1[1]);
                mma_f16(acc[0][n0], alo[0][1], bh0[2], bh0[3]);
                mma_f16(acc[1][n0], alo[1][1], bh0[2], bh0[3]);
                mma_f16(acc[0][n1], alo[0][1], bh1[2], bh1[3]);
                mma_f16(acc[1][n1], alo[1][1], bh1[2], bh1[3]);
                mma_f16(acc[0][n0], ahi[0][0], bl0[0], bl0[1]);
                mma_f16(acc[1][n0], ahi[1][0], bl0[0], bl0[1]);
                mma_f16(acc[0][n1], ahi[0][0], bl1[0], bl1[1]);
                mma_f16(acc[1][n1], ahi[1][0], bl1[0], bl1[1]);
                mma_f16(acc[0][n0], ahi[0][1], bl0[2], bl0[3]);
                mma_f16(acc[1][n0], ahi[1][1], bl0[2], bl0[3]);
                mma_f16(acc[0][n1], ahi[0][1], bl1[2], bl1[3]);
                mma_f16(acc[1][n1], ahi[1][1], bl1[2], bl1[3]);
            }
        }
        __syncthreads();
        if (ch + 2 < 16) issue(ch + 2, ch & 1);
    }

#pragma unroll
    for (int mt = 0; mt < 2; ++mt)
#pragma unroll
        for (int n = 0; n < 4; ++n) {
            int row = row0 + wm * 32 + mt * 16 + qr;
            int col = col0 + wn * 32 + n * 8 + qc * 2;
            float2 bi = *(const float2*)&bias[col];
            float2 v0 = make_float2(acc[mt][n][0] + bi.x, acc[mt][n][1] + bi.y);
            float2 v1 = make_float2(acc[mt][n][2] + bi.x, acc[mt][n][3] + bi.y);
            *(float2*)&Y[(size_t)row * 512 + col] = v0;
            *(float2*)&Y[(size_t)(row + 8) * 512 + col] = v1;
        }
}

// ---------------------------------------------------------------------------
// RoPE 2D: fp32 [b,n,h,64] -> fp16 [b,h,n,64], scale folded in.
// ---------------------------------------------------------------------------
__global__ void rope2d_h_kernel(const float* __restrict__ src, __half* __restrict__ dst,
                                const int* __restrict__ pos, float qscale, int total)
{
    int idx = blockIdx.x * blockDim.x + threadIdx.x;
    if (idx >= total) return;
    int pair = idx & 31;
    int h    = (idx >> 5) & 7;
    int n    = (idx >> 8) & 4095;
    int b    = idx >> 20;
    int blk  = pair >> 4;
    int ii   = pair & 15;

    float invf = exp2f(-(float)ii * 0.41524101186092864f);
    int p = pos[((size_t)(b * 4096 + n)) * 2 + blk];
    float ang = (float)p * invf;
    float sn, cs;
    sincosf(ang, &sn, &cs);

    size_t sbase = ((size_t)(b * 4096 + n) * 8 + h) * 64 + blk * 32 + ii;
    float v1 = src[sbase];
    float v2 = src[sbase + 16];
    size_t dbase = ((size_t)((b * 8 + h) * 4096 + n)) * 64 + blk * 32 + ii;
    dst[dbase]      = __float2half((v1 * cs - v2 * sn) * qscale);
    dst[dbase + 16] = __float2half((v2 * cs + v1 * sn) * qscale);
}

// ---------------------------------------------------------------------------
// V: fp32 [b,m,(h,d)] -> fp16 transposed [b,h,d,m]
// ---------------------------------------------------------------------------
__global__ __launch_bounds__(256) void vtrans_kernel(
    const float* __restrict__ V, uint32_t* __restrict__ Vt)
{
    const int m0 = blockIdx.x * 64;
    const int h  = blockIdx.y;
    const int b  = blockIdx.z;
    const int t  = threadIdx.x;
    __shared__ float S[64][65];
#pragma unroll
    for (int i = 0; i < 16; ++i) {
        int e = i * 256 + t;
        int m = e >> 6, d = e & 63;
        S[m][d] = V[((size_t)(b * 4096 + m0 + m)) * 512 + h * 64 + d];
    }
    __syncthreads();
#pragma unroll
    for (int i = 0; i < 8; ++i) {
        int e = i * 256 + t;
        int d = e >> 5, mm = e & 31;
        uint32_t v = pack_h2(S[2 * mm][d], S[2 * mm + 1][d]);
        Vt[((size_t)((b * 8 + h) * 64 + d)) * 2048 + (m0 >> 1) + mm] = v;
    }
}

// ---------------------------------------------------------------------------
// Flash attention (round-9 proven version): 512 threads, key-split,
// static-max softmax via ex2.f16x2, deferred-PV, 3-stage cp.async ring.
// ---------------------------------------------------------------------------
#define AKOFF(s) ((s) * 9216)
#define AVOFF(s) (27648 + (s) * 9216)
#define ATT_SMEM 55296

__global__ __launch_bounds__(512) void attn_mma_kernel(
    const uint32_t* __restrict__ Qh, const uint32_t* __restrict__ Kh,
    const uint32_t* __restrict__ Vt, const uint32_t* __restrict__ Mb,
    uint32_t* __restrict__ Oh, uint32_t* __restrict__ Ol)
{
    extern __shared__ uint32_t smn[];
    const int b = blockIdx.z, h = blockIdx.y;
    const int q0 = blockIdx.x * 128;
    const int t = threadIdx.x, w = t >> 5, lane = t & 31;
    const int qr = lane >> 2, qc = lane & 3;
    const int wq = w & 7;
    const int g  = w >> 3;

    const uint32_t smb = smem_u32(smn);
    const size_t bh = (size_t)(b * 8 + h);
    const int n0 = q0 + wq * 16 + qr;
    const int n1 = n0 + 8;

    const uint32_t lmk = ((g * 32 + (lane & 7)) * 36 + (lane >> 3) * 4) * 4;
    const uint32_t lmv = (((lane & 7)) * 36 + g * 16 + (lane >> 3) * 4) * 4;

    const uint32_t* Kg = Kh + bh * SEQ_M * 32;
    const uint32_t* Vg = Vt + bh * HDIM * 2048;
    const uint32_t* Mrow = Mb + (size_t)b * 128 * 4096;

    auto issue = [&](int mt, int st) {
        const int mk = mt * 64;
        const int seg = (t & 7) * 4;
        const int row = t >> 3;
        cp16(smb + AKOFF(st) + (row * 36 + seg) * 4,
             &Kg[(size_t)(mk + row) * 32 + seg]);
        cp16(smb + AVOFF(st) + (row * 36 + seg) * 4,
             &Vg[(size_t)row * 2048 + (mk >> 1) + seg]);
        cp_commit();
    };

    issue(0, 0);
    issue(1, 1);

    uint32_t qa[4][4];
    {
        const uint32_t* Qb = Qh + (bh * 4096 + q0 + (size_t)wq * 16) * 32;
#pragma unroll
        for (int kc = 0; kc < 4; ++kc) {
            qa[kc][0] = Qb[qr * 32 + kc * 8 + qc];
            qa[kc][1] = Qb[(qr + 8) * 32 + kc * 8 + qc];
            qa[kc][2] = Qb[qr * 32 + kc * 8 + qc + 4];
            qa[kc][3] = Qb[(qr + 8) * 32 + kc * 8 + qc + 4];
        }
    }

    float o[8][4];
#pragma unroll
    for (int j = 0; j < 8; ++j)
#pragma unroll
        for (int k = 0; k < 4; ++k) o[j][k] = 0.f;
    float l0 = 0.f, l1 = 0.f;
    uint32_t pa[2][4];

    auto softmax_pack = [&](float c[4][4], uint32_t mw0, uint32_t mw1) {
#pragma unroll
        for (int j = 0; j < 4; ++j) {
            int sh = j * 8 + qc * 2;
            if ((mw0 >> sh) & 1u)       c[j][0] = -1e30f;
            if ((mw0 >> (sh + 1)) & 1u) c[j][1] = -1e30f;
            if ((mw1 >> sh) & 1u)       c[j][2] = -1e30f;
            if ((mw1 >> (sh + 1)) & 1u) c[j][3] = -1e30f;
        }
#pragma unroll
        for (int kc = 0; kc < 2; ++kc) {
            pa[kc][0] = ex2h2(pack_h2(c[2 * kc][0], c[2 * kc][1]));
            pa[kc][1] = ex2h2(pack_h2(c[2 * kc][2], c[2 * kc][3]));
            pa[kc][2] = ex2h2(pack_h2(c[2 * kc + 1][0], c[2 * kc + 1][1]));
            pa[kc][3] = ex2h2(pack_h2(c[2 * kc + 1][2], c[2 * kc + 1][3]));
        }
#pragma unroll
        for (int kc = 0; kc < 2; ++kc) {
            float2 f0 = __half22float2(*(__half2*)&pa[kc][0]);
            float2 f1 = __half22float2(*(__half2*)&pa[kc][1]);
            float2 f2 = __half22float2(*(__half2*)&pa[kc][2]);
            float2 f3 = __half22float2(*(__half2*)&pa[kc][3]);
            l0 += f0.x + f0.y + f2.x + f2.y;
            l1 += f1.x + f1.y + f3.x + f3.y;
        }
    };

    {
        uint32_t mw0 = Mrow[(size_t)g * 4096 + n0];
        uint32_t mw1 = Mrow[(size_t)g * 4096 + n1];
        cp_wait1();
        __syncthreads();
        issue(2, 2);
        const uint32_t ksb = smb + AKOFF(0) + lmk;
        float c[4][4];
#pragma unroll
        for (int u = 0; u < 4; ++u) {
            uint32_t kf[4], kf2[4];
            ldsm_x4(kf,  ksb + u * 1152);
            ldsm_x4(kf2, ksb + u * 1152 + 64);
            c[u][0] = c[u][1] = c[u][2] = c[u][3] = 0.f;
            mma_f16(c[u], qa[0], kf[0], kf[1]);
            mma_f16(c[u], qa[1], kf[2], kf[3]);
            mma_f16(c[u], qa[2], kf2[0], kf2[1]);
            mma_f16(c[u], qa[3], kf2[2], kf2[3]);
        }
        softmax_pack(c, mw0, mw1);
    }

    for (int tt = 1; tt < 64; ++tt) {
        const int wz = tt * 2 + g;
        uint32_t mw0 = Mrow[(size_t)wz * 4096 + n0];
        uint32_t mw1 = Mrow[(size_t)wz * 4096 + n1];

        if (tt < 63) cp_wait1(); else cp_wait0();
        __syncthreads();

        const uint32_t ksb = smb + AKOFF(tt % 3) + lmk;
        const uint32_t vsb = smb + AVOFF((tt + 2) % 3) + lmv;

        float c[4][4];
#pragma unroll
        for (int u = 0; u < 4; ++u) {
            uint32_t kf[4], kf2[4], vf0[4], vf1[4];
            ldsm_x4(kf,  ksb + u * 1152);
            ldsm_x4(kf2, ksb + u * 1152 + 64);
            ldsm_x4(vf0, vsb + (2 * u) * 1152);
            ldsm_x4(vf1, vsb + (2 * u + 1) * 1152);
            c[u][0] = c[u][1] = c[u][2] = c[u][3] = 0.f;
            mma_f16(o[2 * u],     pa[0], vf0[0], vf0[1]);
            mma_f16(c[u],         qa[0], kf[0], kf[1]);
            mma_f16(o[2 * u + 1], pa[0], vf1[0], vf1[1]);
            mma_f16(c[u],         qa[1], kf[2], kf[3]);
            mma_f16(o[2 * u],     pa[1], vf0[2], vf0[3]);
            mma_f16(c[u],         qa[2], kf2[0], kf2[1]);
            mma_f16(o[2 * u + 1], pa[1], vf1[2], vf1[3]);
            mma_f16(c[u],         qa[3], kf2[2], kf2[3]);
        }

        softmax_pack(c, mw0, mw1);

        __syncthreads();
        if (tt + 2 < 64) issue(tt + 2, (tt + 2) % 3);
    }

    {
        const uint32_t vsb = smb + AVOFF(0) + lmv;
#pragma unroll
        for (int u = 0; u < 4; ++u) {
            uint32_t vf0[4], vf1[4];
            ldsm_x4(vf0, vsb + (2 * u) * 1152);
            ldsm_x4(vf1, vsb + (2 * u + 1) * 1152);
            mma_f16(o[2 * u],     pa[0], vf0[0], vf0[1]);
            mma_f16(o[2 * u + 1], pa[0], vf1[0], vf1[1]);
            mma_f16(o[2 * u],     pa[1], vf0[2], vf0[3]);
            mma_f16(o[2 * u + 1], pa[1], vf1[2], vf1[3]);
        }
    }

    l0 += __shfl_xor_sync(0xffffffffu, l0, 1);
    l0 += __shfl_xor_sync(0xffffffffu, l0, 2);
    l1 += __shfl_xor_sync(0xffffffffu, l1, 1);
    l1 += __shfl_xor_sync(0xffffffffu, l1, 2);

    float* sf = reinterpret_cast<float*>(smn);
    const int ro0 = wq * 16 + qr, ro1 = ro0 + 8;
    const int LOFF = 128 * 66;
    __syncthreads();
    if (g == 0) {
#pragma unroll
        for (int j = 0; j < 8; ++j) {
            int col = j * 8 + qc * 2;
            sf[ro0 * 66 + col]     = o[j][0];
            sf[ro0 * 66 + col + 1] = o[j][1];
            sf[ro1 * 66 + col]     = o[j][2];
            sf[ro1 * 66 + col + 1] = o[j][3];
        }
        if (qc == 0) { sf[LOFF + ro0] = l0; sf[LOFF + ro1] = l1; }
    }
    __syncthreads();
    if (g == 1) {
        float i0 = 1.f / fmaxf(l0 + sf[LOFF + ro0], 1e-30f);
        float i1 = 1.f / fmaxf(l1 + sf[LOFF + ro1], 1e-30f);
#pragma unroll
        for (int j = 0; j < 8; ++j) {
            int col = j * 8 + qc * 2;
            float v0 = (o[j][0] + sf[ro0 * 66 + col])     * i0;
            float v1 = (o[j][1] + sf[ro0 * 66 + col + 1]) * i0;
            float v2 = (o[j][2] + sf[ro1 * 66 + col])     * i1;
            float v3 = (o[j][3] + sf[ro1 * 66 + col + 1]) * i1;
            int colw = h * 32 + j * 4 + qc;
            __half h0 = __float2half(v0), h1 = __float2half(v1);
            __half h2 = __float2half(v2), h3 = __float2half(v3);
            Oh[(size_t)n0 * 256 + (size_t)b * 4096 * 256 + colw] =
                ((uint32_t)__half_as_ushort(h1) << 16) | __half_as_ushort(h0);
            Ol[(size_t)n0 * 256 + (size_t)b * 4096 * 256 + colw] =
                pack_h2(v0 - __half2float(h0), v1 - __half2float(h1));
            Oh[(size_t)n1 * 256 + (size_t)b * 4096 * 256 + colw] =
                ((uint32_t)__half_as_ushort(h3) << 16) | __half_as_ushort(h2);
            Ol[(size_t)n1 * 256 + (size_t)b * 4096 * 256 + colw] =
                pack_h2(v2 - __half2float(h2), v3 - __half2float(h3));
        }
    }
}

// ---------------------------------------------------------------------------
// Launch
// ---------------------------------------------------------------------------
extern "C" void kernel_launch(void* const* d_in, const int* in_sizes, int n_in,
                              void* d_out, int out_size)
{
    const float* x       = (const float*)d_in[0];
    const float* context = (const float*)d_in[1];
    const int*   pos_x   = (const int*)d_in[2];
    const int*   pos_ctx = (const int*)d_in[3];
    const unsigned char* mask = (const unsigned char*)d_in[4];
    const float* Wq = (const float*)d_in[5];
    const float* bq = (const float*)d_in[6];
    const float* Wk = (const float*)d_in[7];
    const float* bk = (const float*)d_in[8];
    const float* Wv = (const float*)d_in[9];
    const float* bv = (const float*)d_in[10];
    const float* Wo = (const float*)d_in[11];
    const float* bo = (const float*)d_in[12];
    float* out = (float*)d_out;

    float *qp, *kp, *vp;
    __half *qh, *kh;
    uint32_t *vt, *mb;
    __half *xh, *xl, *chh, *wth, *wtl;
    cudaGetSymbolAddress((void**)&qp, g_Q);
    cudaGetSymbolAddress((void**)&kp, g_K);
    cudaGetSymbolAddress((void**)&vp, g_V);
    cudaGetSymbolAddress((void**)&qh, g_Qh);
    cudaGetSymbolAddress((void**)&kh, g_Kh);
    cudaGetSymbolAddress((void**)&vt, g_Vt);
    cudaGetSymbolAddress((void**)&mb, g_Mbits);
    cudaGetSymbolAddress((void**)&xh, g_Xh);
    cudaGetSymbolAddress((void**)&xl, g_Xl);
    cudaGetSymbolAddress((void**)&chh, g_Ch);
    cudaGetSymbolAddress((void**)&wth, g_Wth);
    cudaGetSymbolAddress((void**)&wtl, g_Wtl);

    const int WSZ2 = DIM_C * DIM_C / 2;
    const int GEMM_SMEM = 2 * GSTAGE_WORDS * 4;   // 80 KB
    cudaFuncSetAttribute(gemm_mma_kernel,
                         cudaFuncAttributeMaxDynamicSharedMemorySize, GEMM_SMEM);
    cudaFuncSetAttribute(attn_mma_kernel,
                         cudaFuncAttributeMaxDynamicSharedMemorySize, ATT_SMEM);

    dim3 wgrid(8, 8, 4);
    wsplit4_kernel<<<wgrid, 256>>>(Wq, Wk, Wv, Wo, (uint32_t*)wth, (uint32_t*)wtl);

    const int n4 = BATCH * SEQ_N * DIM_C / 4;
    dim3 sgrid(n4 / 256, 2);
    split2_kernel<<<sgrid, 256>>>((const float4*)x, (const float4*)context,
                                  (uint2*)xh, (uint2*)chh, n4);

    detect_mask_kernel<<<1, 256>>>((const uint32_t*)mask);

    dim3 ggrid(DIM_C / 128, (BATCH * SEQ_N) / 128);   // (4, 64)
    gemm_mma_kernel<<<ggrid, 512, GEMM_SMEM>>>(
        (const uint32_t*)xh, (const uint32_t*)xl,
        (const uint32_t*)wth + 0 * WSZ2, (const uint32_t*)wtl + 0 * WSZ2, bq, qp, 1);

    pack_mask_kernel<<<BATCH * SEQ_N, 128>>>(mask, mb);

    gemm_mma_kernel<<<ggrid, 512, GEMM_SMEM>>>(
        (const uint32_t*)chh, (const uint32_t*)chh,
        (const uint32_t*)wth + 1 * WSZ2, (const uint32_t*)wtl + 1 * WSZ2, bk, kp, 1);
    gemm_mma_kernel<<<ggrid, 512, GEMM_SMEM>>>(
        (const uint32_t*)chh, (const uint32_t*)chh,
        (const uint32_t*)wth + 2 * WSZ2, (const uint32_t*)wtl + 2 * WSZ2, bv, vp, 1);

    const int rope_total = BATCH * SEQ_N * HEADS * 32;
    const float qscale = 0.125f * 1.4426950408889634f;
    rope2d_h_kernel<<<(rope_total + 255) / 256, 256>>>(qp, qh, pos_x, qscale, rope_total);
    rope2d_h_kernel<<<(rope_total + 255) / 256, 256>>>(kp, kh, pos_ctx, 1.0f, rope_total);

    dim3 vgrid(SEQ_M / 64, HEADS, BATCH);
    vtrans_kernel<<<vgrid, 256>>>(vp, vt);

    dim3 agrid(SEQ_N / 128, HEADS, BATCH);
    attn_mma_kernel<<<agrid, 512, ATT_SMEM>>>(
        (const uint32_t*)qh, (const uint32_t*)kh, vt, mb,
        (uint32_t*)xh, (uint32_t*)xl);

    gemm_mma_kernel<<<ggrid, 512, GEMM_SMEM>>>(
        (const uint32_t*)xh, (const uint32_t*)xl,
        (const uint32_t*)wth + 3 * WSZ2, (const uint32_t*)wtl + 3 * WSZ2, bo, out, 3);
}

// round 12
// speedup vs baseline: 1.2058x; 1.0740x over previous
#include <cuda_runtime.h>
#include <cuda_fp16.h>
#include <cstdint>

#define BATCH 2
#define SEQ_N 4096
#define SEQ_M 4096
#define DIM_C 512
#define HEADS 8
#define HDIM  64

// ---------------------------------------------------------------------------
// Scratch
// ---------------------------------------------------------------------------
__device__ float g_Q[BATCH * SEQ_N * DIM_C];
__device__ float g_K[BATCH * SEQ_M * DIM_C];
__device__ float g_V[BATCH * SEQ_M * DIM_C];
__device__ __half g_Qh[BATCH * HEADS * SEQ_N * HDIM];
__device__ __half g_Kh[BATCH * HEADS * SEQ_M * HDIM];
__device__ __half g_Vt[BATCH * HEADS * HDIM * SEQ_M];
__device__ uint32_t g_Mbits[BATCH * 128 * SEQ_N];
__device__ int g_maskBool;
__device__ __half g_Xh[BATCH * SEQ_N * DIM_C];
__device__ __half g_Xl[BATCH * SEQ_N * DIM_C];
__device__ __half g_Ch[BATCH * SEQ_M * DIM_C];
__device__ __half g_Cl[BATCH * SEQ_M * DIM_C];
__device__ __half g_Wth[4 * DIM_C * DIM_C];   // transposed [n][k]
__device__ __half g_Wtl[4 * DIM_C * DIM_C];

// ---------------------------------------------------------------------------
// helpers
// ---------------------------------------------------------------------------
__device__ __forceinline__ uint32_t pack_h2(float lo, float hi) {
    uint32_t r; asm("cvt.rn.f16x2.f32 %0, %1, %2;" : "=r"(r) : "f"(hi), "f"(lo)); return r;
}
__device__ __forceinline__ uint32_t ex2h2(uint32_t x) {
    uint32_t y; asm("ex2.approx.f16x2 %0, %1;" : "=r"(y) : "r"(x)); return y;
}
__device__ __forceinline__ void mma_f16(float c[4], const uint32_t a[4],
                                        uint32_t b0, uint32_t b1) {
    asm volatile(
        "mma.sync.aligned.m16n8k16.row.col.f32.f16.f16.f32 "
        "{%0,%1,%2,%3}, {%4,%5,%6,%7}, {%8,%9}, {%0,%1,%2,%3};"
        : "+f"(c[0]), "+f"(c[1]), "+f"(c[2]), "+f"(c[3])
        : "r"(a[0]), "r"(a[1]), "r"(a[2]), "r"(a[3]), "r"(b0), "r"(b1));
}
__device__ __forceinline__ void ldsm_x4(uint32_t r[4], uint32_t addr) {
    asm volatile("ldmatrix.sync.aligned.m8n8.x4.shared.b16 {%0,%1,%2,%3}, [%4];"
                 : "=r"(r[0]), "=r"(r[1]), "=r"(r[2]), "=r"(r[3]) : "r"(addr));
}
__device__ __forceinline__ uint32_t smem_u32(const void* p) {
    return (uint32_t)__cvta_generic_to_shared(p);
}
__device__ __forceinline__ void cp16(uint32_t smem_dst, const void* gsrc) {
    asm volatile("cp.async.cg.shared.global [%0], [%1], 16;" ::
                 "r"(smem_dst), "l"(gsrc));
}
__device__ __forceinline__ void cp_commit() {
    asm volatile("cp.async.commit_group;");
}
__device__ __forceinline__ void cp_wait1() {
    asm volatile("cp.async.wait_group 1;");
}
__device__ __forceinline__ void cp_wait0() {
    asm volatile("cp.async.wait_group 0;");
}

// ---------------------------------------------------------------------------
// Mask dtype detection + packing (verified)
// ---------------------------------------------------------------------------
__global__ void detect_mask_kernel(const uint32_t* __restrict__ m)
{
    __shared__ int found;
    if (threadIdx.x == 0) found = 0;
    __syncthreads();
    uint32_t v = m[threadIdx.x] | m[threadIdx.x + 256] |
                 m[threadIdx.x + 512] | m[threadIdx.x + 768];
    if (v > 1u) atomicOr(&found, 1);
    __syncthreads();
    if (threadIdx.x == 0) g_maskBool = found;
}

__global__ __launch_bounds__(128) void pack_mask_kernel(
    const unsigned char* __restrict__ mraw, uint32_t* __restrict__ out)
{
    const int bn = blockIdx.x;
    const int w  = threadIdx.x;
    const int b  = bn >> 12;
    const int n  = bn & 4095;
    uint32_t bits = 0;
    if (g_maskBool) {
        const uint32_t* p = (const uint32_t*)(mraw + (size_t)bn * 4096) + w * 8;
#pragma unroll
        for (int i = 0; i < 8; ++i) {
            uint32_t v = p[i];
#pragma unroll
            for (int j = 0; j < 4; ++j)
                if ((v >> (j * 8)) & 0xFFu) bits |= 1u << (i * 4 + j);
        }
    } else {
        const int* p = (const int*)mraw + (size_t)bn * 4096 + w * 32;
#pragma unroll
        for (int i = 0; i < 32; ++i)
            if (p[i] != 0) bits |= 1u << i;
    }
    out[((size_t)(b * 128 + w)) * 4096 + n] = bits;
}

// ---------------------------------------------------------------------------
// All 4 weights: transpose + fp16 split in one launch (grid z = weight id)
// ---------------------------------------------------------------------------
__global__ __launch_bounds__(256) void wsplit4_kernel(
    const float* __restrict__ W0, const float* __restrict__ W1,
    const float* __restrict__ W2, const float* __restrict__ W3,
    uint32_t* __restrict__ Wth, uint32_t* __restrict__ Wtl)
{
    const int z = blockIdx.z;
    const float* W = (z == 0) ? W0 : (z == 1) ? W1 : (z == 2) ? W2 : W3;
    uint32_t* oh = Wth + (size_t)z * (DIM_C * DIM_C / 2);
    uint32_t* ol = Wtl + (size_t)z * (DIM_C * DIM_C / 2);

    const int n0 = blockIdx.x * 64;
    const int k0 = blockIdx.y * 64;
    const int t  = threadIdx.x;
    __shared__ float S[64][65];
#pragma unroll
    for (int i = 0; i < 16; ++i) {
        int e = i * 256 + t;
        int r = e >> 6, c = e & 63;
        S[r][c] = W[(size_t)(k0 + r) * 512 + n0 + c];
    }
    __syncthreads();
#pragma unroll
    for (int i = 0; i < 8; ++i) {
        int e = i * 256 + t;
        int n = e >> 5, kw = e & 31;
        float v0 = S[2 * kw][n], v1 = S[2 * kw + 1][n];
        __half h0 = __float2half(v0), h1 = __float2half(v1);
        float r0 = v0 - __half2float(h0), r1 = v1 - __half2float(h1);
        size_t dst = (size_t)(n0 + n) * 256 + (k0 >> 1) + kw;
        oh[dst] = ((uint32_t)__half_as_ushort(h1) << 16) | __half_as_ushort(h0);
        ol[dst] = pack_h2(r0, r1);
    }
}

// ---------------------------------------------------------------------------
// x and context fp16 hi-conversion in one launch
// ---------------------------------------------------------------------------
__global__ void split2_kernel(const float4* __restrict__ x, const float4* __restrict__ ctx,
                              uint2* __restrict__ xh, uint2* __restrict__ ch, int n4)
{
    int i = blockIdx.x * blockDim.x + threadIdx.x;
    if (i >= n4) return;
    const float4* s = blockIdx.y ? ctx : x;
    uint2* oh = blockIdx.y ? ch : xh;
    float4 v = s[i];
    __half hx = __float2half(v.x), hy = __float2half(v.y);
    __half hz = __float2half(v.z), hw = __float2half(v.w);
    uint2 h;
    h.x = ((uint32_t)__half_as_ushort(hy) << 16) | __half_as_ushort(hx);
    h.y = ((uint32_t)__half_as_ushort(hw) << 16) | __half_as_ushort(hz);
    oh[i] = h;
}

// ---------------------------------------------------------------------------
// Tensor-core GEMM (verified R11): nprod=1 single product, nprod=3 fp16-split.
// ---------------------------------------------------------------------------
#define GSTAGE_WORDS (4 * 128 * 20)
__global__ __launch_bounds__(512) void gemm_mma_kernel(
    const uint32_t* __restrict__ Ah, const uint32_t* __restrict__ Al,
    const uint32_t* __restrict__ Wth, const uint32_t* __restrict__ Wtl,
    const float* __restrict__ bias, float* __restrict__ Y, int nprod)
{
    extern __shared__ uint32_t sm[];
    const int row0 = blockIdx.y * 128;
    const int col0 = blockIdx.x * 128;
    const int t = threadIdx.x, w = t >> 5, lane = t & 31;
    const int wm = w & 3, wn = w >> 2;
    const int qr = lane >> 2, qc = lane & 3;

    const uint32_t smb = smem_u32(sm);

    float acc[2][4][4];
#pragma unroll
    for (int mt = 0; mt < 2; ++mt)
#pragma unroll
        for (int n = 0; n < 4; ++n)
#pragma unroll
            for (int k = 0; k < 4; ++k) acc[mt][n][k] = 0.f;

    const int a_row = wm * 32 + (lane & 7) + ((lane >> 3) & 1) * 8;
    const int a_wrd = (lane >> 4) * 4;
    const uint32_t ah_o = (0 * 2560 + a_row * 20 + a_wrd) * 4;
    const uint32_t al_o = (1 * 2560 + a_row * 20 + a_wrd) * 4;
    const int b_row = wn * 32 + (lane & 7);
    const int b_wrd = (lane >> 3) * 4;
    const uint32_t wh_o = (2 * 2560 + b_row * 20 + b_wrd) * 4;
    const uint32_t wl_o = (3 * 2560 + b_row * 20 + b_wrd) * 4;

    const int ldr = t >> 2;
    const int lds = (t & 3) * 4;

    auto issue = [&](int ch, int st) {
        const int kw = ch * 16;
        const uint32_t sb = smb + st * GSTAGE_WORDS * 4;
        size_t ga = (size_t)(row0 + ldr) * 256 + kw + lds;
        size_t gw = (size_t)(col0 + ldr) * 256 + kw + lds;
        uint32_t so = (ldr * 20 + lds) * 4;
        cp16(sb + 0 * 2560 * 4 + so, &Ah[ga]);
        cp16(sb + 2 * 2560 * 4 + so, &Wth[gw]);
        if (nprod == 3) {
            cp16(sb + 1 * 2560 * 4 + so, &Al[ga]);
            cp16(sb + 3 * 2560 * 4 + so, &Wtl[gw]);
        }
        cp_commit();
    };

    issue(0, 0);
    issue(1, 1);

    for (int ch = 0; ch < 16; ++ch) {
        if (ch < 15) cp_wait1(); else cp_wait0();
        __syncthreads();

        const uint32_t sb = smb + (ch & 1) * GSTAGE_WORDS * 4;
        uint32_t ahi[2][2][4], alo[2][2][4];
#pragma unroll
        for (int mt = 0; mt < 2; ++mt)
#pragma unroll
            for (int kc = 0; kc < 2; ++kc) {
                ldsm_x4(ahi[mt][kc], sb + ah_o + (mt * 16 * 20 + kc * 8) * 4);
                if (nprod == 3)
                    ldsm_x4(alo[mt][kc], sb + al_o + (mt * 16 * 20 + kc * 8) * 4);
            }
#pragma unroll
        for (int np = 0; np < 2; ++np) {
            const int n0 = 2 * np, n1 = 2 * np + 1;
            uint32_t bh0[4], bh1[4];
            ldsm_x4(bh0, sb + wh_o + n0 * 8 * 20 * 4);
            ldsm_x4(bh1, sb + wh_o + n1 * 8 * 20 * 4);
            mma_f16(acc[0][n0], ahi[0][0], bh0[0], bh0[1]);
            mma_f16(acc[1][n0], ahi[1][0], bh0[0], bh0[1]);
            mma_f16(acc[0][n1], ahi[0][0], bh1[0], bh1[1]);
            mma_f16(acc[1][n1], ahi[1][0], bh1[0], bh1[1]);
            mma_f16(acc[0][n0], ahi[0][1], bh0[2], bh0[3]);
            mma_f16(acc[1][n0], ahi[1][1], bh0[2], bh0[3]);
            mma_f16(acc[0][n1], ahi[0][1], bh1[2], bh1[3]);
            mma_f16(acc[1][n1], ahi[1][1], bh1[2], bh1[3]);
            if (nprod == 3) {
                uint32_t bl0[4], bl1[4];
                ldsm_x4(bl0, sb + wl_o + n0 * 8 * 20 * 4);
                ldsm_x4(bl1, sb + wl_o + n1 * 8 * 20 * 4);
                mma_f16(acc[0][n0], alo[0][0], bh0[0], bh0[1]);
                mma_f16(acc[1][n0], alo[1][0], bh0[0], bh0[1]);
                mma_f16(acc[0][n1], alo[0][0], bh1[0], bh1[1]);
                mma_f16(acc[1][n1], alo[1][0], bh1[0], bh1[1]);
                mma_f16(acc[0][n0], alo[0][1], bh0[2], bh0[3]);
                mma_f16(acc[1][n0], alo[1][1], bh0[2], bh0[3]);
                mma_f16(acc[0][n1], alo[0][1], bh1[2], bh1[3]);
                mma_f16(acc[1][n1], alo[1][1], bh1[2], bh1[3]);
                mma_f16(acc[0][n0], ahi[0][0], bl0[0], bl0[1]);
                mma_f16(acc[1][n0], ahi[1][0], bl0[0], bl0[1]);
                mma_f16(acc[0][n1], ahi[0][0], bl1[0], bl1[1]);
                mma_f16(acc[1][n1], ahi[1][0], bl1[0], bl1[1]);
                mma_f16(acc[0][n0], ahi[0][1], bl0[2], bl0[3]);
                mma_f16(acc[1][n0], ahi[1][1], bl0[2], bl0[3]);
                mma_f16(acc[0][n1], ahi[0][1], bl1[2], bl1[3]);
                mma_f16(acc[1][n1], ahi[1][1], bl1[2], bl1[3]);
            }
        }
        __syncthreads();
        if (ch + 2 < 16) issue(ch + 2, ch & 1);
    }

#pragma unroll
    for (int mt = 0; mt < 2; ++mt)
#pragma unroll
        for (int n = 0; n < 4; ++n) {
            int row = row0 + wm * 32 + mt * 16 + qr;
            int col = col0 + wn * 32 + n * 8 + qc * 2;
            float2 bi = *(const float2*)&bias[col];
            float2 v0 = make_float2(acc[mt][n][0] + bi.x, acc[mt][n][1] + bi.y);
            float2 v1 = make_float2(acc[mt][n][2] + bi.x, acc[mt][n][3] + bi.y);
            *(float2*)&Y[(size_t)row * 512 + col] = v0;
            *(float2*)&Y[(size_t)(row + 8) * 512 + col] = v1;
        }
}

// ---------------------------------------------------------------------------
// RoPE 2D: fp32 [b,n,h,64] -> fp16 [b,h,n,64], scale folded in.
// ---------------------------------------------------------------------------
__global__ void rope2d_h_kernel(const float* __restrict__ src, __half* __restrict__ dst,
                                const int* __restrict__ pos, float qscale, int total)
{
    int idx = blockIdx.x * blockDim.x + threadIdx.x;
    if (idx >= total) return;
    int pair = idx & 31;
    int h    = (idx >> 5) & 7;
    int n    = (idx >> 8) & 4095;
    int b    = idx >> 20;
    int blk  = pair >> 4;
    int ii   = pair & 15;

    float invf = exp2f(-(float)ii * 0.41524101186092864f);
    int p = pos[((size_t)(b * 4096 + n)) * 2 + blk];
    float ang = (float)p * invf;
    float sn, cs;
    sincosf(ang, &sn, &cs);

    size_t sbase = ((size_t)(b * 4096 + n) * 8 + h) * 64 + blk * 32 + ii;
    float v1 = src[sbase];
    float v2 = src[sbase + 16];
    size_t dbase = ((size_t)((b * 8 + h) * 4096 + n)) * 64 + blk * 32 + ii;
    dst[dbase]      = __float2half((v1 * cs - v2 * sn) * qscale);
    dst[dbase + 16] = __float2half((v2 * cs + v1 * sn) * qscale);
}

// ---------------------------------------------------------------------------
// V: fp32 [b,m,(h,d)] -> fp16 transposed [b,h,d,m]
// ---------------------------------------------------------------------------
__global__ __launch_bounds__(256) void vtrans_kernel(
    const float* __restrict__ V, uint32_t* __restrict__ Vt)
{
    const int m0 = blockIdx.x * 64;
    const int h  = blockIdx.y;
    const int b  = blockIdx.z;
    const int t  = threadIdx.x;
    __shared__ float S[64][65];
#pragma unroll
    for (int i = 0; i < 16; ++i) {
        int e = i * 256 + t;
        int m = e >> 6, d = e & 63;
        S[m][d] = V[((size_t)(b * 4096 + m0 + m)) * 512 + h * 64 + d];
    }
    __syncthreads();
#pragma unroll
    for (int i = 0; i < 8; ++i) {
        int e = i * 256 + t;
        int d = e >> 5, mm = e & 31;
        uint32_t v = pack_h2(S[2 * mm][d], S[2 * mm + 1][d]);
        Vt[((size_t)((b * 8 + h) * 64 + d)) * 2048 + (m0 >> 1) + mm] = v;
    }
}

// ---------------------------------------------------------------------------
// Flash attention: 512 threads (8 q-groups x 2 key halves), 128-key
// iterations (2 x 64-key chunks), 3-stage ring (6 sub-stages), ONE
// __syncthreads per 128 keys. Classic order: S -> softmax -> PV per chunk.
// Static-max softmax via ex2.f16x2; fused hi/lo fp16 output split.
// ---------------------------------------------------------------------------
#define ASUB_K(s) ((s) * 9216)
#define ASUB_V(s) (55296 + (s) * 9216)
#define ATT_SMEM 110592

__global__ __launch_bounds__(512) void attn_mma_kernel(
    const uint32_t* __restrict__ Qh, const uint32_t* __restrict__ Kh,
    const uint32_t* __restrict__ Vt, const uint32_t* __restrict__ Mb,
    uint32_t* __restrict__ Oh, uint32_t* __restrict__ Ol)
{
    extern __shared__ uint32_t smn[];
    const int b = blockIdx.z, h = blockIdx.y;
    const int q0 = blockIdx.x * 128;
    const int t = threadIdx.x, w = t >> 5, lane = t & 31;
    const int qr = lane >> 2, qc = lane & 3;
    const int wq = w & 7;          // q-row group
    const int g  = w >> 3;         // 32-key half within each 64-key chunk

    const uint32_t smb = smem_u32(smn);
    const size_t bh = (size_t)(b * 8 + h);
    const int n0 = q0 + wq * 16 + qr;
    const int n1 = n0 + 8;

    const uint32_t lmk = ((g * 32 + (lane & 7)) * 36 + (lane >> 3) * 4) * 4;
    const uint32_t lmv = (((lane & 7)) * 36 + g * 16 + (lane >> 3) * 4) * 4;

    const uint32_t* Kg = Kh + bh * SEQ_M * 32;
    const uint32_t* Vg = Vt + bh * HDIM * 2048;
    const uint32_t* Mrow = Mb + (size_t)b * 128 * 4096;

    // one issue = 128 keys (2 sub-stages), one commit group
    auto issue = [&](int tt) {
        const int seg = (t & 7) * 4;
        const int row = t >> 3;          // 0..63
#pragma unroll
        for (int cc = 0; cc < 2; ++cc) {
            const int sub = (2 * tt + cc) % 6;
            const int mk = tt * 128 + cc * 64;
            cp16(smb + ASUB_K(sub) + (row * 36 + seg) * 4,
                 &Kg[(size_t)(mk + row) * 32 + seg]);
            cp16(smb + ASUB_V(sub) + (row * 36 + seg) * 4,
                 &Vg[(size_t)row * 2048 + (mk >> 1) + seg]);
        }
        cp_commit();
    };

    issue(0);
    issue(1);

    uint32_t qa[4][4];
    {
        const uint32_t* Qb = Qh + (bh * 4096 + q0 + (size_t)wq * 16) * 32;
#pragma unroll
        for (int kc = 0; kc < 4; ++kc) {
            qa[kc][0] = Qb[qr * 32 + kc * 8 + qc];
            qa[kc][1] = Qb[(qr + 8) * 32 + kc * 8 + qc];
            qa[kc][2] = Qb[qr * 32 + kc * 8 + qc + 4];
            qa[kc][3] = Qb[(qr + 8) * 32 + kc * 8 + qc + 4];
        }
    }

    float o[8][4];
#pragma unroll
    for (int j = 0; j < 8; ++j)
#pragma unroll
        for (int k = 0; k < 4; ++k) o[j][k] = 0.f;
    float l0 = 0.f, l1 = 0.f;

    // 64-key chunk: S -> softmax(static max, f16x2 exp) -> PV
    auto chunk = [&](int sub, uint32_t mw0, uint32_t mw1) {
        const uint32_t ksb = smb + ASUB_K(sub) + lmk;
        const uint32_t vsb = smb + ASUB_V(sub) + lmv;
        float c[4][4];
#pragma unroll
        for (int u = 0; u < 4; ++u) {
            uint32_t kf[4], kf2[4];
            ldsm_x4(kf,  ksb + u * 1152);
            ldsm_x4(kf2, ksb + u * 1152 + 64);
            c[u][0] = c[u][1] = c[u][2] = c[u][3] = 0.f;
            mma_f16(c[u], qa[0], kf[0], kf[1]);
            mma_f16(c[u], qa[1], kf[2], kf[3]);
            mma_f16(c[u], qa[2], kf2[0], kf2[1]);
            mma_f16(c[u], qa[3], kf2[2], kf2[3]);
        }
        // mask + exp2 (f16x2) + l accumulation
        uint32_t pa[2][4];
#pragma unroll
        for (int j = 0; j < 4; ++j) {
            int sh = j * 8 + qc * 2;
            if ((mw0 >> sh) & 1u)       c[j][0] = -1e30f;
            if ((mw0 >> (sh + 1)) & 1u) c[j][1] = -1e30f;
            if ((mw1 >> sh) & 1u)       c[j][2] = -1e30f;
            if ((mw1 >> (sh + 1)) & 1u) c[j][3] = -1e30f;
        }
#pragma unroll
        for (int kc = 0; kc < 2; ++kc) {
            pa[kc][0] = ex2h2(pack_h2(c[2 * kc][0], c[2 * kc][1]));
            pa[kc][1] = ex2h2(pack_h2(c[2 * kc][2], c[2 * kc][3]));
            pa[kc][2] = ex2h2(pack_h2(c[2 * kc + 1][0], c[2 * kc + 1][1]));
            pa[kc][3] = ex2h2(pack_h2(c[2 * kc + 1][2], c[2 * kc + 1][3]));
        }
#pragma unroll
        for (int kc = 0; kc < 2; ++kc) {
            float2 f0 = __half22float2(*(__half2*)&pa[kc][0]);
            float2 f1 = __half22float2(*(__half2*)&pa[kc][1]);
            float2 f2 = __half22float2(*(__half2*)&pa[kc][2]);
            float2 f3 = __half22float2(*(__half2*)&pa[kc][3]);
            l0 += f0.x + f0.y + f2.x + f2.y;
            l1 += f1.x + f1.y + f3.x + f3.y;
        }
        // PV
#pragma unroll
        for (int u = 0; u < 4; ++u) {
            uint32_t vf0[4], vf1[4];
            ldsm_x4(vf0, vsb + (2 * u) * 1152);
            ldsm_x4(vf1, vsb + (2 * u + 1) * 1152);
            mma_f16(o[2 * u],     pa[0], vf0[0], vf0[1]);
            mma_f16(o[2 * u + 1], pa[0], vf1[0], vf1[1]);
            mma_f16(o[2 * u],     pa[1], vf0[2], vf0[3]);
            mma_f16(o[2 * u + 1], pa[1], vf1[2], vf1[3]);
        }
    };

    for (int tt = 0; tt < 32; ++tt) {
        // mask prefetch for both chunks (before the pipeline wait)
        const int wzA = tt * 4 + g;
        const int wzB = tt * 4 + 2 + g;
        uint32_t ma0 = Mrow[(size_t)wzA * 4096 + n0];
        uint32_t ma1 = Mrow[(size_t)wzA * 4096 + n1];
        uint32_t mb0 = Mrow[(size_t)wzB * 4096 + n0];
        uint32_t mb1 = Mrow[(size_t)wzB * 4096 + n1];

        if (tt < 31) cp_wait1(); else cp_wait0();
        __syncthreads();   // single barrier per 128 keys

        chunk((2 * tt) % 6,     ma0, ma1);
        chunk((2 * tt + 1) % 6, mb0, mb1);

        if (tt + 2 < 32) issue(tt + 2);
    }

    l0 += __shfl_xor_sync(0xffffffffu, l0, 1);
    l0 += __shfl_xor_sync(0xffffffffu, l0, 2);
    l1 += __shfl_xor_sync(0xffffffffu, l1, 1);
    l1 += __shfl_xor_sync(0xffffffffu, l1, 2);

    // merge the two key-halves via smem (stages are dead now)
    float* sf = reinterpret_cast<float*>(smn);
    const int ro0 = wq * 16 + qr, ro1 = ro0 + 8;
    const int LOFF = 128 * 66;
    __syncthreads();
    if (g == 0) {
#pragma unroll
        for (int j = 0; j < 8; ++j) {
            int col = j * 8 + qc * 2;
            sf[ro0 * 66 + col]     = o[j][0];
            sf[ro0 * 66 + col + 1] = o[j][1];
            sf[ro1 * 66 + col]     = o[j][2];
            sf[ro1 * 66 + col + 1] = o[j][3];
        }
        if (qc == 0) { sf[LOFF + ro0] = l0; sf[LOFF + ro1] = l1; }
    }
    __syncthreads();
    if (g == 1) {
        float i0 = 1.f / fmaxf(l0 + sf[LOFF + ro0], 1e-30f);
        float i1 = 1.f / fmaxf(l1 + sf[LOFF + ro1], 1e-30f);
#pragma unroll
        for (int j = 0; j < 8; ++j) {
            int col = j * 8 + qc * 2;
            float v0 = (o[j][0] + sf[ro0 * 66 + col])     * i0;
            float v1 = (o[j][1] + sf[ro0 * 66 + col + 1]) * i0;
            float v2 = (o[j][2] + sf[ro1 * 66 + col])     * i1;
            float v3 = (o[j][3] + sf[ro1 * 66 + col + 1]) * i1;
            int colw = h * 32 + j * 4 + qc;
            __half h0 = __float2half(v0), h1 = __float2half(v1);
            __half h2 = __float2half(v2), h3 = __float2half(v3);
            Oh[(size_t)n0 * 256 + (size_t)b * 4096 * 256 + colw] =
                ((uint32_t)__half_as_ushort(h1) << 16) | __half_as_ushort(h0);
            Ol[(size_t)n0 * 256 + (size_t)b * 4096 * 256 + colw] =
                pack_h2(v0 - __half2float(h0), v1 - __half2float(h1));
            Oh[(size_t)n1 * 256 + (size_t)b * 4096 * 256 + colw] =
                ((uint32_t)__half_as_ushort(h3) << 16) | __half_as_ushort(h2);
            Ol[(size_t)n1 * 256 + (size_t)b * 4096 * 256 + colw] =
                pack_h2(v2 - __half2float(h2), v3 - __half2float(h3));
        }
    }
}

// ---------------------------------------------------------------------------
// Launch
// ---------------------------------------------------------------------------
extern "C" void kernel_launch(void* const* d_in, const int* in_sizes, int n_in,
                              void* d_out, int out_size)
{
    const float* x       = (const float*)d_in[0];
    const float* context = (const float*)d_in[1];
    const int*   pos_x   = (const int*)d_in[2];
    const int*   pos_ctx = (const int*)d_in[3];
    const unsigned char* mask = (const unsigned char*)d_in[4];
    const float* Wq = (const float*)d_in[5];
    const float* bq = (const float*)d_in[6];
    const float* Wk = (const float*)d_in[7];
    const float* bk = (const float*)d_in[8];
    const float* Wv = (const float*)d_in[9];
    const float* bv = (const float*)d_in[10];
    const float* Wo = (const float*)d_in[11];
    const float* bo = (const float*)d_in[12];
    float* out = (float*)d_out;

    float *qp, *kp, *vp;
    __half *qh, *kh;
    uint32_t *vt, *mb;
    __half *xh, *xl, *chh, *wth, *wtl;
    cudaGetSymbolAddress((void**)&qp, g_Q);
    cudaGetSymbolAddress((void**)&kp, g_K);
    cudaGetSymbolAddress((void**)&vp, g_V);
    cudaGetSymbolAddress((void**)&qh, g_Qh);
    cudaGetSymbolAddress((void**)&kh, g_Kh);
    cudaGetSymbolAddress((void**)&vt, g_Vt);
    cudaGetSymbolAddress((void**)&mb, g_Mbits);
    cudaGetSymbolAddress((void**)&xh, g_Xh);
    cudaGetSymbolAddress((void**)&xl, g_Xl);
    cudaGetSymbolAddress((void**)&chh, g_Ch);
    cudaGetSymbolAddress((void**)&wth, g_Wth);
    cudaGetSymbolAddress((void**)&wtl, g_Wtl);

    const int WSZ2 = DIM_C * DIM_C / 2;
    const int GEMM_SMEM = 2 * GSTAGE_WORDS * 4;   // 80 KB
    cudaFuncSetAttribute(gemm_mma_kernel,
                         cudaFuncAttributeMaxDynamicSharedMemorySize, GEMM_SMEM);
    cudaFuncSetAttribute(attn_mma_kernel,
                         cudaFuncAttributeMaxDynamicSharedMemorySize, ATT_SMEM);

    dim3 wgrid(8, 8, 4);
    wsplit4_kernel<<<wgrid, 256>>>(Wq, Wk, Wv, Wo, (uint32_t*)wth, (uint32_t*)wtl);

    const int n4 = BATCH * SEQ_N * DIM_C / 4;
    dim3 sgrid(n4 / 256, 2);
    split2_kernel<<<sgrid, 256>>>((const float4*)x, (const float4*)context,
                                  (uint2*)xh, (uint2*)chh, n4);

    detect_mask_kernel<<<1, 256>>>((const uint32_t*)mask);

    dim3 ggrid(DIM_C / 128, (BATCH * SEQ_N) / 128);   // (4, 64)
    gemm_mma_kernel<<<ggrid, 512, GEMM_SMEM>>>(
        (const uint32_t*)xh, (const uint32_t*)xl,
        (const uint32_t*)wth + 0 * WSZ2, (const uint32_t*)wtl + 0 * WSZ2, bq, qp, 1);

    pack_mask_kernel<<<BATCH * SEQ_N, 128>>>(mask, mb);

    gemm_mma_kernel<<<ggrid, 512, GEMM_SMEM>>>(
        (const uint32_t*)chh, (const uint32_t*)chh,
        (const uint32_t*)wth + 1 * WSZ2, (const uint32_t*)wtl + 1 * WSZ2, bk, kp, 1);
    gemm_mma_kernel<<<ggrid, 512, GEMM_SMEM>>>(
        (const uint32_t*)chh, (const uint32_t*)chh,
        (const uint32_t*)wth + 2 * WSZ2, (const uint32_t*)wtl + 2 * WSZ2, bv, vp, 1);

    const int rope_total = BATCH * SEQ_N * HEADS * 32;
    const float qscale = 0.125f * 1.4426950408889634f;
    rope2d_h_kernel<<<(rope_total + 255) / 256, 256>>>(qp, qh, pos_x, qscale, rope_total);
    rope2d_h_kernel<<<(rope_total + 255) / 256, 256>>>(kp, kh, pos_ctx, 1.0f, rope_total);

    dim3 vgrid(SEQ_M / 64, HEADS, BATCH);
    vtrans_kernel<<<vgrid, 256>>>(vp, vt);

    dim3 agrid(SEQ_N / 128, HEADS, BATCH);
    attn_mma_kernel<<<agrid, 512, ATT_SMEM>>>(
        (const uint32_t*)qh, (const uint32_t*)kh, vt, mb,
        (uint32_t*)xh, (uint32_t*)xl);

    gemm_mma_kernel<<<ggrid, 512, GEMM_SMEM>>>(
        (const uint32_t*)xh, (const uint32_t*)xl,
        (const uint32_t*)wth + 3 * WSZ2, (const uint32_t*)wtl + 3 * WSZ2, bo, out, 3);
}

// round 13
// speedup vs baseline: 1.2799x; 1.0614x over previous
#include <cuda_runtime.h>
#include <cuda_fp16.h>
#include <cstdint>

#define BATCH 2
#define SEQ_N 4096
#define SEQ_M 4096
#define DIM_C 512
#define HEADS 8
#define HDIM  64

// ---------------------------------------------------------------------------
// Scratch
// ---------------------------------------------------------------------------
__device__ float g_Q[BATCH * SEQ_N * DIM_C];
__device__ float g_K[BATCH * SEQ_M * DIM_C];
__device__ float g_V[BATCH * SEQ_M * DIM_C];
__device__ __half g_Qh[BATCH * HEADS * SEQ_N * HDIM];
__device__ __half g_Kh[BATCH * HEADS * SEQ_M * HDIM];
__device__ __half g_Vt[BATCH * HEADS * HDIM * SEQ_M];
__device__ uint32_t g_Mbits[BATCH * 128 * SEQ_N];
__device__ int g_maskBool;
__device__ __half g_Xh[BATCH * SEQ_N * DIM_C];
__device__ __half g_Xl[BATCH * SEQ_N * DIM_C];
__device__ __half g_Ch[BATCH * SEQ_M * DIM_C];
__device__ __half g_Wth[4 * DIM_C * DIM_C];   // transposed [n][k]
__device__ __half g_Wtl[4 * DIM_C * DIM_C];

// ---------------------------------------------------------------------------
// helpers
// ---------------------------------------------------------------------------
__device__ __forceinline__ uint32_t pack_h2(float lo, float hi) {
    uint32_t r; asm("cvt.rn.f16x2.f32 %0, %1, %2;" : "=r"(r) : "f"(hi), "f"(lo)); return r;
}
__device__ __forceinline__ uint32_t ex2h2(uint32_t x) {
    uint32_t y; asm("ex2.approx.f16x2 %0, %1;" : "=r"(y) : "r"(x)); return y;
}
__device__ __forceinline__ void mma_f16(float c[4], const uint32_t a[4],
                                        uint32_t b0, uint32_t b1) {
    asm volatile(
        "mma.sync.aligned.m16n8k16.row.col.f32.f16.f16.f32 "
        "{%0,%1,%2,%3}, {%4,%5,%6,%7}, {%8,%9}, {%0,%1,%2,%3};"
        : "+f"(c[0]), "+f"(c[1]), "+f"(c[2]), "+f"(c[3])
        : "r"(a[0]), "r"(a[1]), "r"(a[2]), "r"(a[3]), "r"(b0), "r"(b1));
}
__device__ __forceinline__ void ldsm_x4(uint32_t r[4], uint32_t addr) {
    asm volatile("ldmatrix.sync.aligned.m8n8.x4.shared.b16 {%0,%1,%2,%3}, [%4];"
                 : "=r"(r[0]), "=r"(r[1]), "=r"(r[2]), "=r"(r[3]) : "r"(addr));
}
__device__ __forceinline__ uint32_t smem_u32(const void* p) {
    return (uint32_t)__cvta_generic_to_shared(p);
}
__device__ __forceinline__ void cp16(uint32_t smem_dst, const void* gsrc) {
    asm volatile("cp.async.cg.shared.global [%0], [%1], 16;" ::
                 "r"(smem_dst), "l"(gsrc));
}
__device__ __forceinline__ void cp_commit() {
    asm volatile("cp.async.commit_group;");
}
__device__ __forceinline__ void cp_wait1() {
    asm volatile("cp.async.wait_group 1;");
}
__device__ __forceinline__ void cp_wait0() {
    asm volatile("cp.async.wait_group 0;");
}

// ---------------------------------------------------------------------------
// Mask dtype detection + packing (verified)
// ---------------------------------------------------------------------------
__global__ void detect_mask_kernel(const uint32_t* __restrict__ m)
{
    __shared__ int found;
    if (threadIdx.x == 0) found = 0;
    __syncthreads();
    uint32_t v = m[threadIdx.x] | m[threadIdx.x + 256] |
                 m[threadIdx.x + 512] | m[threadIdx.x + 768];
    if (v > 1u) atomicOr(&found, 1);
    __syncthreads();
    if (threadIdx.x == 0) g_maskBool = found;
}

__global__ __launch_bounds__(128) void pack_mask_kernel(
    const unsigned char* __restrict__ mraw, uint32_t* __restrict__ out)
{
    const int bn = blockIdx.x;
    const int w  = threadIdx.x;
    const int b  = bn >> 12;
    const int n  = bn & 4095;
    uint32_t bits = 0;
    if (g_maskBool) {
        const uint32_t* p = (const uint32_t*)(mraw + (size_t)bn * 4096) + w * 8;
#pragma unroll
        for (int i = 0; i < 8; ++i) {
            uint32_t v = p[i];
#pragma unroll
            for (int j = 0; j < 4; ++j)
                if ((v >> (j * 8)) & 0xFFu) bits |= 1u << (i * 4 + j);
        }
    } else {
        const int* p = (const int*)mraw + (size_t)bn * 4096 + w * 32;
#pragma unroll
        for (int i = 0; i < 32; ++i)
            if (p[i] != 0) bits |= 1u << i;
    }
    out[((size_t)(b * 128 + w)) * 4096 + n] = bits;
}

// ---------------------------------------------------------------------------
// All 4 weights: transpose + fp16 split; lo residual only for Wo (z==3)
// ---------------------------------------------------------------------------
__global__ __launch_bounds__(256) void wsplit4_kernel(
    const float* __restrict__ W0, const float* __restrict__ W1,
    const float* __restrict__ W2, const float* __restrict__ W3,
    uint32_t* __restrict__ Wth, uint32_t* __restrict__ Wtl)
{
    const int z = blockIdx.z;
    const float* W = (z == 0) ? W0 : (z == 1) ? W1 : (z == 2) ? W2 : W3;
    uint32_t* oh = Wth + (size_t)z * (DIM_C * DIM_C / 2);
    uint32_t* ol = Wtl + (size_t)z * (DIM_C * DIM_C / 2);

    const int n0 = blockIdx.x * 64;
    const int k0 = blockIdx.y * 64;
    const int t  = threadIdx.x;
    __shared__ float S[64][65];
#pragma unroll
    for (int i = 0; i < 16; ++i) {
        int e = i * 256 + t;
        int r = e >> 6, c = e & 63;
        S[r][c] = W[(size_t)(k0 + r) * 512 + n0 + c];
    }
    __syncthreads();
#pragma unroll
    for (int i = 0; i < 8; ++i) {
        int e = i * 256 + t;
        int n = e >> 5, kw = e & 31;
        float v0 = S[2 * kw][n], v1 = S[2 * kw + 1][n];
        __half h0 = __float2half(v0), h1 = __float2half(v1);
        size_t dst = (size_t)(n0 + n) * 256 + (k0 >> 1) + kw;
        oh[dst] = ((uint32_t)__half_as_ushort(h1) << 16) | __half_as_ushort(h0);
        if (z == 3) {
            float r0 = v0 - __half2float(h0), r1 = v1 - __half2float(h1);
            ol[dst] = pack_h2(r0, r1);
        }
    }
}

// ---------------------------------------------------------------------------
// x and context fp16 hi-conversion in one launch
// ---------------------------------------------------------------------------
__global__ void split2_kernel(const float4* __restrict__ x, const float4* __restrict__ ctx,
                              uint2* __restrict__ xh, uint2* __restrict__ ch, int n4)
{
    int i = blockIdx.x * blockDim.x + threadIdx.x;
    if (i >= n4) return;
    const float4* s = blockIdx.y ? ctx : x;
    uint2* oh = blockIdx.y ? ch : xh;
    float4 v = s[i];
    __half hx = __float2half(v.x), hy = __float2half(v.y);
    __half hz = __float2half(v.z), hw = __float2half(v.w);
    uint2 h;
    h.x = ((uint32_t)__half_as_ushort(hy) << 16) | __half_as_ushort(hx);
    h.y = ((uint32_t)__half_as_ushort(hw) << 16) | __half_as_ushort(hz);
    oh[i] = h;
}

// ---------------------------------------------------------------------------
// Tensor-core GEMM (verified R11/R12): nprod=1 single product, nprod=3 split.
// ---------------------------------------------------------------------------
#define GSTAGE_WORDS (4 * 128 * 20)
__global__ __launch_bounds__(512) void gemm_mma_kernel(
    const uint32_t* __restrict__ Ah, const uint32_t* __restrict__ Al,
    const uint32_t* __restrict__ Wth, const uint32_t* __restrict__ Wtl,
    const float* __restrict__ bias, float* __restrict__ Y, int nprod)
{
    extern __shared__ uint32_t sm[];
    const int row0 = blockIdx.y * 128;
    const int col0 = blockIdx.x * 128;
    const int t = threadIdx.x, w = t >> 5, lane = t & 31;
    const int wm = w & 3, wn = w >> 2;
    const int qr = lane >> 2, qc = lane & 3;

    const uint32_t smb = smem_u32(sm);

    float acc[2][4][4];
#pragma unroll
    for (int mt = 0; mt < 2; ++mt)
#pragma unroll
        for (int n = 0; n < 4; ++n)
#pragma unroll
            for (int k = 0; k < 4; ++k) acc[mt][n][k] = 0.f;

    const int a_row = wm * 32 + (lane & 7) + ((lane >> 3) & 1) * 8;
    const int a_wrd = (lane >> 4) * 4;
    const uint32_t ah_o = (0 * 2560 + a_row * 20 + a_wrd) * 4;
    const uint32_t al_o = (1 * 2560 + a_row * 20 + a_wrd) * 4;
    const int b_row = wn * 32 + (lane & 7);
    const int b_wrd = (lane >> 3) * 4;
    const uint32_t wh_o = (2 * 2560 + b_row * 20 + b_wrd) * 4;
    const uint32_t wl_o = (3 * 2560 + b_row * 20 + b_wrd) * 4;

    const int ldr = t >> 2;
    const int lds = (t & 3) * 4;

    auto issue = [&](int ch, int st) {
        const int kw = ch * 16;
        const uint32_t sb = smb + st * GSTAGE_WORDS * 4;
        size_t ga = (size_t)(row0 + ldr) * 256 + kw + lds;
        size_t gw = (size_t)(col0 + ldr) * 256 + kw + lds;
        uint32_t so = (ldr * 20 + lds) * 4;
        cp16(sb + 0 * 2560 * 4 + so, &Ah[ga]);
        cp16(sb + 2 * 2560 * 4 + so, &Wth[gw]);
        if (nprod == 3) {
            cp16(sb + 1 * 2560 * 4 + so, &Al[ga]);
            cp16(sb + 3 * 2560 * 4 + so, &Wtl[gw]);
        }
        cp_commit();
    };

    issue(0, 0);
    issue(1, 1);

    for (int ch = 0; ch < 16; ++ch) {
        if (ch < 15) cp_wait1(); else cp_wait0();
        __syncthreads();

        const uint32_t sb = smb + (ch & 1) * GSTAGE_WORDS * 4;
        uint32_t ahi[2][2][4], alo[2][2][4];
#pragma unroll
        for (int mt = 0; mt < 2; ++mt)
#pragma unroll
            for (int kc = 0; kc < 2; ++kc) {
                ldsm_x4(ahi[mt][kc], sb + ah_o + (mt * 16 * 20 + kc * 8) * 4);
                if (nprod == 3)
                    ldsm_x4(alo[mt][kc], sb + al_o + (mt * 16 * 20 + kc * 8) * 4);
            }
#pragma unroll
        for (int np = 0; np < 2; ++np) {
            const int n0 = 2 * np, n1 = 2 * np + 1;
            uint32_t bh0[4], bh1[4];
            ldsm_x4(bh0, sb + wh_o + n0 * 8 * 20 * 4);
            ldsm_x4(bh1, sb + wh_o + n1 * 8 * 20 * 4);
            mma_f16(acc[0][n0], ahi[0][0], bh0[0], bh0[1]);
            mma_f16(acc[1][n0], ahi[1][0], bh0[0], bh0[1]);
            mma_f16(acc[0][n1], ahi[0][0], bh1[0], bh1[1]);
            mma_f16(acc[1][n1], ahi[1][0], bh1[0], bh1[1]);
            mma_f16(acc[0][n0], ahi[0][1], bh0[2], bh0[3]);
            mma_f16(acc[1][n0], ahi[1][1], bh0[2], bh0[3]);
            mma_f16(acc[0][n1], ahi[0][1], bh1[2], bh1[3]);
            mma_f16(acc[1][n1], ahi[1][1], bh1[2], bh1[3]);
            if (nprod == 3) {
                uint32_t bl0[4], bl1[4];
                ldsm_x4(bl0, sb + wl_o + n0 * 8 * 20 * 4);
                ldsm_x4(bl1, sb + wl_o + n1 * 8 * 20 * 4);
                mma_f16(acc[0][n0], alo[0][0], bh0[0], bh0[1]);
                mma_f16(acc[1][n0], alo[1][0], bh0[0], bh0[1]);
                mma_f16(acc[0][n1], alo[0][0], bh1[0], bh1[1]);
                mma_f16(acc[1][n1], alo[1][0], bh1[0], bh1[1]);
                mma_f16(acc[0][n0], alo[0][1], bh0[2], bh0[3]);
                mma_f16(acc[1][n0], alo[1][1], bh0[2], bh0[3]);
                mma_f16(acc[0][n1], alo[0][1], bh1[2], bh1[3]);
                mma_f16(acc[1][n1], alo[1][1], bh1[2], bh1[3]);
                mma_f16(acc[0][n0], ahi[0][0], bl0[0], bl0[1]);
                mma_f16(acc[1][n0], ahi[1][0], bl0[0], bl0[1]);
                mma_f16(acc[0][n1], ahi[0][0], bl1[0], bl1[1]);
                mma_f16(acc[1][n1], ahi[1][0], bl1[0], bl1[1]);
                mma_f16(acc[0][n0], ahi[0][1], bl0[2], bl0[3]);
                mma_f16(acc[1][n0], ahi[1][1], bl0[2], bl0[3]);
                mma_f16(acc[0][n1], ahi[0][1], bl1[2], bl1[3]);
                mma_f16(acc[1][n1], ahi[1][1], bl1[2], bl1[3]);
            }
        }
        __syncthreads();
        if (ch + 2 < 16) issue(ch + 2, ch & 1);
    }

#pragma unroll
    for (int mt = 0; mt < 2; ++mt)
#pragma unroll
        for (int n = 0; n < 4; ++n) {
            int row = row0 + wm * 32 + mt * 16 + qr;
            int col = col0 + wn * 32 + n * 8 + qc * 2;
            float2 bi = *(const float2*)&bias[col];
            float2 v0 = make_float2(acc[mt][n][0] + bi.x, acc[mt][n][1] + bi.y);
            float2 v1 = make_float2(acc[mt][n][2] + bi.x, acc[mt][n][3] + bi.y);
            *(float2*)&Y[(size_t)row * 512 + col] = v0;
            *(float2*)&Y[(size_t)(row + 8) * 512 + col] = v1;
        }
}

// ---------------------------------------------------------------------------
// RoPE 2D: fp32 [b,n,h,64] -> fp16 [b,h,n,64], scale folded in.
// ---------------------------------------------------------------------------
__global__ void rope2d_h_kernel(const float* __restrict__ src, __half* __restrict__ dst,
                                const int* __restrict__ pos, float qscale, int total)
{
    int idx = blockIdx.x * blockDim.x + threadIdx.x;
    if (idx >= total) return;
    int pair = idx & 31;
    int h    = (idx >> 5) & 7;
    int n    = (idx >> 8) & 4095;
    int b    = idx >> 20;
    int blk  = pair >> 4;
    int ii   = pair & 15;

    float invf = exp2f(-(float)ii * 0.41524101186092864f);
    int p = pos[((size_t)(b * 4096 + n)) * 2 + blk];
    float ang = (float)p * invf;
    float sn, cs;
    sincosf(ang, &sn, &cs);

    size_t sbase = ((size_t)(b * 4096 + n) * 8 + h) * 64 + blk * 32 + ii;
    float v1 = src[sbase];
    float v2 = src[sbase + 16];
    size_t dbase = ((size_t)((b * 8 + h) * 4096 + n)) * 64 + blk * 32 + ii;
    dst[dbase]      = __float2half((v1 * cs - v2 * sn) * qscale);
    dst[dbase + 16] = __float2half((v2 * cs + v1 * sn) * qscale);
}

// ---------------------------------------------------------------------------
// V: fp32 [b,m,(h,d)] -> fp16 transposed [b,h,d,m]
// ---------------------------------------------------------------------------
__global__ __launch_bounds__(256) void vtrans_kernel(
    const float* __restrict__ V, uint32_t* __restrict__ Vt)
{
    const int m0 = blockIdx.x * 64;
    const int h  = blockIdx.y;
    const int b  = blockIdx.z;
    const int t  = threadIdx.x;
    __shared__ float S[64][65];
#pragma unroll
    for (int i = 0; i < 16; ++i) {
        int e = i * 256 + t;
        int m = e >> 6, d = e & 63;
        S[m][d] = V[((size_t)(b * 4096 + m0 + m)) * 512 + h * 64 + d];
    }
    __syncthreads();
#pragma unroll
    for (int i = 0; i < 8; ++i) {
        int e = i * 256 + t;
        int d = e >> 5, mm = e & 31;
        uint32_t v = pack_h2(S[2 * mm][d], S[2 * mm + 1][d]);
        Vt[((size_t)((b * 8 + h) * 64 + d)) * 2048 + (m0 >> 1) + mm] = v;
    }
}

// ---------------------------------------------------------------------------
// Flash attention: 64 q-rows/CTA, 256 threads (4 q-groups x 2 key halves),
// 128-key iterations, 3-stage ring (6 sub-stages), one __syncthreads per
// 128 keys. Static-max softmax via ex2.f16x2; fused hi/lo output split.
// Grid = 1024 CTAs -> ~7 waves of half-size CTAs (tail ~1%).
// ---------------------------------------------------------------------------
#define ASUB_K(s) ((s) * 9216)
#define ASUB_V(s) (55296 + (s) * 9216)
#define ATT_SMEM 110592

__global__ __launch_bounds__(256) void attn_mma_kernel(
    const uint32_t* __restrict__ Qh, const uint32_t* __restrict__ Kh,
    const uint32_t* __restrict__ Vt, const uint32_t* __restrict__ Mb,
    uint32_t* __restrict__ Oh, uint32_t* __restrict__ Ol)
{
    extern __shared__ uint32_t smn[];
    const int b = blockIdx.z, h = blockIdx.y;
    const int q0 = blockIdx.x * 64;
    const int t = threadIdx.x, w = t >> 5, lane = t & 31;
    const int qr = lane >> 2, qc = lane & 3;
    const int wq = w & 3;          // q-row group (4 x 16 rows)
    const int g  = w >> 2;         // 32-key half within each 64-key chunk

    const uint32_t smb = smem_u32(smn);
    const size_t bh = (size_t)(b * 8 + h);
    const int n0 = q0 + wq * 16 + qr;
    const int n1 = n0 + 8;

    const uint32_t lmk = ((g * 32 + (lane & 7)) * 36 + (lane >> 3) * 4) * 4;
    const uint32_t lmv = (((lane & 7)) * 36 + g * 16 + (lane >> 3) * 4) * 4;

    const uint32_t* Kg = Kh + bh * SEQ_M * 32;
    const uint32_t* Vg = Vt + bh * HDIM * 2048;
    const uint32_t* Mrow = Mb + (size_t)b * 128 * 4096;

    // one issue = 128 keys (2 sub-stages); 256 threads -> 2 rows each
    auto issue = [&](int tt) {
        const int seg = (t & 7) * 4;
#pragma unroll
        for (int cc = 0; cc < 2; ++cc) {
            const int sub = (2 * tt + cc) % 6;
            const int mk = tt * 128 + cc * 64;
#pragma unroll
            for (int i = 0; i < 2; ++i) {
                const int row = i * 32 + (t >> 3);
                cp16(smb + ASUB_K(sub) + (row * 36 + seg) * 4,
                     &Kg[(size_t)(mk + row) * 32 + seg]);
                cp16(smb + ASUB_V(sub) + (row * 36 + seg) * 4,
                     &Vg[(size_t)row * 2048 + (mk >> 1) + seg]);
            }
        }
        cp_commit();
    };

    issue(0);
    issue(1);

    uint32_t qa[4][4];
    {
        const uint32_t* Qb = Qh + (bh * 4096 + q0 + (size_t)wq * 16) * 32;
#pragma unroll
        for (int kc = 0; kc < 4; ++kc) {
            qa[kc][0] = Qb[qr * 32 + kc * 8 + qc];
            qa[kc][1] = Qb[(qr + 8) * 32 + kc * 8 + qc];
            qa[kc][2] = Qb[qr * 32 + kc * 8 + qc + 4];
            qa[kc][3] = Qb[(qr + 8) * 32 + kc * 8 + qc + 4];
        }
    }

    float o[8][4];
#pragma unroll
    for (int j = 0; j < 8; ++j)
#pragma unroll
        for (int k = 0; k < 4; ++k) o[j][k] = 0.f;
    float l0 = 0.f, l1 = 0.f;

    auto chunk = [&](int sub, uint32_t mw0, uint32_t mw1) {
        const uint32_t ksb = smb + ASUB_K(sub) + lmk;
        const uint32_t vsb = smb + ASUB_V(sub) + lmv;
        float c[4][4];
#pragma unroll
        for (int u = 0; u < 4; ++u) {
            uint32_t kf[4], kf2[4];
            ldsm_x4(kf,  ksb + u * 1152);
            ldsm_x4(kf2, ksb + u * 1152 + 64);
            c[u][0] = c[u][1] = c[u][2] = c[u][3] = 0.f;
            mma_f16(c[u], qa[0], kf[0], kf[1]);
            mma_f16(c[u], qa[1], kf[2], kf[3]);
            mma_f16(c[u], qa[2], kf2[0], kf2[1]);
            mma_f16(c[u], qa[3], kf2[2], kf2[3]);
        }
        uint32_t pa[2][4];
#pragma unroll
        for (int j = 0; j < 4; ++j) {
            int sh = j * 8 + qc * 2;
            if ((mw0 >> sh) & 1u)       c[j][0] = -1e30f;
            if ((mw0 >> (sh + 1)) & 1u) c[j][1] = -1e30f;
            if ((mw1 >> sh) & 1u)       c[j][2] = -1e30f;
            if ((mw1 >> (sh + 1)) & 1u) c[j][3] = -1e30f;
        }
#pragma unroll
        for (int kc = 0; kc < 2; ++kc) {
            pa[kc][0] = ex2h2(pack_h2(c[2 * kc][0], c[2 * kc][1]));
            pa[kc][1] = ex2h2(pack_h2(c[2 * kc][2], c[2 * kc][3]));
            pa[kc][2] = ex2h2(pack_h2(c[2 * kc + 1][0], c[2 * kc + 1][1]));
            pa[kc][3] = ex2h2(pack_h2(c[2 * kc + 1][2], c[2 * kc + 1][3]));
        }
#pragma unroll
        for (int kc = 0; kc < 2; ++kc) {
            float2 f0 = __half22float2(*(__half2*)&pa[kc][0]);
            float2 f1 = __half22float2(*(__half2*)&pa[kc][1]);
            float2 f2 = __half22float2(*(__half2*)&pa[kc][2]);
            float2 f3 = __half22float2(*(__half2*)&pa[kc][3]);
            l0 += f0.x + f0.y + f2.x + f2.y;
            l1 += f1.x + f1.y + f3.x + f3.y;
        }
#pragma unroll
        for (int u = 0; u < 4; ++u) {
            uint32_t vf0[4], vf1[4];
            ldsm_x4(vf0, vsb + (2 * u) * 1152);
            ldsm_x4(vf1, vsb + (2 * u + 1) * 1152);
            mma_f16(o[2 * u],     pa[0], vf0[0], vf0[1]);
            mma_f16(o[2 * u + 1], pa[0], vf1[0], vf1[1]);
            mma_f16(o[2 * u],     pa[1], vf0[2], vf0[3]);
            mma_f16(o[2 * u + 1], pa[1], vf1[2], vf1[3]);
        }
    };

    for (int tt = 0; tt < 32; ++tt) {
        const int wzA = tt * 4 + g;
        const int wzB = tt * 4 + 2 + g;
        uint32_t ma0 = Mrow[(size_t)wzA * 4096 + n0];
        uint32_t ma1 = Mrow[(size_t)wzA * 4096 + n1];
        uint32_t mb0 = Mrow[(size_t)wzB * 4096 + n0];
        uint32_t mb1 = Mrow[(size_t)wzB * 4096 + n1];

        if (tt < 31) cp_wait1(); else cp_wait0();
        __syncthreads();

        chunk((2 * tt) % 6,     ma0, ma1);
        chunk((2 * tt + 1) % 6, mb0, mb1);

        if (tt + 2 < 32) issue(tt + 2);
    }

    l0 += __shfl_xor_sync(0xffffffffu, l0, 1);
    l0 += __shfl_xor_sync(0xffffffffu, l0, 2);
    l1 += __shfl_xor_sync(0xffffffffu, l1, 1);
    l1 += __shfl_xor_sync(0xffffffffu, l1, 2);

    // merge the two key-halves via smem (stages are dead now)
    float* sf = reinterpret_cast<float*>(smn);
    const int ro0 = wq * 16 + qr, ro1 = ro0 + 8;
    const int LOFF = 64 * 66;
    __syncthreads();
    if (g == 0) {
#pragma unroll
        for (int j = 0; j < 8; ++j) {
            int col = j * 8 + qc * 2;
            sf[ro0 * 66 + col]     = o[j][0];
            sf[ro0 * 66 + col + 1] = o[j][1];
            sf[ro1 * 66 + col]     = o[j][2];
            sf[ro1 * 66 + col + 1] = o[j][3];
        }
        if (qc == 0) { sf[LOFF + ro0] = l0; sf[LOFF + ro1] = l1; }
    }
    __syncthreads();
    if (g == 1) {
        float i0 = 1.f / fmaxf(l0 + sf[LOFF + ro0], 1e-30f);
        float i1 = 1.f / fmaxf(l1 + sf[LOFF + ro1], 1e-30f);
#pragma unroll
        for (int j = 0; j < 8; ++j) {
            int col = j * 8 + qc * 2;
            float v0 = (o[j][0] + sf[ro0 * 66 + col])     * i0;
            float v1 = (o[j][1] + sf[ro0 * 66 + col + 1]) * i0;
            float v2 = (o[j][2] + sf[ro1 * 66 + col])     * i1;
            float v3 = (o[j][3] + sf[ro1 * 66 + col + 1]) * i1;
            int colw = h * 32 + j * 4 + qc;
            __half h0 = __float2half(v0), h1 = __float2half(v1);
            __half h2 = __float2half(v2), h3 = __float2half(v3);
            Oh[(size_t)n0 * 256 + (size_t)b * 4096 * 256 + colw] =
                ((uint32_t)__half_as_ushort(h1) << 16) | __half_as_ushort(h0);
            Ol[(size_t)n0 * 256 + (size_t)b * 4096 * 256 + colw] =
                pack_h2(v0 - __half2float(h0), v1 - __half2float(h1));
            Oh[(size_t)n1 * 256 + (size_t)b * 4096 * 256 + colw] =
                ((uint32_t)__half_as_ushort(h3) << 16) | __half_as_ushort(h2);
            Ol[(size_t)n1 * 256 + (size_t)b * 4096 * 256 + colw] =
                pack_h2(v2 - __half2float(h2), v3 - __half2float(h3));
        }
    }
}

// ---------------------------------------------------------------------------
// Launch
// ---------------------------------------------------------------------------
extern "C" void kernel_launch(void* const* d_in, const int* in_sizes, int n_in,
                              void* d_out, int out_size)
{
    const float* x       = (const float*)d_in[0];
    const float* context = (const float*)d_in[1];
    const int*   pos_x   = (const int*)d_in[2];
    const int*   pos_ctx = (const int*)d_in[3];
    const unsigned char* mask = (const unsigned char*)d_in[4];
    const float* Wq = (const float*)d_in[5];
    const float* bq = (const float*)d_in[6];
    const float* Wk = (const float*)d_in[7];
    const float* bk = (const float*)d_in[8];
    const float* Wv = (const float*)d_in[9];
    const float* bv = (const float*)d_in[10];
    const float* Wo = (const float*)d_in[11];
    const float* bo = (const float*)d_in[12];
    float* out = (float*)d_out;

    float *qp, *kp, *vp;
    __half *qh, *kh;
    uint32_t *vt, *mb;
    __half *xh, *xl, *chh, *wth, *wtl;
    cudaGetSymbolAddress((void**)&qp, g_Q);
    cudaGetSymbolAddress((void**)&kp, g_K);
    cudaGetSymbolAddress((void**)&vp, g_V);
    cudaGetSymbolAddress((void**)&qh, g_Qh);
    cudaGetSymbolAddress((void**)&kh, g_Kh);
    cudaGetSymbolAddress((void**)&vt, g_Vt);
    cudaGetSymbolAddress((void**)&mb, g_Mbits);
    cudaGetSymbolAddress((void**)&xh, g_Xh);
    cudaGetSymbolAddress((void**)&xl, g_Xl);
    cudaGetSymbolAddress((void**)&chh, g_Ch);
    cudaGetSymbolAddress((void**)&wth, g_Wth);
    cudaGetSymbolAddress((void**)&wtl, g_Wtl);

    const int WSZ2 = DIM_C * DIM_C / 2;
    const int GEMM_SMEM = 2 * GSTAGE_WORDS * 4;   // 80 KB
    cudaFuncSetAttribute(gemm_mma_kernel,
                         cudaFuncAttributeMaxDynamicSharedMemorySize, GEMM_SMEM);
    cudaFuncSetAttribute(attn_mma_kernel,
                         cudaFuncAttributeMaxDynamicSharedMemorySize, ATT_SMEM);

    dim3 wgrid(8, 8, 4);
    wsplit4_kernel<<<wgrid, 256>>>(Wq, Wk, Wv, Wo, (uint32_t*)wth, (uint32_t*)wtl);

    const int n4 = BATCH * SEQ_N * DIM_C / 4;
    dim3 sgrid(n4 / 256, 2);
    split2_kernel<<<sgrid, 256>>>((const float4*)x, (const float4*)context,
                                  (uint2*)xh, (uint2*)chh, n4);

    detect_mask_kernel<<<1, 256>>>((const uint32_t*)mask);

    dim3 ggrid(DIM_C / 128, (BATCH * SEQ_N) / 128);   // (4, 64)
    gemm_mma_kernel<<<ggrid, 512, GEMM_SMEM>>>(
        (const uint32_t*)xh, (const uint32_t*)xl,
        (const uint32_t*)wth + 0 * WSZ2, (const uint32_t*)wtl + 0 * WSZ2, bq, qp, 1);

    pack_mask_kernel<<<BATCH * SEQ_N, 128>>>(mask, mb);

    gemm_mma_kernel<<<ggrid, 512, GEMM_SMEM>>>(
        (const uint32_t*)chh, (const uint32_t*)chh,
        (const uint32_t*)wth + 1 * WSZ2, (const uint32_t*)wtl + 1 * WSZ2, bk, kp, 1);
    gemm_mma_kernel<<<ggrid, 512, GEMM_SMEM>>>(
        (const uint32_t*)chh, (const uint32_t*)chh,
        (const uint32_t*)wth + 2 * WSZ2, (const uint32_t*)wtl + 2 * WSZ2, bv, vp, 1);

    const int rope_total = BATCH * SEQ_N * HEADS * 32;
    const float qscale = 0.125f * 1.4426950408889634f;
    rope2d_h_kernel<<<(rope_total + 255) / 256, 256>>>(qp, qh, pos_x, qscale, rope_total);
    rope2d_h_kernel<<<(rope_total + 255) / 256, 256>>>(kp, kh, pos_ctx, 1.0f, rope_total);

    dim3 vgrid(SEQ_M / 64, HEADS, BATCH);
    vtrans_kernel<<<vgrid, 256>>>(vp, vt);

    dim3 agrid(SEQ_N / 64, HEADS, BATCH);   // (64, 8, 2) = 1024 CTAs
    attn_mma_kernel<<<agrid, 256, ATT_SMEM>>>(
        (const uint32_t*)qh, (const uint32_t*)kh, vt, mb,
        (uint32_t*)xh, (uint32_t*)xl);

    gemm_mma_kernel<<<ggrid, 512, GEMM_SMEM>>>(
        (const uint32_t*)xh, (const uint32_t*)xl,
        (const uint32_t*)wth + 3 * WSZ2, (const uint32_t*)wtl + 3 * WSZ2, bo, out, 3);
}

// round 14
// speedup vs baseline: 1.4191x; 1.1087x over previous
#include <cuda_runtime.h>
#include <cuda_fp16.h>
#include <cstdint>

#define BATCH 2
#define SEQ_N 4096
#define SEQ_M 4096
#define DIM_C 512
#define HEADS 8
#define HDIM  64

// ---------------------------------------------------------------------------
// Scratch
// ---------------------------------------------------------------------------
__device__ float g_Q[BATCH * SEQ_N * DIM_C];
__device__ float g_K[BATCH * SEQ_M * DIM_C];
__device__ float g_V[BATCH * SEQ_M * DIM_C];
__device__ __half g_Qh[BATCH * HEADS * SEQ_N * HDIM];
__device__ __half g_Kh[BATCH * HEADS * SEQ_M * HDIM];
__device__ __half g_Vt[BATCH * HEADS * HDIM * SEQ_M];
__device__ uint32_t g_Mbits[BATCH * 128 * SEQ_N];
__device__ int g_maskBool;
__device__ __half g_Xh[BATCH * SEQ_N * DIM_C];
__device__ __half g_Xl[BATCH * SEQ_N * DIM_C];
__device__ __half g_Ch[BATCH * SEQ_M * DIM_C];
__device__ __half g_Wth[4 * DIM_C * DIM_C];   // transposed [n][k]
__device__ __half g_Wtl[4 * DIM_C * DIM_C];

// ---------------------------------------------------------------------------
// helpers
// ---------------------------------------------------------------------------
__device__ __forceinline__ uint32_t pack_h2(float lo, float hi) {
    uint32_t r; asm("cvt.rn.f16x2.f32 %0, %1, %2;" : "=r"(r) : "f"(hi), "f"(lo)); return r;
}
__device__ __forceinline__ uint32_t ex2h2(uint32_t x) {
    uint32_t y; asm("ex2.approx.f16x2 %0, %1;" : "=r"(y) : "r"(x)); return y;
}
__device__ __forceinline__ void mma_f16(float c[4], const uint32_t a[4],
                                        uint32_t b0, uint32_t b1) {
    asm volatile(
        "mma.sync.aligned.m16n8k16.row.col.f32.f16.f16.f32 "
        "{%0,%1,%2,%3}, {%4,%5,%6,%7}, {%8,%9}, {%0,%1,%2,%3};"
        : "+f"(c[0]), "+f"(c[1]), "+f"(c[2]), "+f"(c[3])
        : "r"(a[0]), "r"(a[1]), "r"(a[2]), "r"(a[3]), "r"(b0), "r"(b1));
}
__device__ __forceinline__ void ldsm_x4(uint32_t r[4], uint32_t addr) {
    asm volatile("ldmatrix.sync.aligned.m8n8.x4.shared.b16 {%0,%1,%2,%3}, [%4];"
                 : "=r"(r[0]), "=r"(r[1]), "=r"(r[2]), "=r"(r[3]) : "r"(addr));
}
__device__ __forceinline__ uint32_t smem_u32(const void* p) {
    return (uint32_t)__cvta_generic_to_shared(p);
}
__device__ __forceinline__ void cp16(uint32_t smem_dst, const void* gsrc) {
    asm volatile("cp.async.cg.shared.global [%0], [%1], 16;" ::
                 "r"(smem_dst), "l"(gsrc));
}
__device__ __forceinline__ void cp_commit() {
    asm volatile("cp.async.commit_group;");
}
__device__ __forceinline__ void cp_wait1() {
    asm volatile("cp.async.wait_group 1;");
}
__device__ __forceinline__ void cp_wait0() {
    asm volatile("cp.async.wait_group 0;");
}

// ---------------------------------------------------------------------------
// Mask dtype detection + packing (verified)
// ---------------------------------------------------------------------------
__global__ void detect_mask_kernel(const uint32_t* __restrict__ m)
{
    __shared__ int found;
    if (threadIdx.x == 0) found = 0;
    __syncthreads();
    uint32_t v = m[threadIdx.x] | m[threadIdx.x + 256] |
                 m[threadIdx.x + 512] | m[threadIdx.x + 768];
    if (v > 1u) atomicOr(&found, 1);
    __syncthreads();
    if (threadIdx.x == 0) g_maskBool = found;
}

__global__ __launch_bounds__(128) void pack_mask_kernel(
    const unsigned char* __restrict__ mraw, uint32_t* __restrict__ out)
{
    const int bn = blockIdx.x;
    const int w  = threadIdx.x;
    const int b  = bn >> 12;
    const int n  = bn & 4095;
    uint32_t bits = 0;
    if (g_maskBool) {
        const uint32_t* p = (const uint32_t*)(mraw + (size_t)bn * 4096) + w * 8;
#pragma unroll
        for (int i = 0; i < 8; ++i) {
            uint32_t v = p[i];
#pragma unroll
            for (int j = 0; j < 4; ++j)
                if ((v >> (j * 8)) & 0xFFu) bits |= 1u << (i * 4 + j);
        }
    } else {
        const int* p = (const int*)mraw + (size_t)bn * 4096 + w * 32;
#pragma unroll
        for (int i = 0; i < 32; ++i)
            if (p[i] != 0) bits |= 1u << i;
    }
    out[((size_t)(b * 128 + w)) * 4096 + n] = bits;
}

// ---------------------------------------------------------------------------
// All 4 weights: transpose + fp16 split; lo residual only for Wo (z==3)
// ---------------------------------------------------------------------------
__global__ __launch_bounds__(256) void wsplit4_kernel(
    const float* __restrict__ W0, const float* __restrict__ W1,
    const float* __restrict__ W2, const float* __restrict__ W3,
    uint32_t* __restrict__ Wth, uint32_t* __restrict__ Wtl)
{
    const int z = blockIdx.z;
    const float* W = (z == 0) ? W0 : (z == 1) ? W1 : (z == 2) ? W2 : W3;
    uint32_t* oh = Wth + (size_t)z * (DIM_C * DIM_C / 2);
    uint32_t* ol = Wtl + (size_t)z * (DIM_C * DIM_C / 2);

    const int n0 = blockIdx.x * 64;
    const int k0 = blockIdx.y * 64;
    const int t  = threadIdx.x;
    __shared__ float S[64][65];
#pragma unroll
    for (int i = 0; i < 16; ++i) {
        int e = i * 256 + t;
        int r = e >> 6, c = e & 63;
        S[r][c] = W[(size_t)(k0 + r) * 512 + n0 + c];
    }
    __syncthreads();
#pragma unroll
    for (int i = 0; i < 8; ++i) {
        int e = i * 256 + t;
        int n = e >> 5, kw = e & 31;
        float v0 = S[2 * kw][n], v1 = S[2 * kw + 1][n];
        __half h0 = __float2half(v0), h1 = __float2half(v1);
        size_t dst = (size_t)(n0 + n) * 256 + (k0 >> 1) + kw;
        oh[dst] = ((uint32_t)__half_as_ushort(h1) << 16) | __half_as_ushort(h0);
        if (z == 3) {
            float r0 = v0 - __half2float(h0), r1 = v1 - __half2float(h1);
            ol[dst] = pack_h2(r0, r1);
        }
    }
}

// ---------------------------------------------------------------------------
// x and context fp16 hi-conversion in one launch
// ---------------------------------------------------------------------------
__global__ void split2_kernel(const float4* __restrict__ x, const float4* __restrict__ ctx,
                              uint2* __restrict__ xh, uint2* __restrict__ ch, int n4)
{
    int i = blockIdx.x * blockDim.x + threadIdx.x;
    if (i >= n4) return;
    const float4* s = blockIdx.y ? ctx : x;
    uint2* oh = blockIdx.y ? ch : xh;
    float4 v = s[i];
    __half hx = __float2half(v.x), hy = __float2half(v.y);
    __half hz = __float2half(v.z), hw = __float2half(v.w);
    uint2 h;
    h.x = ((uint32_t)__half_as_ushort(hy) << 16) | __half_as_ushort(hx);
    h.y = ((uint32_t)__half_as_ushort(hw) << 16) | __half_as_ushort(hz);
    oh[i] = h;
}

// ---------------------------------------------------------------------------
// Single-product GEMM (Q/K/V): BK=64, 8 iterations, 2 x 32KB stages.
// Stage layout (words): A[128*36] W[128*36]  (32 words data + 4 pad per row)
// ---------------------------------------------------------------------------
#define G1_ROW 36
#define G1_STAGE_WORDS (2 * 128 * G1_ROW)
__global__ __launch_bounds__(512) void gemm1_mma_kernel(
    const uint32_t* __restrict__ Ah, const uint32_t* __restrict__ Wth,
    const float* __restrict__ bias, float* __restrict__ Y)
{
    extern __shared__ uint32_t sm[];
    const int row0 = blockIdx.y * 128;
    const int col0 = blockIdx.x * 128;
    const int t = threadIdx.x, w = t >> 5, lane = t & 31;
    const int wm = w & 3, wn = w >> 2;
    const int qr = lane >> 2, qc = lane & 3;

    const uint32_t smb = smem_u32(sm);

    float acc[2][4][4];
#pragma unroll
    for (int mt = 0; mt < 2; ++mt)
#pragma unroll
        for (int n = 0; n < 4; ++n)
#pragma unroll
            for (int k = 0; k < 4; ++k) acc[mt][n][k] = 0.f;

    const int a_row = wm * 32 + (lane & 7) + ((lane >> 3) & 1) * 8;
    const int a_wrd = (lane >> 4) * 4;
    const uint32_t ah_o = (a_row * G1_ROW + a_wrd) * 4;
    const int b_row = wn * 32 + (lane & 7);
    const int b_wrd = (lane >> 3) * 4;
    const uint32_t wh_o = (128 * G1_ROW + b_row * G1_ROW + b_wrd) * 4;

    // cp.async: 512 thr, 8 x 16B rows of 128B -> each thread 2 segs per buf
    const int ldr = t >> 2;            // 0..127
    const int lds = (t & 3) * 4;       // word offset 0,4,8,12

    auto issue = [&](int ch, int st) {
        const int kw = ch * 32;
        const uint32_t sb = smb + st * G1_STAGE_WORDS * 4;
        size_t ga = (size_t)(row0 + ldr) * 256 + kw + lds;
        size_t gw = (size_t)(col0 + ldr) * 256 + kw + lds;
        uint32_t so = (ldr * G1_ROW + lds) * 4;
        cp16(sb + so, &Ah[ga]);
        cp16(sb + so + 64, &Ah[ga + 16]);
        cp16(sb + 128 * G1_ROW * 4 + so, &Wth[gw]);
        cp16(sb + 128 * G1_ROW * 4 + so + 64, &Wth[gw + 16]);
        cp_commit();
    };

    issue(0, 0);
    issue(1, 1);

    for (int ch = 0; ch < 8; ++ch) {
        if (ch < 7) cp_wait1(); else cp_wait0();
        __syncthreads();

        const uint32_t sb = smb + (ch & 1) * G1_STAGE_WORDS * 4;
        uint32_t ahi[2][4][4];
#pragma unroll
        for (int mt = 0; mt < 2; ++mt)
#pragma unroll
            for (int kc = 0; kc < 4; ++kc)
                ldsm_x4(ahi[mt][kc], sb + ah_o + (mt * 16 * G1_ROW + kc * 8) * 4);
#pragma unroll
        for (int np = 0; np < 2; ++np) {
            const int n0 = 2 * np, n1 = 2 * np + 1;
            uint32_t b0a[4], b0b[4], b1a[4], b1b[4];
            ldsm_x4(b0a, sb + wh_o + (n0 * 8 * G1_ROW) * 4);
            ldsm_x4(b0b, sb + wh_o + (n0 * 8 * G1_ROW + 16) * 4);
            ldsm_x4(b1a, sb + wh_o + (n1 * 8 * G1_ROW) * 4);
            ldsm_x4(b1b, sb + wh_o + (n1 * 8 * G1_ROW + 16) * 4);
#pragma unroll
            for (int kc = 0; kc < 4; ++kc) {
                uint32_t p0 = (kc < 2) ? b0a[2 * kc] : b0b[2 * (kc - 2)];
                uint32_t p1 = (kc < 2) ? b0a[2 * kc + 1] : b0b[2 * (kc - 2) + 1];
                uint32_t p2 = (kc < 2) ? b1a[2 * kc] : b1b[2 * (kc - 2)];
                uint32_t p3 = (kc < 2) ? b1a[2 * kc + 1] : b1b[2 * (kc - 2) + 1];
                mma_f16(acc[0][n0], ahi[0][kc], p0, p1);
                mma_f16(acc[1][n0], ahi[1][kc], p0, p1);
                mma_f16(acc[0][n1], ahi[0][kc], p2, p3);
                mma_f16(acc[1][n1], ahi[1][kc], p2, p3);
            }
        }
        __syncthreads();
        if (ch + 2 < 8) issue(ch + 2, ch & 1);
    }

#pragma unroll
    for (int mt = 0; mt < 2; ++mt)
#pragma unroll
        for (int n = 0; n < 4; ++n) {
            int row = row0 + wm * 32 + mt * 16 + qr;
            int col = col0 + wn * 32 + n * 8 + qc * 2;
            float2 bi = *(const float2*)&bias[col];
            float2 v0 = make_float2(acc[mt][n][0] + bi.x, acc[mt][n][1] + bi.y);
            float2 v1 = make_float2(acc[mt][n][2] + bi.x, acc[mt][n][3] + bi.y);
            *(float2*)&Y[(size_t)row * 512 + col] = v0;
            *(float2*)&Y[(size_t)(row + 8) * 512 + col] = v1;
        }
}

// ---------------------------------------------------------------------------
// 3-product fp16-split GEMM for the O projection (verified R11/R12)
// ---------------------------------------------------------------------------
#define GSTAGE_WORDS (4 * 128 * 20)
__global__ __launch_bounds__(512) void gemm3_mma_kernel(
    const uint32_t* __restrict__ Ah, const uint32_t* __restrict__ Al,
    const uint32_t* __restrict__ Wth, const uint32_t* __restrict__ Wtl,
    const float* __restrict__ bias, float* __restrict__ Y)
{
    extern __shared__ uint32_t sm[];
    const int row0 = blockIdx.y * 128;
    const int col0 = blockIdx.x * 128;
    const int t = threadIdx.x, w = t >> 5, lane = t & 31;
    const int wm = w & 3, wn = w >> 2;
    const int qr = lane >> 2, qc = lane & 3;

    const uint32_t smb = smem_u32(sm);

    float acc[2][4][4];
#pragma unroll
    for (int mt = 0; mt < 2; ++mt)
#pragma unroll
        for (int n = 0; n < 4; ++n)
#pragma unroll
            for (int k = 0; k < 4; ++k) acc[mt][n][k] = 0.f;

    const int a_row = wm * 32 + (lane & 7) + ((lane >> 3) & 1) * 8;
    const int a_wrd = (lane >> 4) * 4;
    const uint32_t ah_o = (0 * 2560 + a_row * 20 + a_wrd) * 4;
    const uint32_t al_o = (1 * 2560 + a_row * 20 + a_wrd) * 4;
    const int b_row = wn * 32 + (lane & 7);
    const int b_wrd = (lane >> 3) * 4;
    const uint32_t wh_o = (2 * 2560 + b_row * 20 + b_wrd) * 4;
    const uint32_t wl_o = (3 * 2560 + b_row * 20 + b_wrd) * 4;

    const int ldr = t >> 2;
    const int lds = (t & 3) * 4;

    auto issue = [&](int ch, int st) {
        const int kw = ch * 16;
        const uint32_t sb = smb + st * GSTAGE_WORDS * 4;
        size_t ga = (size_t)(row0 + ldr) * 256 + kw + lds;
        size_t gw = (size_t)(col0 + ldr) * 256 + kw + lds;
        uint32_t so = (ldr * 20 + lds) * 4;
        cp16(sb + 0 * 2560 * 4 + so, &Ah[ga]);
        cp16(sb + 1 * 2560 * 4 + so, &Al[ga]);
        cp16(sb + 2 * 2560 * 4 + so, &Wth[gw]);
        cp16(sb + 3 * 2560 * 4 + so, &Wtl[gw]);
        cp_commit();
    };

    issue(0, 0);
    issue(1, 1);

    for (int ch = 0; ch < 16; ++ch) {
        if (ch < 15) cp_wait1(); else cp_wait0();
        __syncthreads();

        const uint32_t sb = smb + (ch & 1) * GSTAGE_WORDS * 4;
        uint32_t ahi[2][2][4], alo[2][2][4];
#pragma unroll
        for (int mt = 0; mt < 2; ++mt)
#pragma unroll
            for (int kc = 0; kc < 2; ++kc) {
                ldsm_x4(ahi[mt][kc], sb + ah_o + (mt * 16 * 20 + kc * 8) * 4);
                ldsm_x4(alo[mt][kc], sb + al_o + (mt * 16 * 20 + kc * 8) * 4);
            }
#pragma unroll
        for (int np = 0; np < 2; ++np) {
            const int n0 = 2 * np, n1 = 2 * np + 1;
            uint32_t bh0[4], bh1[4], bl0[4], bl1[4];
            ldsm_x4(bh0, sb + wh_o + n0 * 8 * 20 * 4);
            ldsm_x4(bh1, sb + wh_o + n1 * 8 * 20 * 4);
            ldsm_x4(bl0, sb + wl_o + n0 * 8 * 20 * 4);
            ldsm_x4(bl1, sb + wl_o + n1 * 8 * 20 * 4);
            mma_f16(acc[0][n0], ahi[0][0], bh0[0], bh0[1]);
            mma_f16(acc[1][n0], ahi[1][0], bh0[0], bh0[1]);
            mma_f16(acc[0][n1], ahi[0][0], bh1[0], bh1[1]);
            mma_f16(acc[1][n1], ahi[1][0], bh1[0], bh1[1]);
            mma_f16(acc[0][n0], ahi[0][1], bh0[2], bh0[3]);
            mma_f16(acc[1][n0], ahi[1][1], bh0[2], bh0[3]);
            mma_f16(acc[0][n1], ahi[0][1], bh1[2], bh1[3]);
            mma_f16(acc[1][n1], ahi[1][1], bh1[2], bh1[3]);
            mma_f16(acc[0][n0], alo[0][0], bh0[0], bh0[1]);
            mma_f16(acc[1][n0], alo[1][0], bh0[0], bh0[1]);
            mma_f16(acc[0][n1], alo[0][0], bh1[0], bh1[1]);
            mma_f16(acc[1][n1], alo[1][0], bh1[0], bh1[1]);
            mma_f16(acc[0][n0], alo[0][1], bh0[2], bh0[3]);
            mma_f16(acc[1][n0], alo[1][1], bh0[2], bh0[3]);
            mma_f16(acc[0][n1], alo[0][1], bh1[2], bh1[3]);
            mma_f16(acc[1][n1], alo[1][1], bh1[2], bh1[3]);
            mma_f16(acc[0][n0], ahi[0][0], bl0[0], bl0[1]);
            mma_f16(acc[1][n0], ahi[1][0], bl0[0], bl0[1]);
            mma_f16(acc[0][n1], ahi[0][0], bl1[0], bl1[1]);
            mma_f16(acc[1][n1], ahi[1][0], bl1[0], bl1[1]);
            mma_f16(acc[0][n0], ahi[0][1], bl0[2], bl0[3]);
            mma_f16(acc[1][n0], ahi[1][1], bl0[2], bl0[3]);
            mma_f16(acc[0][n1], ahi[0][1], bl1[2], bl1[3]);
            mma_f16(acc[1][n1], ahi[1][1], bl1[2], bl1[3]);
        }
        __syncthreads();
        if (ch + 2 < 16) issue(ch + 2, ch & 1);
    }

#pragma unroll
    for (int mt = 0; mt < 2; ++mt)
#pragma unroll
        for (int n = 0; n < 4; ++n) {
            int row = row0 + wm * 32 + mt * 16 + qr;
            int col = col0 + wn * 32 + n * 8 + qc * 2;
            float2 bi = *(const float2*)&bias[col];
            float2 v0 = make_float2(acc[mt][n][0] + bi.x, acc[mt][n][1] + bi.y);
            float2 v1 = make_float2(acc[mt][n][2] + bi.x, acc[mt][n][3] + bi.y);
            *(float2*)&Y[(size_t)row * 512 + col] = v0;
            *(float2*)&Y[(size_t)(row + 8) * 512 + col] = v1;
        }
}

// ---------------------------------------------------------------------------
// RoPE 2D, Q and K in one launch (grid.y: 0=Q with scale, 1=K)
// ---------------------------------------------------------------------------
__global__ void rope2d_h_kernel(const float* __restrict__ srcQ, const float* __restrict__ srcK,
                                __half* __restrict__ dstQ, __half* __restrict__ dstK,
                                const int* __restrict__ posQ, const int* __restrict__ posK,
                                float qscale, int total)
{
    int idx = blockIdx.x * blockDim.x + threadIdx.x;
    if (idx >= total) return;
    const float* src = blockIdx.y ? srcK : srcQ;
    __half* dst = blockIdx.y ? dstK : dstQ;
    const int* pos = blockIdx.y ? posK : posQ;
    float scale = blockIdx.y ? 1.0f : qscale;

    int pair = idx & 31;
    int h    = (idx >> 5) & 7;
    int n    = (idx >> 8) & 4095;
    int b    = idx >> 20;
    int blk  = pair >> 4;
    int ii   = pair & 15;

    float invf = exp2f(-(float)ii * 0.41524101186092864f);
    int p = pos[((size_t)(b * 4096 + n)) * 2 + blk];
    float ang = (float)p * invf;
    float sn, cs;
    sincosf(ang, &sn, &cs);

    size_t sbase = ((size_t)(b * 4096 + n) * 8 + h) * 64 + blk * 32 + ii;
    float v1 = src[sbase];
    float v2 = src[sbase + 16];
    size_t dbase = ((size_t)((b * 8 + h) * 4096 + n)) * 64 + blk * 32 + ii;
    dst[dbase]      = __float2half((v1 * cs - v2 * sn) * scale);
    dst[dbase + 16] = __float2half((v2 * cs + v1 * sn) * scale);
}

// ---------------------------------------------------------------------------
// V: fp32 [b,m,(h,d)] -> fp16 transposed [b,h,d,m]
// ---------------------------------------------------------------------------
__global__ __launch_bounds__(256) void vtrans_kernel(
    const float* __restrict__ V, uint32_t* __restrict__ Vt)
{
    const int m0 = blockIdx.x * 64;
    const int h  = blockIdx.y;
    const int b  = blockIdx.z;
    const int t  = threadIdx.x;
    __shared__ float S[64][65];
#pragma unroll
    for (int i = 0; i < 16; ++i) {
        int e = i * 256 + t;
        int m = e >> 6, d = e & 63;
        S[m][d] = V[((size_t)(b * 4096 + m0 + m)) * 512 + h * 64 + d];
    }
    __syncthreads();
#pragma unroll
    for (int i = 0; i < 8; ++i) {
        int e = i * 256 + t;
        int d = e >> 5, mm = e & 31;
        uint32_t v = pack_h2(S[2 * mm][d], S[2 * mm + 1][d]);
        Vt[((size_t)((b * 8 + h) * 64 + d)) * 2048 + (m0 >> 1) + mm] = v;
    }
}

// ---------------------------------------------------------------------------
// Flash attention (verified R13): 64 q-rows/CTA, 256 threads, 128-key
// iterations, 6 sub-stage ring, one sync per 128 keys. Now with
// __launch_bounds__(256, 2) to enable 2 CTAs/SM (smem 108KB x 2 <= 228KB).
// ---------------------------------------------------------------------------
#define ASUB_K(s) ((s) * 9216)
#define ASUB_V(s) (55296 + (s) * 9216)
#define ATT_SMEM 110592

__global__ __launch_bounds__(256, 2) void attn_mma_kernel(
    const uint32_t* __restrict__ Qh, const uint32_t* __restrict__ Kh,
    const uint32_t* __restrict__ Vt, const uint32_t* __restrict__ Mb,
    uint32_t* __restrict__ Oh, uint32_t* __restrict__ Ol)
{
    extern __shared__ uint32_t smn[];
    const int b = blockIdx.z, h = blockIdx.y;
    const int q0 = blockIdx.x * 64;
    const int t = threadIdx.x, w = t >> 5, lane = t & 31;
    const int qr = lane >> 2, qc = lane & 3;
    const int wq = w & 3;
    const int g  = w >> 2;

    const uint32_t smb = smem_u32(smn);
    const size_t bh = (size_t)(b * 8 + h);
    const int n0 = q0 + wq * 16 + qr;
    const int n1 = n0 + 8;

    const uint32_t lmk = ((g * 32 + (lane & 7)) * 36 + (lane >> 3) * 4) * 4;
    const uint32_t lmv = (((lane & 7)) * 36 + g * 16 + (lane >> 3) * 4) * 4;

    const uint32_t* Kg = Kh + bh * SEQ_M * 32;
    const uint32_t* Vg = Vt + bh * HDIM * 2048;
    const uint32_t* Mrow = Mb + (size_t)b * 128 * 4096;

    auto issue = [&](int tt) {
        const int seg = (t & 7) * 4;
#pragma unroll
        for (int cc = 0; cc < 2; ++cc) {
            const int sub = (2 * tt + cc) % 6;
            const int mk = tt * 128 + cc * 64;
#pragma unroll
            for (int i = 0; i < 2; ++i) {
                const int row = i * 32 + (t >> 3);
                cp16(smb + ASUB_K(sub) + (row * 36 + seg) * 4,
                     &Kg[(size_t)(mk + row) * 32 + seg]);
                cp16(smb + ASUB_V(sub) + (row * 36 + seg) * 4,
                     &Vg[(size_t)row * 2048 + (mk >> 1) + seg]);
            }
        }
        cp_commit();
    };

    issue(0);
    issue(1);

    uint32_t qa[4][4];
    {
        const uint32_t* Qb = Qh + (bh * 4096 + q0 + (size_t)wq * 16) * 32;
#pragma unroll
        for (int kc = 0; kc < 4; ++kc) {
            qa[kc][0] = Qb[qr * 32 + kc * 8 + qc];
            qa[kc][1] = Qb[(qr + 8) * 32 + kc * 8 + qc];
            qa[kc][2] = Qb[qr * 32 + kc * 8 + qc + 4];
            qa[kc][3] = Qb[(qr + 8) * 32 + kc * 8 + qc + 4];
        }
    }

    float o[8][4];
#pragma unroll
    for (int j = 0; j < 8; ++j)
#pragma unroll
        for (int k = 0; k < 4; ++k) o[j][k] = 0.f;
    float l0 = 0.f, l1 = 0.f;

    auto chunk = [&](int sub, uint32_t mw0, uint32_t mw1) {
        const uint32_t ksb = smb + ASUB_K(sub) + lmk;
        const uint32_t vsb = smb + ASUB_V(sub) + lmv;
        float c[4][4];
#pragma unroll
        for (int u = 0; u < 4; ++u) {
            uint32_t kf[4], kf2[4];
            ldsm_x4(kf,  ksb + u * 1152);
            ldsm_x4(kf2, ksb + u * 1152 + 64);
            c[u][0] = c[u][1] = c[u][2] = c[u][3] = 0.f;
            mma_f16(c[u], qa[0], kf[0], kf[1]);
            mma_f16(c[u], qa[1], kf[2], kf[3]);
            mma_f16(c[u], qa[2], kf2[0], kf2[1]);
            mma_f16(c[u], qa[3], kf2[2], kf2[3]);
        }
        uint32_t pa[2][4];
#pragma unroll
        for (int j = 0; j < 4; ++j) {
            int sh = j * 8 + qc * 2;
            if ((mw0 >> sh) & 1u)       c[j][0] = -1e30f;
            if ((mw0 >> (sh + 1)) & 1u) c[j][1] = -1e30f;
            if ((mw1 >> sh) & 1u)       c[j][2] = -1e30f;
            if ((mw1 >> (sh + 1)) & 1u) c[j][3] = -1e30f;
        }
#pragma unroll
        for (int kc = 0; kc < 2; ++kc) {
            pa[kc][0] = ex2h2(pack_h2(c[2 * kc][0], c[2 * kc][1]));
            pa[kc][1] = ex2h2(pack_h2(c[2 * kc][2], c[2 * kc][3]));
            pa[kc][2] = ex2h2(pack_h2(c[2 * kc + 1][0], c[2 * kc + 1][1]));
            pa[kc][3] = ex2h2(pack_h2(c[2 * kc + 1][2], c[2 * kc + 1][3]));
        }
#pragma unroll
        for (int kc = 0; kc < 2; ++kc) {
            float2 f0 = __half22float2(*(__half2*)&pa[kc][0]);
            float2 f1 = __half22float2(*(__half2*)&pa[kc][1]);
            float2 f2 = __half22float2(*(__half2*)&pa[kc][2]);
            float2 f3 = __half22float2(*(__half2*)&pa[kc][3]);
            l0 += f0.x + f0.y + f2.x + f2.y;
            l1 += f1.x + f1.y + f3.x + f3.y;
        }
#pragma unroll
        for (int u = 0; u < 4; ++u) {
            uint32_t vf0[4], vf1[4];
            ldsm_x4(vf0, vsb + (2 * u) * 1152);
            ldsm_x4(vf1, vsb + (2 * u + 1) * 1152);
            mma_f16(o[2 * u],     pa[0], vf0[0], vf0[1]);
            mma_f16(o[2 * u + 1], pa[0], vf1[0], vf1[1]);
            mma_f16(o[2 * u],     pa[1], vf0[2], vf0[3]);
            mma_f16(o[2 * u + 1], pa[1], vf1[2], vf1[3]);
        }
    };

    for (int tt = 0; tt < 32; ++tt) {
        const int wzA = tt * 4 + g;
        const int wzB = tt * 4 + 2 + g;
        uint32_t ma0 = Mrow[(size_t)wzA * 4096 + n0];
        uint32_t ma1 = Mrow[(size_t)wzA * 4096 + n1];
        uint32_t mb0 = Mrow[(size_t)wzB * 4096 + n0];
        uint32_t mb1 = Mrow[(size_t)wzB * 4096 + n1];

        if (tt < 31) cp_wait1(); else cp_wait0();
        __syncthreads();

        chunk((2 * tt) % 6,     ma0, ma1);
        chunk((2 * tt + 1) % 6, mb0, mb1);

        if (tt + 2 < 32) issue(tt + 2);
    }

    l0 += __shfl_xor_sync(0xffffffffu, l0, 1);
    l0 += __shfl_xor_sync(0xffffffffu, l0, 2);
    l1 += __shfl_xor_sync(0xffffffffu, l1, 1);
    l1 += __shfl_xor_sync(0xffffffffu, l1, 2);

    float* sf = reinterpret_cast<float*>(smn);
    const int ro0 = wq * 16 + qr, ro1 = ro0 + 8;
    const int LOFF = 64 * 66;
    __syncthreads();
    if (g == 0) {
#pragma unroll
        for (int j = 0; j < 8; ++j) {
            int col = j * 8 + qc * 2;
            sf[ro0 * 66 + col]     = o[j][0];
            sf[ro0 * 66 + col + 1] = o[j][1];
            sf[ro1 * 66 + col]     = o[j][2];
            sf[ro1 * 66 + col + 1] = o[j][3];
        }
        if (qc == 0) { sf[LOFF + ro0] = l0; sf[LOFF + ro1] = l1; }
    }
    __syncthreads();
    if (g == 1) {
        float i0 = 1.f / fmaxf(l0 + sf[LOFF + ro0], 1e-30f);
        float i1 = 1.f / fmaxf(l1 + sf[LOFF + ro1], 1e-30f);
#pragma unroll
        for (int j = 0; j < 8; ++j) {
            int col = j * 8 + qc * 2;
            float v0 = (o[j][0] + sf[ro0 * 66 + col])     * i0;
            float v1 = (o[j][1] + sf[ro0 * 66 + col + 1]) * i0;
            float v2 = (o[j][2] + sf[ro1 * 66 + col])     * i1;
            float v3 = (o[j][3] + sf[ro1 * 66 + col + 1]) * i1;
            int colw = h * 32 + j * 4 + qc;
            __half h0 = __float2half(v0), h1 = __float2half(v1);
            __half h2 = __float2half(v2), h3 = __float2half(v3);
            Oh[(size_t)n0 * 256 + (size_t)b * 4096 * 256 + colw] =
                ((uint32_t)__half_as_ushort(h1) << 16) | __half_as_ushort(h0);
            Ol[(size_t)n0 * 256 + (size_t)b * 4096 * 256 + colw] =
                pack_h2(v0 - __half2float(h0), v1 - __half2float(h1));
            Oh[(size_t)n1 * 256 + (size_t)b * 4096 * 256 + colw] =
                ((uint32_t)__half_as_ushort(h3) << 16) | __half_as_ushort(h2);
            Ol[(size_t)n1 * 256 + (size_t)b * 4096 * 256 + colw] =
                pack_h2(v2 - __half2float(h2), v3 - __half2float(h3));
        }
    }
}

// ---------------------------------------------------------------------------
// Launch
// ---------------------------------------------------------------------------
extern "C" void kernel_launch(void* const* d_in, const int* in_sizes, int n_in,
                              void* d_out, int out_size)
{
    const float* x       = (const float*)d_in[0];
    const float* context = (const float*)d_in[1];
    const int*   pos_x   = (const int*)d_in[2];
    const int*   pos_ctx = (const int*)d_in[3];
    const unsigned char* mask = (const unsigned char*)d_in[4];
    const float* Wq = (const float*)d_in[5];
    const float* bq = (const float*)d_in[6];
    const float* Wk = (const float*)d_in[7];
    const float* bk = (const float*)d_in[8];
    const float* Wv = (const float*)d_in[9];
    const float* bv = (const float*)d_in[10];
    const float* Wo = (const float*)d_in[11];
    const float* bo = (const float*)d_in[12];
    float* out = (float*)d_out;

    float *qp, *kp, *vp;
    __half *qh, *kh;
    uint32_t *vt, *mb;
    __half *xh, *xl, *chh, *wth, *wtl;
    cudaGetSymbolAddress((void**)&qp, g_Q);
    cudaGetSymbolAddress((void**)&kp, g_K);
    cudaGetSymbolAddress((void**)&vp, g_V);
    cudaGetSymbolAddress((void**)&qh, g_Qh);
    cudaGetSymbolAddress((void**)&kh, g_Kh);
    cudaGetSymbolAddress((void**)&vt, g_Vt);
    cudaGetSymbolAddress((void**)&mb, g_Mbits);
    cudaGetSymbolAddress((void**)&xh, g_Xh);
    cudaGetSymbolAddress((void**)&xl, g_Xl);
    cudaGetSymbolAddress((void**)&chh, g_Ch);
    cudaGetSymbolAddress((void**)&wth, g_Wth);
    cudaGetSymbolAddress((void**)&wtl, g_Wtl);

    const int WSZ2 = DIM_C * DIM_C / 2;
    const int G1_SMEM = 2 * G1_STAGE_WORDS * 4;   // 72 KB
    const int G3_SMEM = 2 * GSTAGE_WORDS * 4;     // 80 KB
    cudaFuncSetAttribute(gemm1_mma_kernel,
                         cudaFuncAttributeMaxDynamicSharedMemorySize, G1_SMEM);
    cudaFuncSetAttribute(gemm3_mma_kernel,
                         cudaFuncAttributeMaxDynamicSharedMemorySize, G3_SMEM);
    cudaFuncSetAttribute(attn_mma_kernel,
                         cudaFuncAttributeMaxDynamicSharedMemorySize, ATT_SMEM);

    dim3 wgrid(8, 8, 4);
    wsplit4_kernel<<<wgrid, 256>>>(Wq, Wk, Wv, Wo, (uint32_t*)wth, (uint32_t*)wtl);

    const int n4 = BATCH * SEQ_N * DIM_C / 4;
    dim3 sgrid(n4 / 256, 2);
    split2_kernel<<<sgrid, 256>>>((const float4*)x, (const float4*)context,
                                  (uint2*)xh, (uint2*)chh, n4);

    detect_mask_kernel<<<1, 256>>>((const uint32_t*)mask);

    dim3 ggrid(DIM_C / 128, (BATCH * SEQ_N) / 128);   // (4, 64)
    gemm1_mma_kernel<<<ggrid, 512, G1_SMEM>>>(
        (const uint32_t*)xh, (const uint32_t*)wth + 0 * WSZ2, bq, qp);

    pack_mask_kernel<<<BATCH * SEQ_N, 128>>>(mask, mb);

    gemm1_mma_kernel<<<ggrid, 512, G1_SMEM>>>(
        (const uint32_t*)chh, (const uint32_t*)wth + 1 * WSZ2, bk, kp);
    gemm1_mma_kernel<<<ggrid, 512, G1_SMEM>>>(
        (const uint32_t*)chh, (const uint32_t*)wth + 2 * WSZ2, bv, vp);

    const int rope_total = BATCH * SEQ_N * HEADS * 32;
    const float qscale = 0.125f * 1.4426950408889634f;
    dim3 rgrid((rope_total + 255) / 256, 2);
    rope2d_h_kernel<<<rgrid, 256>>>(qp, kp, qh, kh, pos_x, pos_ctx,
                                    qscale, rope_total);

    dim3 vgrid(SEQ_M / 64, HEADS, BATCH);
    vtrans_kernel<<<vgrid, 256>>>(vp, vt);

    dim3 agrid(SEQ_N / 64, HEADS, BATCH);   // 1024 CTAs
    attn_mma_kernel<<<agrid, 256, ATT_SMEM>>>(
        (const uint32_t*)qh, (const uint32_t*)kh, vt, mb,
        (uint32_t*)xh, (uint32_t*)xl);

    gemm3_mma_kernel<<<ggrid, 512, G3_SMEM>>>(
        (const uint32_t*)xh, (const uint32_t*)xl,
        (const uint32_t*)wth + 3 * WSZ2, (const uint32_t*)wtl + 3 * WSZ2, bo, out);
}

// round 16
// speedup vs baseline: 1.4649x; 1.0323x over previous
#include <cuda_runtime.h>
#include <cuda_fp16.h>
#include <cstdint>

#define BATCH 2
#define SEQ_N 4096
#define SEQ_M 4096
#define DIM_C 512
#define HEADS 8
#define HDIM  64

// ---------------------------------------------------------------------------
// Scratch
// ---------------------------------------------------------------------------
__device__ float g_Q[BATCH * SEQ_N * DIM_C];
__device__ float g_K[BATCH * SEQ_M * DIM_C];
__device__ __half g_Qh[BATCH * HEADS * SEQ_N * HDIM];
__device__ __half g_Kh[BATCH * HEADS * SEQ_M * HDIM];
__device__ __half g_Vt[DIM_C * BATCH * SEQ_M];   // [dfull][b*m]
__device__ uint32_t g_Mbits[BATCH * 128 * SEQ_N];
__device__ int g_maskBool;
__device__ __half g_Xh[BATCH * SEQ_N * DIM_C];
__device__ __half g_Xl[BATCH * SEQ_N * DIM_C];
__device__ __half g_Ch[BATCH * SEQ_M * DIM_C];
__device__ __half g_Wth[4 * DIM_C * DIM_C];   // transposed [n][k], hi only

// ---------------------------------------------------------------------------
// helpers
// ---------------------------------------------------------------------------
__device__ __forceinline__ uint32_t pack_h2(float lo, float hi) {
    uint32_t r; asm("cvt.rn.f16x2.f32 %0, %1, %2;" : "=r"(r) : "f"(hi), "f"(lo)); return r;
}
__device__ __forceinline__ uint32_t ex2h2(uint32_t x) {
    uint32_t y; asm("ex2.approx.f16x2 %0, %1;" : "=r"(y) : "r"(x)); return y;
}
__device__ __forceinline__ void mma_f16(float c[4], const uint32_t a[4],
                                        uint32_t b0, uint32_t b1) {
    asm volatile(
        "mma.sync.aligned.m16n8k16.row.col.f32.f16.f16.f32 "
        "{%0,%1,%2,%3}, {%4,%5,%6,%7}, {%8,%9}, {%0,%1,%2,%3};"
        : "+f"(c[0]), "+f"(c[1]), "+f"(c[2]), "+f"(c[3])
        : "r"(a[0]), "r"(a[1]), "r"(a[2]), "r"(a[3]), "r"(b0), "r"(b1));
}
__device__ __forceinline__ void ldsm_x4(uint32_t r[4], uint32_t addr) {
    asm volatile("ldmatrix.sync.aligned.m8n8.x4.shared.b16 {%0,%1,%2,%3}, [%4];"
                 : "=r"(r[0]), "=r"(r[1]), "=r"(r[2]), "=r"(r[3]) : "r"(addr));
}
__device__ __forceinline__ uint32_t smem_u32(const void* p) {
    return (uint32_t)__cvta_generic_to_shared(p);
}
__device__ __forceinline__ void cp16(uint32_t smem_dst, const void* gsrc) {
    asm volatile("cp.async.cg.shared.global [%0], [%1], 16;" ::
                 "r"(smem_dst), "l"(gsrc));
}
__device__ __forceinline__ void cp_commit() {
    asm volatile("cp.async.commit_group;");
}
__device__ __forceinline__ void cp_wait1() {
    asm volatile("cp.async.wait_group 1;");
}
__device__ __forceinline__ void cp_wait0() {
    asm volatile("cp.async.wait_group 0;");
}

// ---------------------------------------------------------------------------
// Mask dtype detection + packing (verified)
// ---------------------------------------------------------------------------
__global__ void detect_mask_kernel(const uint32_t* __restrict__ m)
{
    __shared__ int found;
    if (threadIdx.x == 0) found = 0;
    __syncthreads();
    uint32_t v = m[threadIdx.x] | m[threadIdx.x + 256] |
                 m[threadIdx.x + 512] | m[threadIdx.x + 768];
    if (v > 1u) atomicOr(&found, 1);
    __syncthreads();
    if (threadIdx.x == 0) g_maskBool = found;
}

__global__ __launch_bounds__(128) void pack_mask_kernel(
    const unsigned char* __restrict__ mraw, uint32_t* __restrict__ out)
{
    const int bn = blockIdx.x;
    const int w  = threadIdx.x;
    const int b  = bn >> 12;
    const int n  = bn & 4095;
    uint32_t bits = 0;
    if (g_maskBool) {
        const uint32_t* p = (const uint32_t*)(mraw + (size_t)bn * 4096) + w * 8;
#pragma unroll
        for (int i = 0; i < 8; ++i) {
            uint32_t v = p[i];
#pragma unroll
            for (int j = 0; j < 4; ++j)
                if ((v >> (j * 8)) & 0xFFu) bits |= 1u << (i * 4 + j);
        }
    } else {
        const int* p = (const int*)mraw + (size_t)bn * 4096 + w * 32;
#pragma unroll
        for (int i = 0; i < 32; ++i)
            if (p[i] != 0) bits |= 1u << i;
    }
    out[((size_t)(b * 128 + w)) * 4096 + n] = bits;
}

// ---------------------------------------------------------------------------
// All 4 weights: transpose + fp16 hi conversion
// ---------------------------------------------------------------------------
__global__ __launch_bounds__(256) void wsplit4_kernel(
    const float* __restrict__ W0, const float* __restrict__ W1,
    const float* __restrict__ W2, const float* __restrict__ W3,
    uint32_t* __restrict__ Wth)
{
    const int z = blockIdx.z;
    const float* W = (z == 0) ? W0 : (z == 1) ? W1 : (z == 2) ? W2 : W3;
    uint32_t* oh = Wth + (size_t)z * (DIM_C * DIM_C / 2);

    const int n0 = blockIdx.x * 64;
    const int k0 = blockIdx.y * 64;
    const int t  = threadIdx.x;
    __shared__ float S[64][65];
#pragma unroll
    for (int i = 0; i < 16; ++i) {
        int e = i * 256 + t;
        int r = e >> 6, c = e & 63;
        S[r][c] = W[(size_t)(k0 + r) * 512 + n0 + c];
    }
    __syncthreads();
#pragma unroll
    for (int i = 0; i < 8; ++i) {
        int e = i * 256 + t;
        int n = e >> 5, kw = e & 31;
        float v0 = S[2 * kw][n], v1 = S[2 * kw + 1][n];
        __half h0 = __float2half(v0), h1 = __float2half(v1);
        size_t dst = (size_t)(n0 + n) * 256 + (k0 >> 1) + kw;
        oh[dst] = ((uint32_t)__half_as_ushort(h1) << 16) | __half_as_ushort(h0);
    }
}

// ---------------------------------------------------------------------------
// x and context fp16 hi-conversion in one launch
// ---------------------------------------------------------------------------
__global__ void split2_kernel(const float4* __restrict__ x, const float4* __restrict__ ctx,
                              uint2* __restrict__ xh, uint2* __restrict__ ch, int n4)
{
    int i = blockIdx.x * blockDim.x + threadIdx.x;
    if (i >= n4) return;
    const float4* s = blockIdx.y ? ctx : x;
    uint2* oh = blockIdx.y ? ch : xh;
    float4 v = s[i];
    __half hx = __float2half(v.x), hy = __float2half(v.y);
    __half hz = __float2half(v.z), hw = __float2half(v.w);
    uint2 h;
    h.x = ((uint32_t)__half_as_ushort(hy) << 16) | __half_as_ushort(hx);
    h.y = ((uint32_t)__half_as_ushort(hw) << 16) | __half_as_ushort(hz);
    oh[i] = h;
}

// ---------------------------------------------------------------------------
// Single-product GEMM (Q/K): BK=64, 8 iterations, 2 x 32KB stages. (verified)
// ---------------------------------------------------------------------------
#define G1_ROW 36
#define G1_STAGE_WORDS (2 * 128 * G1_ROW)
__global__ __launch_bounds__(512) void gemm1_mma_kernel(
    const uint32_t* __restrict__ Ah, const uint32_t* __restrict__ Wth,
    const float* __restrict__ bias, float* __restrict__ Y)
{
    extern __shared__ uint32_t sm[];
    const int row0 = blockIdx.y * 128;
    const int col0 = blockIdx.x * 128;
    const int t = threadIdx.x, w = t >> 5, lane = t & 31;
    const int wm = w & 3, wn = w >> 2;
    const int qr = lane >> 2, qc = lane & 3;

    const uint32_t smb = smem_u32(sm);

    float acc[2][4][4];
#pragma unroll
    for (int mt = 0; mt < 2; ++mt)
#pragma unroll
        for (int n = 0; n < 4; ++n)
#pragma unroll
            for (int k = 0; k < 4; ++k) acc[mt][n][k] = 0.f;

    const int a_row = wm * 32 + (lane & 7) + ((lane >> 3) & 1) * 8;
    const int a_wrd = (lane >> 4) * 4;
    const uint32_t ah_o = (a_row * G1_ROW + a_wrd) * 4;
    const int b_row = wn * 32 + (lane & 7);
    const int b_wrd = (lane >> 3) * 4;
    const uint32_t wh_o = (128 * G1_ROW + b_row * G1_ROW + b_wrd) * 4;

    const int ldr = t >> 2;
    const int lds = (t & 3) * 4;

    auto issue = [&](int ch, int st) {
        const int kw = ch * 32;
        const uint32_t sb = smb + st * G1_STAGE_WORDS * 4;
        size_t ga = (size_t)(row0 + ldr) * 256 + kw + lds;
        size_t gw = (size_t)(col0 + ldr) * 256 + kw + lds;
        uint32_t so = (ldr * G1_ROW + lds) * 4;
        cp16(sb + so, &Ah[ga]);
        cp16(sb + so + 64, &Ah[ga + 16]);
        cp16(sb + 128 * G1_ROW * 4 + so, &Wth[gw]);
        cp16(sb + 128 * G1_ROW * 4 + so + 64, &Wth[gw + 16]);
        cp_commit();
    };

    issue(0, 0);
    issue(1, 1);

    for (int ch = 0; ch < 8; ++ch) {
        if (ch < 7) cp_wait1(); else cp_wait0();
        __syncthreads();

        const uint32_t sb = smb + (ch & 1) * G1_STAGE_WORDS * 4;
        uint32_t ahi[2][4][4];
#pragma unroll
        for (int mt = 0; mt < 2; ++mt)
#pragma unroll
            for (int kc = 0; kc < 4; ++kc)
                ldsm_x4(ahi[mt][kc], sb + ah_o + (mt * 16 * G1_ROW + kc * 8) * 4);
#pragma unroll
        for (int np = 0; np < 2; ++np) {
            const int n0 = 2 * np, n1 = 2 * np + 1;
            uint32_t b0a[4], b0b[4], b1a[4], b1b[4];
            ldsm_x4(b0a, sb + wh_o + (n0 * 8 * G1_ROW) * 4);
            ldsm_x4(b0b, sb + wh_o + (n0 * 8 * G1_ROW + 16) * 4);
            ldsm_x4(b1a, sb + wh_o + (n1 * 8 * G1_ROW) * 4);
            ldsm_x4(b1b, sb + wh_o + (n1 * 8 * G1_ROW + 16) * 4);
#pragma unroll
            for (int kc = 0; kc < 4; ++kc) {
                uint32_t p0 = (kc < 2) ? b0a[2 * kc] : b0b[2 * (kc - 2)];
                uint32_t p1 = (kc < 2) ? b0a[2 * kc + 1] : b0b[2 * (kc - 2) + 1];
                uint32_t p2 = (kc < 2) ? b1a[2 * kc] : b1b[2 * (kc - 2)];
                uint32_t p3 = (kc < 2) ? b1a[2 * kc + 1] : b1b[2 * (kc - 2) + 1];
                mma_f16(acc[0][n0], ahi[0][kc], p0, p1);
                mma_f16(acc[1][n0], ahi[1][kc], p0, p1);
                mma_f16(acc[0][n1], ahi[0][kc], p2, p3);
                mma_f16(acc[1][n1], ahi[1][kc], p2, p3);
            }
        }
        __syncthreads();
        if (ch + 2 < 8) issue(ch + 2, ch & 1);
    }

#pragma unroll
    for (int mt = 0; mt < 2; ++mt)
#pragma unroll
        for (int n = 0; n < 4; ++n) {
            int row = row0 + wm * 32 + mt * 16 + qr;
            int col = col0 + wn * 32 + n * 8 + qc * 2;
            float2 bi = *(const float2*)&bias[col];
            float2 v0 = make_float2(acc[mt][n][0] + bi.x, acc[mt][n][1] + bi.y);
            float2 v1 = make_float2(acc[mt][n][2] + bi.x, acc[mt][n][3] + bi.y);
            *(float2*)&Y[(size_t)row * 512 + col] = v0;
            *(float2*)&Y[(size_t)(row + 8) * 512 + col] = v1;
        }
}

// ---------------------------------------------------------------------------
// V GEMM, transposed output: Vt[dfull][b*m] fp16 = WvT x context^T + bv.
// A = WvT (512 rows), B operand = context-hi (8192 rows); grid (64, 4).
// Epilogue writes word index row*4096 + col/2 (col = b*4096 + m).
// ---------------------------------------------------------------------------
__global__ __launch_bounds__(512) void gemm1t_mma_kernel(
    const uint32_t* __restrict__ Ah, const uint32_t* __restrict__ Wth,
    const float* __restrict__ bias, uint32_t* __restrict__ Yh)
{
    extern __shared__ uint32_t sm[];
    const int row0 = blockIdx.y * 128;
    const int col0 = blockIdx.x * 128;
    const int t = threadIdx.x, w = t >> 5, lane = t & 31;
    const int wm = w & 3, wn = w >> 2;
    const int qr = lane >> 2, qc = lane & 3;

    const uint32_t smb = smem_u32(sm);

    float acc[2][4][4];
#pragma unroll
    for (int mt = 0; mt < 2; ++mt)
#pragma unroll
        for (int n = 0; n < 4; ++n)
#pragma unroll
            for (int k = 0; k < 4; ++k) acc[mt][n][k] = 0.f;

    const int a_row = wm * 32 + (lane & 7) + ((lane >> 3) & 1) * 8;
    const int a_wrd = (lane >> 4) * 4;
    const uint32_t ah_o = (a_row * G1_ROW + a_wrd) * 4;
    const int b_row = wn * 32 + (lane & 7);
    const int b_wrd = (lane >> 3) * 4;
    const uint32_t wh_o = (128 * G1_ROW + b_row * G1_ROW + b_wrd) * 4;

    const int ldr = t >> 2;
    const int lds = (t & 3) * 4;

    auto issue = [&](int ch, int st) {
        const int kw = ch * 32;
        const uint32_t sb = smb + st * G1_STAGE_WORDS * 4;
        size_t ga = (size_t)(row0 + ldr) * 256 + kw + lds;
        size_t gw = (size_t)(col0 + ldr) * 256 + kw + lds;
        uint32_t so = (ldr * G1_ROW + lds) * 4;
        cp16(sb + so, &Ah[ga]);
        cp16(sb + so + 64, &Ah[ga + 16]);
        cp16(sb + 128 * G1_ROW * 4 + so, &Wth[gw]);
        cp16(sb + 128 * G1_ROW * 4 + so + 64, &Wth[gw + 16]);
        cp_commit();
    };

    issue(0, 0);
    issue(1, 1);

    for (int ch = 0; ch < 8; ++ch) {
        if (ch < 7) cp_wait1(); else cp_wait0();
        __syncthreads();

        const uint32_t sb = smb + (ch & 1) * G1_STAGE_WORDS * 4;
        uint32_t ahi[2][4][4];
#pragma unroll
        for (int mt = 0; mt < 2; ++mt)
#pragma unroll
            for (int kc = 0; kc < 4; ++kc)
                ldsm_x4(ahi[mt][kc], sb + ah_o + (mt * 16 * G1_ROW + kc * 8) * 4);
#pragma unroll
        for (int np = 0; np < 2; ++np) {
            const int n0 = 2 * np, n1 = 2 * np + 1;
            uint32_t b0a[4], b0b[4], b1a[4], b1b[4];
            ldsm_x4(b0a, sb + wh_o + (n0 * 8 * G1_ROW) * 4);
            ldsm_x4(b0b, sb + wh_o + (n0 * 8 * G1_ROW + 16) * 4);
            ldsm_x4(b1a, sb + wh_o + (n1 * 8 * G1_ROW) * 4);
            ldsm_x4(b1b, sb + wh_o + (n1 * 8 * G1_ROW + 16) * 4);
#pragma unroll
            for (int kc = 0; kc < 4; ++kc) {
                uint32_t p0 = (kc < 2) ? b0a[2 * kc] : b0b[2 * (kc - 2)];
                uint32_t p1 = (kc < 2) ? b0a[2 * kc + 1] : b0b[2 * (kc - 2) + 1];
                uint32_t p2 = (kc < 2) ? b1a[2 * kc] : b1b[2 * (kc - 2)];
                uint32_t p3 = (kc < 2) ? b1a[2 * kc + 1] : b1b[2 * (kc - 2) + 1];
                mma_f16(acc[0][n0], ahi[0][kc], p0, p1);
                mma_f16(acc[1][n0], ahi[1][kc], p0, p1);
                mma_f16(acc[0][n1], ahi[0][kc], p2, p3);
                mma_f16(acc[1][n1], ahi[1][kc], p2, p3);
            }
        }
        __syncthreads();
        if (ch + 2 < 8) issue(ch + 2, ch & 1);
    }

    // transposed fp16 epilogue: Yh word index = row * 4096 + col/2
#pragma unroll
    for (int mt = 0; mt < 2; ++mt)
#pragma unroll
        for (int n = 0; n < 4; ++n) {
            int row = row0 + wm * 32 + mt * 16 + qr;
            int col = col0 + wn * 32 + n * 8 + qc * 2;
            float b0 = bias[row];
            float b1 = bias[row + 8];
            Yh[(size_t)row * 4096 + (col >> 1)] =
                pack_h2(acc[mt][n][0] + b0, acc[mt][n][1] + b0);
            Yh[(size_t)(row + 8) * 4096 + (col >> 1)] =
                pack_h2(acc[mt][n][2] + b1, acc[mt][n][3] + b1);
        }
}

// ---------------------------------------------------------------------------
// 2-product GEMM for the O projection: Y = (Ah + Al) x Wh + bias.
// ---------------------------------------------------------------------------
#define G2STAGE_WORDS (3 * 128 * 20)
__global__ __launch_bounds__(512) void gemm2_mma_kernel(
    const uint32_t* __restrict__ Ah, const uint32_t* __restrict__ Al,
    const uint32_t* __restrict__ Wth,
    const float* __restrict__ bias, float* __restrict__ Y)
{
    extern __shared__ uint32_t sm[];
    const int row0 = blockIdx.y * 128;
    const int col0 = blockIdx.x * 128;
    const int t = threadIdx.x, w = t >> 5, lane = t & 31;
    const int wm = w & 3, wn = w >> 2;
    const int qr = lane >> 2, qc = lane & 3;

    const uint32_t smb = smem_u32(sm);

    float acc[2][4][4];
#pragma unroll
    for (int mt = 0; mt < 2; ++mt)
#pragma unroll
        for (int n = 0; n < 4; ++n)
#pragma unroll
            for (int k = 0; k < 4; ++k) acc[mt][n][k] = 0.f;

    const int a_row = wm * 32 + (lane & 7) + ((lane >> 3) & 1) * 8;
    const int a_wrd = (lane >> 4) * 4;
    const uint32_t ah_o = (0 * 2560 + a_row * 20 + a_wrd) * 4;
    const uint32_t al_o = (1 * 2560 + a_row * 20 + a_wrd) * 4;
    const int b_row = wn * 32 + (lane & 7);
    const int b_wrd = (lane >> 3) * 4;
    const uint32_t wh_o = (2 * 2560 + b_row * 20 + b_wrd) * 4;

    const int ldr = t >> 2;
    const int lds = (t & 3) * 4;

    auto issue = [&](int ch, int st) {
        const int kw = ch * 16;
        const uint32_t sb = smb + st * G2STAGE_WORDS * 4;
        size_t ga = (size_t)(row0 + ldr) * 256 + kw + lds;
        size_t gw = (size_t)(col0 + ldr) * 256 + kw + lds;
        uint32_t so = (ldr * 20 + lds) * 4;
        cp16(sb + 0 * 2560 * 4 + so, &Ah[ga]);
        cp16(sb + 1 * 2560 * 4 + so, &Al[ga]);
        cp16(sb + 2 * 2560 * 4 + so, &Wth[gw]);
        cp_commit();
    };

    issue(0, 0);
    issue(1, 1);

    for (int ch = 0; ch < 16; ++ch) {
        if (ch < 15) cp_wait1(); else cp_wait0();
        __syncthreads();

        const uint32_t sb = smb + (ch & 1) * G2STAGE_WORDS * 4;
        uint32_t ahi[2][2][4], alo[2][2][4];
#pragma unroll
        for (int mt = 0; mt < 2; ++mt)
#pragma unroll
            for (int kc = 0; kc < 2; ++kc) {
                ldsm_x4(ahi[mt][kc], sb + ah_o + (mt * 16 * 20 + kc * 8) * 4);
                ldsm_x4(alo[mt][kc], sb + al_o + (mt * 16 * 20 + kc * 8) * 4);
            }
#pragma unroll
        for (int np = 0; np < 2; ++np) {
            const int n0 = 2 * np, n1 = 2 * np + 1;
            uint32_t bh0[4], bh1[4];
            ldsm_x4(bh0, sb + wh_o + n0 * 8 * 20 * 4);
            ldsm_x4(bh1, sb + wh_o + n1 * 8 * 20 * 4);
            mma_f16(acc[0][n0], ahi[0][0], bh0[0], bh0[1]);
            mma_f16(acc[1][n0], ahi[1][0], bh0[0], bh0[1]);
            mma_f16(acc[0][n1], ahi[0][0], bh1[0], bh1[1]);
            mma_f16(acc[1][n1], ahi[1][0], bh1[0], bh1[1]);
            mma_f16(acc[0][n0], ahi[0][1], bh0[2], bh0[3]);
            mma_f16(acc[1][n0], ahi[1][1], bh0[2], bh0[3]);
            mma_f16(acc[0][n1], ahi[0][1], bh1[2], bh1[3]);
            mma_f16(acc[1][n1], ahi[1][1], bh1[2], bh1[3]);
            mma_f16(acc[0][n0], alo[0][0], bh0[0], bh0[1]);
            mma_f16(acc[1][n0], alo[1][0], bh0[0], bh0[1]);
            mma_f16(acc[0][n1], alo[0][0], bh1[0], bh1[1]);
            mma_f16(acc[1][n1], alo[1][0], bh1[0], bh1[1]);
            mma_f16(acc[0][n0], alo[0][1], bh0[2], bh0[3]);
            mma_f16(acc[1][n0], alo[1][1], bh0[2], bh0[3]);
            mma_f16(acc[0][n1], alo[0][1], bh1[2], bh1[3]);
            mma_f16(acc[1][n1], alo[1][1], bh1[2], bh1[3]);
        }
        __syncthreads();
        if (ch + 2 < 16) issue(ch + 2, ch & 1);
    }

#pragma unroll
    for (int mt = 0; mt < 2; ++mt)
#pragma unroll
        for (int n = 0; n < 4; ++n) {
            int row = row0 + wm * 32 + mt * 16 + qr;
            int col = col0 + wn * 32 + n * 8 + qc * 2;
            float2 bi = *(const float2*)&bias[col];
            float2 v0 = make_float2(acc[mt][n][0] + bi.x, acc[mt][n][1] + bi.y);
            float2 v1 = make_float2(acc[mt][n][2] + bi.x, acc[mt][n][3] + bi.y);
            *(float2*)&Y[(size_t)row * 512 + col] = v0;
            *(float2*)&Y[(size_t)(row + 8) * 512 + col] = v1;
        }
}

// ---------------------------------------------------------------------------
// RoPE 2D, Q and K in one launch (grid.y: 0=Q with scale, 1=K)
// ---------------------------------------------------------------------------
__global__ void rope2d_h_kernel(const float* __restrict__ srcQ, const float* __restrict__ srcK,
                                __half* __restrict__ dstQ, __half* __restrict__ dstK,
                                const int* __restrict__ posQ, const int* __restrict__ posK,
                                float qscale, int total)
{
    int idx = blockIdx.x * blockDim.x + threadIdx.x;
    if (idx >= total) return;
    const float* src = blockIdx.y ? srcK : srcQ;
    __half* dst = blockIdx.y ? dstK : dstQ;
    const int* pos = blockIdx.y ? posK : posQ;
    float scale = blockIdx.y ? 1.0f : qscale;

    int pair = idx & 31;
    int h    = (idx >> 5) & 7;
    int n    = (idx >> 8) & 4095;
    int b    = idx >> 20;
    int blk  = pair >> 4;
    int ii   = pair & 15;

    float invf = exp2f(-(float)ii * 0.41524101186092864f);
    int p = pos[((size_t)(b * 4096 + n)) * 2 + blk];
    float ang = (float)p * invf;
    float sn, cs;
    sincosf(ang, &sn, &cs);

    size_t sbase = ((size_t)(b * 4096 + n) * 8 + h) * 64 + blk * 32 + ii;
    float v1 = src[sbase];
    float v2 = src[sbase + 16];
    size_t dbase = ((size_t)((b * 8 + h) * 4096 + n)) * 64 + blk * 32 + ii;
    dst[dbase]      = __float2half((v1 * cs - v2 * sn) * scale);
    dst[dbase + 16] = __float2half((v2 * cs + v1 * sn) * scale);
}

// ---------------------------------------------------------------------------
// Flash attention (verified R13/R14), updated V layout [dfull][b*m]:
// Vg = Vt + (h*64)*4096 + b*2048, row stride 4096 words.
// ---------------------------------------------------------------------------
#define ASUB_K(s) ((s) * 9216)
#define ASUB_V(s) (55296 + (s) * 9216)
#define ATT_SMEM 110592

__global__ __launch_bounds__(256, 2) void attn_mma_kernel(
    const uint32_t* __restrict__ Qh, const uint32_t* __restrict__ Kh,
    const uint32_t* __restrict__ Vt, const uint32_t* __restrict__ Mb,
    uint32_t* __restrict__ Oh, uint32_t* __restrict__ Ol)
{
    extern __shared__ uint32_t smn[];
    const int b = blockIdx.z, h = blockIdx.y;
    const int q0 = blockIdx.x * 64;
    const int t = threadIdx.x, w = t >> 5, lane = t & 31;
    const int qr = lane >> 2, qc = lane & 3;
    const int wq = w & 3;
    const int g  = w >> 2;

    const uint32_t smb = smem_u32(smn);
    const size_t bh = (size_t)(b * 8 + h);
    const int n0 = q0 + wq * 16 + qr;
    const int n1 = n0 + 8;

    const uint32_t lmk = ((g * 32 + (lane & 7)) * 36 + (lane >> 3) * 4) * 4;
    const uint32_t lmv = (((lane & 7)) * 36 + g * 16 + (lane >> 3) * 4) * 4;

    const uint32_t* Kg = Kh + bh * SEQ_M * 32;
    // V layout: [dfull][b*m]; per (b,h): base = (h*64)*4096 + b*2048, stride 4096
    const uint32_t* Vg = Vt + (size_t)(h * 64) * 4096 + (size_t)b * 2048;
    const uint32_t* Mrow = Mb + (size_t)b * 128 * 4096;

    auto issue = [&](int tt) {
        const int seg = (t & 7) * 4;
#pragma unroll
        for (int cc = 0; cc < 2; ++cc) {
            const int sub = (2 * tt + cc) % 6;
            const int mk = tt * 128 + cc * 64;
#pragma unroll
            for (int i = 0; i < 2; ++i) {
                const int row = i * 32 + (t >> 3);
                cp16(smb + ASUB_K(sub) + (row * 36 + seg) * 4,
                     &Kg[(size_t)(mk + row) * 32 + seg]);
                cp16(smb + ASUB_V(sub) + (row * 36 + seg) * 4,
                     &Vg[(size_t)row * 4096 + (mk >> 1) + seg]);
            }
        }
        cp_commit();
    };

    issue(0);
    issue(1);

    uint32_t qa[4][4];
    {
        const uint32_t* Qb = Qh + (bh * 4096 + q0 + (size_t)wq * 16) * 32;
#pragma unroll
        for (int kc = 0; kc < 4; ++kc) {
            qa[kc][0] = Qb[qr * 32 + kc * 8 + qc];
            qa[kc][1] = Qb[(qr + 8) * 32 + kc * 8 + qc];
            qa[kc][2] = Qb[qr * 32 + kc * 8 + qc + 4];
            qa[kc][3] = Qb[(qr + 8) * 32 + kc * 8 + qc + 4];
        }
    }

    float o[8][4];
#pragma unroll
    for (int j = 0; j < 8; ++j)
#pragma unroll
        for (int k = 0; k < 4; ++k) o[j][k] = 0.f;
    float l0 = 0.f, l1 = 0.f;

    auto chunk = [&](int sub, uint32_t mw0, uint32_t mw1) {
        const uint32_t ksb = smb + ASUB_K(sub) + lmk;
        const uint32_t vsb = smb + ASUB_V(sub) + lmv;
        float c[4][4];
#pragma unroll
        for (int u = 0; u < 4; ++u) {
            uint32_t kf[4], kf2[4];
            ldsm_x4(kf,  ksb + u * 1152);
            ldsm_x4(kf2, ksb + u * 1152 + 64);
            c[u][0] = c[u][1] = c[u][2] = c[u][3] = 0.f;
            mma_f16(c[u], qa[0], kf[0], kf[1]);
            mma_f16(c[u], qa[1], kf[2], kf[3]);
            mma_f16(c[u], qa[2], kf2[0], kf2[1]);
            mma_f16(c[u], qa[3], kf2[2], kf2[3]);
        }
        uint32_t pa[2][4];
#pragma unroll
        for (int j = 0; j < 4; ++j) {
            int sh = j * 8 + qc * 2;
            if ((mw0 >> sh) & 1u)       c[j][0] = -1e30f;
            if ((mw0 >> (sh + 1)) & 1u) c[j][1] = -1e30f;
            if ((mw1 >> sh) & 1u)       c[j][2] = -1e30f;
            if ((mw1 >> (sh + 1)) & 1u) c[j][3] = -1e30f;
        }
#pragma unroll
        for (int kc = 0; kc < 2; ++kc) {
            pa[kc][0] = ex2h2(pack_h2(c[2 * kc][0], c[2 * kc][1]));
            pa[kc][1] = ex2h2(pack_h2(c[2 * kc][2], c[2 * kc][3]));
            pa[kc][2] = ex2h2(pack_h2(c[2 * kc + 1][0], c[2 * kc + 1][1]));
            pa[kc][3] = ex2h2(pack_h2(c[2 * kc + 1][2], c[2 * kc + 1][3]));
        }
#pragma unroll
        for (int kc = 0; kc < 2; ++kc) {
            float2 f0 = __half22float2(*(__half2*)&pa[kc][0]);
            float2 f1 = __half22float2(*(__half2*)&pa[kc][1]);
            float2 f2 = __half22float2(*(__half2*)&pa[kc][2]);
            float2 f3 = __half22float2(*(__half2*)&pa[kc][3]);
            l0 += f0.x + f0.y + f2.x + f2.y;
            l1 += f1.x + f1.y + f3.x + f3.y;
        }
#pragma unroll
        for (int u = 0; u < 4; ++u) {
            uint32_t vf0[4], vf1[4];
            ldsm_x4(vf0, vsb + (2 * u) * 1152);
            ldsm_x4(vf1, vsb + (2 * u + 1) * 1152);
            mma_f16(o[2 * u],     pa[0], vf0[0], vf0[1]);
            mma_f16(o[2 * u + 1], pa[0], vf1[0], vf1[1]);
            mma_f16(o[2 * u],     pa[1], vf0[2], vf0[3]);
            mma_f16(o[2 * u + 1], pa[1], vf1[2], vf1[3]);
        }
    };

    for (int tt = 0; tt < 32; ++tt) {
        const int wzA = tt * 4 + g;
        const int wzB = tt * 4 + 2 + g;
        uint32_t ma0 = Mrow[(size_t)wzA * 4096 + n0];
        uint32_t ma1 = Mrow[(size_t)wzA * 4096 + n1];
        uint32_t mb0 = Mrow[(size_t)wzB * 4096 + n0];
        uint32_t mb1 = Mrow[(size_t)wzB * 4096 + n1];

        if (tt < 31) cp_wait1(); else cp_wait0();
        __syncthreads();

        chunk((2 * tt) % 6,     ma0, ma1);
        chunk((2 * tt + 1) % 6, mb0, mb1);

        if (tt + 2 < 32) issue(tt + 2);
    }

    l0 += __shfl_xor_sync(0xffffffffu, l0, 1);
    l0 += __shfl_xor_sync(0xffffffffu, l0, 2);
    l1 += __shfl_xor_sync(0xffffffffu, l1, 1);
    l1 += __shfl_xor_sync(0xffffffffu, l1, 2);

    float* sf = reinterpret_cast<float*>(smn);
    const int ro0 = wq * 16 + qr, ro1 = ro0 + 8;
    const int LOFF = 64 * 66;
    __syncthreads();
    if (g == 0) {
#pragma unroll
        for (int j = 0; j < 8; ++j) {
            int col = j * 8 + qc * 2;
            sf[ro0 * 66 + col]     = o[j][0];
            sf[ro0 * 66 + col + 1] = o[j][1];
            sf[ro1 * 66 + col]     = o[j][2];
            sf[ro1 * 66 + col + 1] = o[j][3];
        }
        if (qc == 0) { sf[LOFF + ro0] = l0; sf[LOFF + ro1] = l1; }
    }
    __syncthreads();
    if (g == 1) {
        float i0 = 1.f / fmaxf(l0 + sf[LOFF + ro0], 1e-30f);
        float i1 = 1.f / fmaxf(l1 + sf[LOFF + ro1], 1e-30f);
#pragma unroll
        for (int j = 0; j < 8; ++j) {
            int col = j * 8 + qc * 2;
            float v0 = (o[j][0] + sf[ro0 * 66 + col])     * i0;
            float v1 = (o[j][1] + sf[ro0 * 66 + col + 1]) * i0;
            float v2 = (o[j][2] + sf[ro1 * 66 + col])     * i1;
            float v3 = (o[j][3] + sf[ro1 * 66 + col + 1]) * i1;
            int colw = h * 32 + j * 4 + qc;
            __half h0 = __float2half(v0), h1 = __float2half(v1);
            __half h2 = __float2half(v2), h3 = __float2half(v3);
            Oh[(size_t)n0 * 256 + (size_t)b * 4096 * 256 + colw] =
                ((uint32_t)__half_as_ushort(h1) << 16) | __half_as_ushort(h0);
            Ol[(size_t)n0 * 256 + (size_t)b * 4096 * 256 + colw] =
                pack_h2(v0 - __half2float(h0), v1 - __half2float(h1));
            Oh[(size_t)n1 * 256 + (size_t)b * 4096 * 256 + colw] =
                ((uint32_t)__half_as_ushort(h3) << 16) | __half_as_ushort(h2);
            Ol[(size_t)n1 * 256 + (size_t)b * 4096 * 256 + colw] =
                pack_h2(v2 - __half2float(h2), v3 - __half2float(h3));
        }
    }
}

// ---------------------------------------------------------------------------
// Launch
// ---------------------------------------------------------------------------
extern "C" void kernel_launch(void* const* d_in, const int* in_sizes, int n_in,
                              void* d_out, int out_size)
{
    const float* x       = (const float*)d_in[0];
    const float* context = (const float*)d_in[1];
    const int*   pos_x   = (const int*)d_in[2];
    const int*   pos_ctx = (const int*)d_in[3];
    const unsigned char* mask = (const unsigned char*)d_in[4];
    const float* Wq = (const float*)d_in[5];
    const float* bq = (const float*)d_in[6];
    const float* Wk = (const float*)d_in[7];
    const float* bk = (const float*)d_in[8];
    const float* Wv = (const float*)d_in[9];
    const float* bv = (const float*)d_in[10];
    const float* Wo = (const float*)d_in[11];
    const float* bo = (const float*)d_in[12];
    float* out = (float*)d_out;

    float *qp, *kp;
    __half *qh, *kh;
    uint32_t *vt, *mb;
    __half *xh, *xl, *chh, *wth;
    cudaGetSymbolAddress((void**)&qp, g_Q);
    cudaGetSymbolAddress((void**)&kp, g_K);
    cudaGetSymbolAddress((void**)&qh, g_Qh);
    cudaGetSymbolAddress((void**)&kh, g_Kh);
    cudaGetSymbolAddress((void**)&vt, g_Vt);
    cudaGetSymbolAddress((void**)&mb, g_Mbits);
    cudaGetSymbolAddress((void**)&xh, g_Xh);
    cudaGetSymbolAddress((void**)&xl, g_Xl);
    cudaGetSymbolAddress((void**)&chh, g_Ch);
    cudaGetSymbolAddress((void**)&wth, g_Wth);

    const int WSZ2 = DIM_C * DIM_C / 2;
    const int G1_SMEM = 2 * G1_STAGE_WORDS * 4;   // 72 KB
    const int G2_SMEM = 2 * G2STAGE_WORDS * 4;    // 60 KB
    cudaFuncSetAttribute(gemm1_mma_kernel,
                         cudaFuncAttributeMaxDynamicSharedMemorySize, G1_SMEM);
    cudaFuncSetAttribute(gemm1t_mma_kernel,
                         cudaFuncAttributeMaxDynamicSharedMemorySize, G1_SMEM);
    cudaFuncSetAttribute(gemm2_mma_kernel,
                         cudaFuncAttributeMaxDynamicSharedMemorySize, G2_SMEM);
    cudaFuncSetAttribute(attn_mma_kernel,
                         cudaFuncAttributeMaxDynamicSharedMemorySize, ATT_SMEM);

    dim3 wgrid(8, 8, 4);
    wsplit4_kernel<<<wgrid, 256>>>(Wq, Wk, Wv, Wo, (uint32_t*)wth);

    const int n4 = BATCH * SEQ_N * DIM_C / 4;
    dim3 sgrid(n4 / 256, 2);
    split2_kernel<<<sgrid, 256>>>((const float4*)x, (const float4*)context,
                                  (uint2*)xh, (uint2*)chh, n4);

    detect_mask_kernel<<<1, 256>>>((const uint32_t*)mask);

    dim3 ggrid(DIM_C / 128, (BATCH * SEQ_N) / 128);   // (4, 64)
    gemm1_mma_kernel<<<ggrid, 512, G1_SMEM>>>(
        (const uint32_t*)xh, (const uint32_t*)wth + 0 * WSZ2, bq, qp);

    pack_mask_kernel<<<BATCH * SEQ_N, 128>>>(mask, mb);

    gemm1_mma_kernel<<<ggrid, 512, G1_SMEM>>>(
        (const uint32_t*)chh, (const uint32_t*)wth + 1 * WSZ2, bk, kp);

    // V transposed directly: Vt[dfull][b*m] = WvT x context^T (+ bv per row)
    dim3 vgrid((BATCH * SEQ_M) / 128, DIM_C / 128);   // (64, 4)
    gemm1t_mma_kernel<<<vgrid, 512, G1_SMEM>>>(
        (const uint32_t*)wth + 2 * WSZ2, (const uint32_t*)chh, bv, vt);

    const int rope_total = BATCH * SEQ_N * HEADS * 32;
    const float qscale = 0.125f * 1.4426950408889634f;
    dim3 rgrid((rope_total + 255) / 256, 2);
    rope2d_h_kernel<<<rgrid, 256>>>(qp, kp, qh, kh, pos_x, pos_ctx,
                                    qscale, rope_total);

    dim3 agrid(SEQ_N / 64, HEADS, BATCH);   // 1024 CTAs
    attn_mma_kernel<<<agrid, 256, ATT_SMEM>>>(
        (const uint32_t*)qh, (const uint32_t*)kh, vt, mb,
        (uint32_t*)xh, (uint32_t*)xl);

    gemm2_mma_kernel<<<ggrid, 512, G2_SMEM>>>(
        (const uint32_t*)xh, (const uint32_t*)xl,
        (const uint32_t*)wth + 3 * WSZ2, bo, out);
}